// round 1
// baseline (speedup 1.0000x reference)
#include <cuda_runtime.h>
#include <math.h>

#define NN 50000
#define EE 100000
#define HIDD 128
#define HH 4
#define CCC 128
#define HCC 512
#define LLL 3

// ---------------- scratch (static device globals; no runtime alloc) ----------------
__device__ float g_q[(size_t)NN * HCC];
__device__ float g_k[(size_t)NN * HCC];
__device__ float g_v[(size_t)NN * HCC];
__device__ float g_s[(size_t)NN * HCC];
__device__ float g_agg[(size_t)NN * HCC];
__device__ float g_h[(size_t)NN * HIDD];
__device__ float g_x[(size_t)NN * HIDD];
__device__ float g_p[(size_t)EE * HH];
__device__ float g_den[(size_t)NN * HH];

// ---------------- GEMM: out[M,Ncols] = (A (+A2)) @ W + bias ----------------
// A row-major [M,K], W row-major [K,Ncols]. BM=BN=128, BK=16, 256 thr, 8x8/thread.
#define BM 128
#define BN 128
#define BK 16

__global__ __launch_bounds__(256) void gemm_k(
    const float* __restrict__ A, const float* __restrict__ A2,
    const float* __restrict__ W, const float* __restrict__ bias,
    float* __restrict__ out, int M, int K, int Ncols)
{
    __shared__ float As[BK][BM];
    __shared__ float Bs[BK][BN];

    const int tid = threadIdx.x;
    const int m0 = blockIdx.y * BM;
    const int n0 = blockIdx.x * BN;
    const int tx = tid & 15;   // col group
    const int ty = tid >> 4;   // row group

    float acc[8][8];
#pragma unroll
    for (int i = 0; i < 8; i++)
#pragma unroll
        for (int j = 0; j < 8; j++) acc[i][j] = 0.f;

    for (int k0 = 0; k0 < K; k0 += BK) {
        // Load A tile (128 rows x 16 k) as 512 float4; transpose into As[k][m]
#pragma unroll
        for (int t = 0; t < 2; t++) {
            int i = tid + t * 256;
            int row = i >> 2;
            int c4 = i & 3;
            float4 a = make_float4(0.f, 0.f, 0.f, 0.f);
            int gr = m0 + row;
            if (gr < M) {
                a = *(const float4*)(A + (size_t)gr * K + k0 + c4 * 4);
                if (A2) {
                    float4 a2 = *(const float4*)(A2 + (size_t)gr * K + k0 + c4 * 4);
                    a.x += a2.x; a.y += a2.y; a.z += a2.z; a.w += a2.w;
                }
            }
            As[c4 * 4 + 0][row] = a.x;
            As[c4 * 4 + 1][row] = a.y;
            As[c4 * 4 + 2][row] = a.z;
            As[c4 * 4 + 3][row] = a.w;
        }
        // Load B tile (16 k x 128 n)
#pragma unroll
        for (int t = 0; t < 2; t++) {
            int i = tid + t * 256;
            int kk = i >> 5;
            int c4 = i & 31;
            float4 b = *(const float4*)(W + (size_t)(k0 + kk) * Ncols + n0 + c4 * 4);
            *(float4*)&Bs[kk][c4 * 4] = b;
        }
        __syncthreads();

#pragma unroll
        for (int kk = 0; kk < BK; kk++) {
            float a[8], b[8];
            *(float4*)&a[0] = *(const float4*)&As[kk][ty * 8];
            *(float4*)&a[4] = *(const float4*)&As[kk][ty * 8 + 4];
            *(float4*)&b[0] = *(const float4*)&Bs[kk][tx * 8];
            *(float4*)&b[4] = *(const float4*)&Bs[kk][tx * 8 + 4];
#pragma unroll
            for (int i = 0; i < 8; i++)
#pragma unroll
                for (int j = 0; j < 8; j++)
                    acc[i][j] = fmaf(a[i], b[j], acc[i][j]);
        }
        __syncthreads();
    }

    // Epilogue: + bias, store
#pragma unroll
    for (int i = 0; i < 8; i++) {
        int gr = m0 + ty * 8 + i;
        if (gr >= M) break;
#pragma unroll
        for (int j4 = 0; j4 < 2; j4++) {
            int col = n0 + tx * 8 + j4 * 4;
            float4 bv = *(const float4*)(bias + col);
            float4 o;
            o.x = acc[i][j4 * 4 + 0] + bv.x;
            o.y = acc[i][j4 * 4 + 1] + bv.y;
            o.z = acc[i][j4 * 4 + 2] + bv.z;
            o.w = acc[i][j4 * 4 + 3] + bv.w;
            *(float4*)(out + (size_t)gr * Ncols + col) = o;
        }
    }
}

// ---------------- Edge pass 1: p = exp(scale * q[dst]·(k[src] + ea*We)), denom += p ----------------
// One warp per (edge, head). ED=1 so e-tile is rank-1: ea[e] * We[h, :].
__global__ __launch_bounds__(256) void edge_attn_k(
    const float* __restrict__ q, const float* __restrict__ k,
    const float* __restrict__ ea, const int* __restrict__ src,
    const int* __restrict__ dst, const float* __restrict__ We,
    float* __restrict__ p, float* __restrict__ den)
{
    int wg = blockIdx.x * 8 + (threadIdx.x >> 5);   // = e*4 + h
    int lane = threadIdx.x & 31;
    int e = wg >> 2, h = wg & 3;
    int sN = src[e], dN = dst[e];
    float eav = ea[e];

    const float4 qv = *(const float4*)(q + (size_t)dN * HCC + h * CCC + lane * 4);
    const float4 kv = *(const float4*)(k + (size_t)sN * HCC + h * CCC + lane * 4);
    const float4 wv = *(const float4*)(We + h * CCC + lane * 4);

    float s = qv.x * fmaf(eav, wv.x, kv.x) + qv.y * fmaf(eav, wv.y, kv.y)
            + qv.z * fmaf(eav, wv.z, kv.z) + qv.w * fmaf(eav, wv.w, kv.w);
#pragma unroll
    for (int off = 16; off; off >>= 1) s += __shfl_xor_sync(0xffffffffu, s, off);

    if (lane == 0) {
        float pv = expf(s * 0.08838834764831845f);   // 1/sqrt(128)
        p[wg] = pv;
        atomicAdd(den + (size_t)dN * HH + h, pv);
    }
}

// ---------------- Edge pass 2: agg[dst] += (v[src] + ea*We) * p/(den+1e-16) ----------------
__global__ __launch_bounds__(256) void edge_agg_k(
    const float* __restrict__ v, const float* __restrict__ ea,
    const int* __restrict__ src, const int* __restrict__ dst,
    const float* __restrict__ We, const float* __restrict__ p,
    const float* __restrict__ den, float* __restrict__ agg)
{
    int wg = blockIdx.x * 8 + (threadIdx.x >> 5);
    int lane = threadIdx.x & 31;
    int e = wg >> 2, h = wg & 3;
    int sN = src[e], dN = dst[e];
    float eav = ea[e];

    float a = p[wg] / (den[(size_t)dN * HH + h] + 1e-16f);

    const float4 vv = *(const float4*)(v + (size_t)sN * HCC + h * CCC + lane * 4);
    const float4 wv = *(const float4*)(We + h * CCC + lane * 4);
    float4 m;
    m.x = fmaf(eav, wv.x, vv.x) * a;
    m.y = fmaf(eav, wv.y, vv.y) * a;
    m.z = fmaf(eav, wv.z, vv.z) * a;
    m.w = fmaf(eav, wv.w, vv.w) * a;

    atomicAdd((float4*)(agg + (size_t)dN * HCC + h * CCC + lane * 4), m);
}

// ---------------- Fused ELU + residual + LayerNorm (one warp per row of 128) ----------------
__global__ __launch_bounds__(256) void ln_k(
    const float* __restrict__ x, const float* __restrict__ h,
    const float* __restrict__ gamma, const float* __restrict__ beta,
    float* __restrict__ out)
{
    int row = blockIdx.x * 8 + (threadIdx.x >> 5);
    int lane = threadIdx.x & 31;

    const float4 xv = *(const float4*)(x + (size_t)row * HIDD + lane * 4);
    const float4 hv = *(const float4*)(h + (size_t)row * HIDD + lane * 4);

    float4 y;
    y.x = xv.x + (hv.x > 0.f ? hv.x : expm1f(hv.x));
    y.y = xv.y + (hv.y > 0.f ? hv.y : expm1f(hv.y));
    y.z = xv.z + (hv.z > 0.f ? hv.z : expm1f(hv.z));
    y.w = xv.w + (hv.w > 0.f ? hv.w : expm1f(hv.w));

    float sum = y.x + y.y + y.z + y.w;
    float sq  = y.x * y.x + y.y * y.y + y.z * y.z + y.w * y.w;
#pragma unroll
    for (int off = 16; off; off >>= 1) {
        sum += __shfl_xor_sync(0xffffffffu, sum, off);
        sq  += __shfl_xor_sync(0xffffffffu, sq, off);
    }
    float mu = sum * (1.f / 128.f);
    float var = sq * (1.f / 128.f) - mu * mu;
    float inv = rsqrtf(var + 1e-5f);

    const float4 gv = *(const float4*)(gamma + lane * 4);
    const float4 bv = *(const float4*)(beta + lane * 4);
    float4 o;
    o.x = (y.x - mu) * inv * gv.x + bv.x;
    o.y = (y.y - mu) * inv * gv.y + bv.y;
    o.z = (y.z - mu) * inv * gv.z + bv.z;
    o.w = (y.w - mu) * inv * gv.w + bv.w;
    *(float4*)(out + (size_t)row * HIDD + lane * 4) = o;
}

// ---------------- host ----------------
extern "C" void kernel_launch(void* const* d_in, const int* in_sizes, int n_in,
                              void* d_out, int out_size)
{
    const float* x_in  = (const float*)d_in[0];
    const int*   ei    = (const int*)d_in[1];
    const float* ea    = (const float*)d_in[2];
    const float* Wq    = (const float*)d_in[3];
    const float* bq    = (const float*)d_in[4];
    const float* Wk    = (const float*)d_in[5];
    const float* bk    = (const float*)d_in[6];
    const float* Wv    = (const float*)d_in[7];
    const float* bv    = (const float*)d_in[8];
    const float* We    = (const float*)d_in[9];
    const float* Wskip = (const float*)d_in[10];
    const float* bskip = (const float*)d_in[11];
    const float* Wproj = (const float*)d_in[12];
    const float* bproj = (const float*)d_in[13];
    const float* gamma = (const float*)d_in[14];
    const float* beta  = (const float*)d_in[15];

    float *q, *k, *v, *s, *agg, *h, *xbuf, *p, *den;
    cudaGetSymbolAddress((void**)&q,    g_q);
    cudaGetSymbolAddress((void**)&k,    g_k);
    cudaGetSymbolAddress((void**)&v,    g_v);
    cudaGetSymbolAddress((void**)&s,    g_s);
    cudaGetSymbolAddress((void**)&agg,  g_agg);
    cudaGetSymbolAddress((void**)&h,    g_h);
    cudaGetSymbolAddress((void**)&xbuf, g_x);
    cudaGetSymbolAddress((void**)&p,    g_p);
    cudaGetSymbolAddress((void**)&den,  g_den);

    const int* src = ei;
    const int* dst = ei + EE;

    dim3 gridQKV(HCC / BN, (NN + BM - 1) / BM);   // (4, 391)
    dim3 gridPRJ(HIDD / BN, (NN + BM - 1) / BM);  // (1, 391)
    const int edgeBlocks = (EE * HH) / 8;         // 50000
    const int lnBlocks = NN / 8;                  // 6250

    for (int l = 0; l < LLL; l++) {
        const float* xl = (l == 0) ? x_in : xbuf;
        float* xo = (l == LLL - 1) ? (float*)d_out : xbuf;
        size_t wo = (size_t)l * HIDD * HCC;

        gemm_k<<<gridQKV, 256>>>(xl, nullptr, Wq + wo,    bq + l * HCC,    q, NN, HIDD, HCC);
        gemm_k<<<gridQKV, 256>>>(xl, nullptr, Wk + wo,    bk + l * HCC,    k, NN, HIDD, HCC);
        gemm_k<<<gridQKV, 256>>>(xl, nullptr, Wv + wo,    bv + l * HCC,    v, NN, HIDD, HCC);
        gemm_k<<<gridQKV, 256>>>(xl, nullptr, Wskip + wo, bskip + l * HCC, s, NN, HIDD, HCC);

        cudaMemsetAsync(den, 0, (size_t)NN * HH * sizeof(float));
        cudaMemsetAsync(agg, 0, (size_t)NN * HCC * sizeof(float));

        edge_attn_k<<<edgeBlocks, 256>>>(q, k, ea, src, dst, We + l * HCC, p, den);
        edge_agg_k<<<edgeBlocks, 256>>>(v, ea, src, dst, We + l * HCC, p, den, agg);

        gemm_k<<<gridPRJ, 256>>>(agg, s, Wproj + (size_t)l * HCC * HIDD,
                                 bproj + l * HIDD, h, NN, HCC, HIDD);

        ln_k<<<lnBlocks, 256>>>(xl, h, gamma + l * HIDD, beta + l * HIDD, xo);
    }
}

// round 3
// speedup vs baseline: 1.3720x; 1.3720x over previous
#include <cuda_runtime.h>
#include <mma.h>
#include <math.h>

using namespace nvcuda;

#define NN 50000
#define NPAD 50048          // 391 * 128, so GEMM tiles need no M guards
#define EE 100000
#define HIDD 128
#define HH 4
#define CCC 128
#define HCC 512
#define LLL 3

// ---------------- scratch (static device globals; zero-init, no runtime alloc) ----------------
__device__ float g_q[(size_t)NPAD * HCC];
__device__ float g_k[(size_t)NPAD * HCC];
__device__ float g_v[(size_t)NPAD * HCC];
__device__ float g_s[(size_t)NPAD * HCC];
__device__ float g_agg[(size_t)NPAD * HCC];
__device__ float g_h[(size_t)NPAD * HIDD];
__device__ float g_x[(size_t)NPAD * HIDD];
__device__ float g_p[(size_t)EE * HH];
__device__ float g_den[(size_t)NN * HH];

__device__ __forceinline__ float to_tf32(float x) {
    unsigned r;
    asm("cvt.rna.tf32.f32 %0, %1;" : "=r"(r) : "f"(x));
    return __uint_as_float(r);
}

// ---------------- TF32 tensor-core GEMM: out[NPAD,Ncols] = (A (+A2)) @ W + bias ----------------
// A row-major [NPAD,K] (padded, no guards), W row-major [K,Ncols].
// Block tile 128x128, BK=32. 8 warps in 2x4; warp tile 64x32 = 4x2 wmma(16x16x8) frags.
#define BM 128
#define BN 128

__global__ __launch_bounds__(256, 2) void gemm_tc(
    const float* __restrict__ A, const float* __restrict__ A2,
    const float* __restrict__ W, const float* __restrict__ bias,
    float* __restrict__ out, int K, int Ncols)
{
    __shared__ float As[128][36];     // 32 k-cols + pad 4
    __shared__ float Bs[32][132];     // 128 n-cols + pad 4
    __shared__ float bias_s[16][128];

    const int tid = threadIdx.x;
    const int wid = tid >> 5;
    const int m0 = blockIdx.y * BM;
    const int n0 = blockIdx.x * BN;
    const int wm = wid >> 2;          // 0..1
    const int wn = wid & 3;           // 0..3

    // Replicate bias across 16 rows so acc frags can be initialized from it.
#pragma unroll
    for (int i = tid; i < 16 * 128; i += 256)
        bias_s[i >> 7][i & 127] = bias[n0 + (i & 127)];
    __syncthreads();

    wmma::fragment<wmma::accumulator, 16, 16, 8, float> acc[4][2];
#pragma unroll
    for (int i = 0; i < 4; i++)
#pragma unroll
        for (int j = 0; j < 2; j++)
            wmma::load_matrix_sync(acc[i][j], &bias_s[0][wn * 32 + j * 16], 128,
                                   wmma::mem_row_major);

    for (int kb = 0; kb < K; kb += 32) {
        __syncthreads();
        // A tile: 128 rows x 32 k  (1024 float4, 4 per thread)
#pragma unroll
        for (int t = 0; t < 4; t++) {
            int i = tid + t * 256;
            int r = i >> 3;
            int c = (i & 7) * 4;
            float4 a = *(const float4*)(A + (size_t)(m0 + r) * K + kb + c);
            if (A2) {
                float4 a2 = *(const float4*)(A2 + (size_t)(m0 + r) * K + kb + c);
                a.x += a2.x; a.y += a2.y; a.z += a2.z; a.w += a2.w;
            }
            As[r][c + 0] = to_tf32(a.x);
            As[r][c + 1] = to_tf32(a.y);
            As[r][c + 2] = to_tf32(a.z);
            As[r][c + 3] = to_tf32(a.w);
        }
        // B tile: 32 k x 128 n (1024 float4, 4 per thread)
#pragma unroll
        for (int t = 0; t < 4; t++) {
            int i = tid + t * 256;
            int r = i >> 5;
            int c = (i & 31) * 4;
            float4 b = *(const float4*)(W + (size_t)(kb + r) * Ncols + n0 + c);
            Bs[r][c + 0] = to_tf32(b.x);
            Bs[r][c + 1] = to_tf32(b.y);
            Bs[r][c + 2] = to_tf32(b.z);
            Bs[r][c + 3] = to_tf32(b.w);
        }
        __syncthreads();

#pragma unroll
        for (int ks = 0; ks < 4; ks++) {
            wmma::fragment<wmma::matrix_a, 16, 16, 8, wmma::precision::tf32,
                           wmma::row_major> af[4];
            wmma::fragment<wmma::matrix_b, 16, 16, 8, wmma::precision::tf32,
                           wmma::row_major> bf[2];
#pragma unroll
            for (int i = 0; i < 4; i++)
                wmma::load_matrix_sync(af[i], &As[wm * 64 + i * 16][ks * 8], 36);
#pragma unroll
            for (int j = 0; j < 2; j++)
                wmma::load_matrix_sync(bf[j], &Bs[ks * 8][wn * 32 + j * 16], 132);
#pragma unroll
            for (int i = 0; i < 4; i++)
#pragma unroll
                for (int j = 0; j < 2; j++)
                    wmma::mma_sync(acc[i][j], af[i], bf[j], acc[i][j]);
        }
    }

#pragma unroll
    for (int i = 0; i < 4; i++)
#pragma unroll
        for (int j = 0; j < 2; j++)
            wmma::store_matrix_sync(
                out + (size_t)(m0 + wm * 64 + i * 16) * Ncols + n0 + wn * 32 + j * 16,
                acc[i][j], Ncols, wmma::mem_row_major);
}

// ---------------- Edge pass 1: p = exp(scale * q[dst]·(k[src] + ea*We)), denom += p ----------------
__global__ __launch_bounds__(256) void edge_attn_k(
    const float* __restrict__ q, const float* __restrict__ k,
    const float* __restrict__ ea, const int* __restrict__ src,
    const int* __restrict__ dst, const float* __restrict__ We,
    float* __restrict__ p, float* __restrict__ den)
{
    int wg = blockIdx.x * 8 + (threadIdx.x >> 5);   // = e*4 + h
    int lane = threadIdx.x & 31;
    int e = wg >> 2, h = wg & 3;
    int sN = src[e], dN = dst[e];
    float eav = ea[e];

    const float4 qv = *(const float4*)(q + (size_t)dN * HCC + h * CCC + lane * 4);
    const float4 kv = *(const float4*)(k + (size_t)sN * HCC + h * CCC + lane * 4);
    const float4 wv = *(const float4*)(We + h * CCC + lane * 4);

    float s = qv.x * fmaf(eav, wv.x, kv.x) + qv.y * fmaf(eav, wv.y, kv.y)
            + qv.z * fmaf(eav, wv.z, kv.z) + qv.w * fmaf(eav, wv.w, kv.w);
#pragma unroll
    for (int off = 16; off; off >>= 1) s += __shfl_xor_sync(0xffffffffu, s, off);

    if (lane == 0) {
        float pv = expf(s * 0.08838834764831845f);   // 1/sqrt(128)
        p[wg] = pv;
        atomicAdd(den + (size_t)dN * HH + h, pv);
    }
}

// ---------------- Edge pass 2: agg[dst] += (v[src] + ea*We) * p/(den+1e-16) ----------------
__global__ __launch_bounds__(256) void edge_agg_k(
    const float* __restrict__ v, const float* __restrict__ ea,
    const int* __restrict__ src, const int* __restrict__ dst,
    const float* __restrict__ We, const float* __restrict__ p,
    const float* __restrict__ den, float* __restrict__ agg)
{
    int wg = blockIdx.x * 8 + (threadIdx.x >> 5);
    int lane = threadIdx.x & 31;
    int e = wg >> 2, h = wg & 3;
    int sN = src[e], dN = dst[e];
    float eav = ea[e];

    float a = p[wg] / (den[(size_t)dN * HH + h] + 1e-16f);

    const float4 vv = *(const float4*)(v + (size_t)sN * HCC + h * CCC + lane * 4);
    const float4 wv = *(const float4*)(We + h * CCC + lane * 4);
    float4 m;
    m.x = fmaf(eav, wv.x, vv.x) * a;
    m.y = fmaf(eav, wv.y, vv.y) * a;
    m.z = fmaf(eav, wv.z, vv.z) * a;
    m.w = fmaf(eav, wv.w, vv.w) * a;

    atomicAdd((float4*)(agg + (size_t)dN * HCC + h * CCC + lane * 4), m);
}

// ---------------- Fused ELU + residual + LayerNorm (one warp per row of 128) ----------------
__global__ __launch_bounds__(256) void ln_k(
    const float* __restrict__ x, const float* __restrict__ h,
    const float* __restrict__ gamma, const float* __restrict__ beta,
    float* __restrict__ out)
{
    int row = blockIdx.x * 8 + (threadIdx.x >> 5);
    int lane = threadIdx.x & 31;

    const float4 xv = *(const float4*)(x + (size_t)row * HIDD + lane * 4);
    const float4 hv = *(const float4*)(h + (size_t)row * HIDD + lane * 4);

    float4 y;
    y.x = xv.x + (hv.x > 0.f ? hv.x : expm1f(hv.x));
    y.y = xv.y + (hv.y > 0.f ? hv.y : expm1f(hv.y));
    y.z = xv.z + (hv.z > 0.f ? hv.z : expm1f(hv.z));
    y.w = xv.w + (hv.w > 0.f ? hv.w : expm1f(hv.w));

    float sum = y.x + y.y + y.z + y.w;
    float sq  = y.x * y.x + y.y * y.y + y.z * y.z + y.w * y.w;
#pragma unroll
    for (int off = 16; off; off >>= 1) {
        sum += __shfl_xor_sync(0xffffffffu, sum, off);
        sq  += __shfl_xor_sync(0xffffffffu, sq, off);
    }
    float mu = sum * (1.f / 128.f);
    float var = sq * (1.f / 128.f) - mu * mu;
    float inv = rsqrtf(var + 1e-5f);

    const float4 gv = *(const float4*)(gamma + lane * 4);
    const float4 bv = *(const float4*)(beta + lane * 4);
    float4 o;
    o.x = (y.x - mu) * inv * gv.x + bv.x;
    o.y = (y.y - mu) * inv * gv.y + bv.y;
    o.z = (y.z - mu) * inv * gv.z + bv.z;
    o.w = (y.w - mu) * inv * gv.w + bv.w;
    *(float4*)(out + (size_t)row * HIDD + lane * 4) = o;
}

// ---------------- host ----------------
extern "C" void kernel_launch(void* const* d_in, const int* in_sizes, int n_in,
                              void* d_out, int out_size)
{
    const float* x_in  = (const float*)d_in[0];
    const int*   ei    = (const int*)d_in[1];
    const float* ea    = (const float*)d_in[2];
    const float* Wq    = (const float*)d_in[3];
    const float* bq    = (const float*)d_in[4];
    const float* Wk    = (const float*)d_in[5];
    const float* bk    = (const float*)d_in[6];
    const float* Wv    = (const float*)d_in[7];
    const float* bv    = (const float*)d_in[8];
    const float* We    = (const float*)d_in[9];
    const float* Wskip = (const float*)d_in[10];
    const float* bskip = (const float*)d_in[11];
    const float* Wproj = (const float*)d_in[12];
    const float* bproj = (const float*)d_in[13];
    const float* gamma = (const float*)d_in[14];
    const float* beta  = (const float*)d_in[15];

    float *q, *k, *v, *s, *agg, *h, *xbuf, *p, *den;
    cudaGetSymbolAddress((void**)&q,    g_q);
    cudaGetSymbolAddress((void**)&k,    g_k);
    cudaGetSymbolAddress((void**)&v,    g_v);
    cudaGetSymbolAddress((void**)&s,    g_s);
    cudaGetSymbolAddress((void**)&agg,  g_agg);
    cudaGetSymbolAddress((void**)&h,    g_h);
    cudaGetSymbolAddress((void**)&xbuf, g_x);
    cudaGetSymbolAddress((void**)&p,    g_p);
    cudaGetSymbolAddress((void**)&den,  g_den);

    const int* src = ei;
    const int* dst = ei + EE;

    // Copy x into padded buffer once; pad rows stay zero (never written).
    cudaMemcpyAsync(xbuf, x_in, (size_t)NN * HIDD * sizeof(float),
                    cudaMemcpyDeviceToDevice);

    dim3 gridQKV(HCC / BN, NPAD / BM);    // (4, 391)
    dim3 gridPRJ(HIDD / BN, NPAD / BM);   // (1, 391)
    const int edgeBlocks = (EE * HH) / 8; // 50000
    const int lnBlocks = NN / 8;          // 6250

    for (int l = 0; l < LLL; l++) {
        float* xo = (l == LLL - 1) ? (float*)d_out : xbuf;
        size_t wo = (size_t)l * HIDD * HCC;

        gemm_tc<<<gridQKV, 256>>>(xbuf, nullptr, Wq + wo,    bq + l * HCC,    q, HIDD, HCC);
        gemm_tc<<<gridQKV, 256>>>(xbuf, nullptr, Wk + wo,    bk + l * HCC,    k, HIDD, HCC);
        gemm_tc<<<gridQKV, 256>>>(xbuf, nullptr, Wv + wo,    bv + l * HCC,    v, HIDD, HCC);
        gemm_tc<<<gridQKV, 256>>>(xbuf, nullptr, Wskip + wo, bskip + l * HCC, s, HIDD, HCC);

        cudaMemsetAsync(den, 0, (size_t)NN * HH * sizeof(float));
        cudaMemsetAsync(agg, 0, (size_t)NPAD * HCC * sizeof(float));

        edge_attn_k<<<edgeBlocks, 256>>>(q, k, ea, src, dst, We + l * HCC, p, den);
        edge_agg_k<<<edgeBlocks, 256>>>(v, ea, src, dst, We + l * HCC, p, den, agg);

        gemm_tc<<<gridPRJ, 256>>>(agg, s, Wproj + (size_t)l * HCC * HIDD,
                                  bproj + l * HIDD, h, HCC, HIDD);

        ln_k<<<lnBlocks, 256>>>(xbuf, h, gamma + l * HIDD, beta + l * HIDD, xo);
    }
}

// round 4
// speedup vs baseline: 1.5782x; 1.1503x over previous
#include <cuda_runtime.h>
#include <mma.h>
#include <math.h>

using namespace nvcuda;

#define NN 50000
#define NPAD 50048          // 391 * 128
#define EE 100000
#define HIDD 128
#define HH 4
#define CCC 128
#define HCC 512
#define LLL 3

// ---------------- scratch ----------------
__device__ float g_q[(size_t)NPAD * HCC];
__device__ float g_k[(size_t)NPAD * HCC];
__device__ float g_v[(size_t)NPAD * HCC];
__device__ float g_agg[(size_t)NPAD * HCC];
__device__ float g_h[(size_t)NPAD * HIDD];
__device__ float g_x[(size_t)NPAD * HIDD];
__device__ float g_p[(size_t)EE * HH];
__device__ float g_den[(size_t)NN * HH];
__device__ float g_wf[(size_t)LLL * HIDD * HIDD];   // Wskip @ Wproj
__device__ float g_bf[(size_t)LLL * HIDD];          // bskip @ Wproj + bproj

__device__ __forceinline__ float to_tf32(float x) {
    unsigned r;
    asm("cvt.rna.tf32.f32 %0, %1;" : "=r"(r) : "f"(x));
    return __uint_as_float(r);
}

// smem sizes
#define QKV_SMEM (128*132*4 + 2*32*132*4 + 16*128*4)    // 109568
#define PRJ_SMEM (2*128*36*4 + 2*32*132*4 + 16*128*4)   // 78848

// ---------------- Fused QKV GEMM ----------------
// Whole-K (128) A tile resident in smem (tf32), 3 weight matrices processed
// sequentially with double-buffered B tiles. 12 stages, 1 sync per stage.
__global__ __launch_bounds__(256, 2) void gemm_qkv(
    const float* __restrict__ A,
    const float* __restrict__ W0, const float* __restrict__ W1, const float* __restrict__ W2,
    const float* __restrict__ b0, const float* __restrict__ b1, const float* __restrict__ b2,
    float* __restrict__ o0, float* __restrict__ o1, float* __restrict__ o2)
{
    extern __shared__ float sm[];
    float* AsP   = sm;                        // [128][132]
    float* BsP   = sm + 128 * 132;            // 2 x [32][132]
    float* biasP = BsP + 2 * 32 * 132;        // [16][128]

    const float* Wp[3] = {W0, W1, W2};
    const float* bp[3] = {b0, b1, b2};
    float*       op[3] = {o0, o1, o2};

    const int tid = threadIdx.x;
    const int wid = tid >> 5;
    const int m0 = blockIdx.y * 128;
    const int n0 = blockIdx.x * 128;
    const int wm = wid >> 2;
    const int wn = wid & 3;

    // prologue: As (whole K), Bs stage 0, bias for w=0
#pragma unroll
    for (int t = 0; t < 16; t++) {
        int i = tid + t * 256;                // 0..4095
        int r = i >> 5, c = (i & 31) * 4;
        float4 a = *(const float4*)(A + (size_t)(m0 + r) * HIDD + c);
        AsP[r * 132 + c + 0] = to_tf32(a.x);
        AsP[r * 132 + c + 1] = to_tf32(a.y);
        AsP[r * 132 + c + 2] = to_tf32(a.z);
        AsP[r * 132 + c + 3] = to_tf32(a.w);
    }
#pragma unroll
    for (int t = 0; t < 4; t++) {
        int i = tid + t * 256;
        int r = i >> 5, c = (i & 31) * 4;
        float4 b = *(const float4*)(W0 + (size_t)r * HCC + n0 + c);
        BsP[r * 132 + c + 0] = to_tf32(b.x);
        BsP[r * 132 + c + 1] = to_tf32(b.y);
        BsP[r * 132 + c + 2] = to_tf32(b.z);
        BsP[r * 132 + c + 3] = to_tf32(b.w);
    }
#pragma unroll
    for (int i = tid; i < 2048; i += 256) biasP[i] = b0[n0 + (i & 127)];

    wmma::fragment<wmma::accumulator, 16, 16, 8, float> acc[4][2];
    float4 ldreg[4];

    for (int s = 0; s < 12; s++) {
        const int w = s >> 2, kb = s & 3;
        __syncthreads();

        if (kb == 0) {
#pragma unroll
            for (int i = 0; i < 4; i++)
#pragma unroll
                for (int j = 0; j < 2; j++)
                    wmma::load_matrix_sync(acc[i][j], biasP + wn * 32 + j * 16, 128,
                                           wmma::mem_row_major);
        }

        // LDG next B tile
        if (s < 11) {
            const int wn_ = (s + 1) >> 2, kb_ = (s + 1) & 3;
            const float* Wn = Wp[wn_];
#pragma unroll
            for (int t = 0; t < 4; t++) {
                int i = tid + t * 256;
                int r = i >> 5, c = (i & 31) * 4;
                ldreg[t] = *(const float4*)(Wn + (size_t)(kb_ * 32 + r) * HCC + n0 + c);
            }
        }

        // MMA on current stage
        const float* Bcur = BsP + (s & 1) * 32 * 132;
#pragma unroll
        for (int ks = 0; ks < 4; ks++) {
            wmma::fragment<wmma::matrix_a, 16, 16, 8, wmma::precision::tf32,
                           wmma::row_major> af[4];
            wmma::fragment<wmma::matrix_b, 16, 16, 8, wmma::precision::tf32,
                           wmma::row_major> bf[2];
#pragma unroll
            for (int i = 0; i < 4; i++)
                wmma::load_matrix_sync(af[i], AsP + (wm * 64 + i * 16) * 132 + kb * 32 + ks * 8, 132);
#pragma unroll
            for (int j = 0; j < 2; j++)
                wmma::load_matrix_sync(bf[j], Bcur + (ks * 8) * 132 + wn * 32 + j * 16, 132);
#pragma unroll
            for (int i = 0; i < 4; i++)
#pragma unroll
                for (int j = 0; j < 2; j++)
                    wmma::mma_sync(acc[i][j], af[i], bf[j], acc[i][j]);
        }

        // STS next B tile (other buffer)
        if (s < 11) {
            float* Bnxt = BsP + ((s + 1) & 1) * 32 * 132;
#pragma unroll
            for (int t = 0; t < 4; t++) {
                int i = tid + t * 256;
                int r = i >> 5, c = (i & 31) * 4;
                Bnxt[r * 132 + c + 0] = to_tf32(ldreg[t].x);
                Bnxt[r * 132 + c + 1] = to_tf32(ldreg[t].y);
                Bnxt[r * 132 + c + 2] = to_tf32(ldreg[t].z);
                Bnxt[r * 132 + c + 3] = to_tf32(ldreg[t].w);
            }
        }

        if (kb == 3) {
            // bias for next w (safe: bias readers for w finished at stage 4w)
            if (w < 2) {
                const float* bn = bp[w + 1];
#pragma unroll
                for (int i = tid; i < 2048; i += 256) biasP[i] = bn[n0 + (i & 127)];
            }
            // epilogue for w
            float* out = op[w];
#pragma unroll
            for (int i = 0; i < 4; i++)
#pragma unroll
                for (int j = 0; j < 2; j++)
                    wmma::store_matrix_sync(
                        out + (size_t)(m0 + wm * 64 + i * 16) * HCC + n0 + wn * 32 + j * 16,
                        acc[i][j], HCC, wmma::mem_row_major);
        }
    }
}

// ---------------- Proj GEMM: out = A1@W1 (K=512) + A2@W2 (K=128) + bias ----------------
// 20 double-buffered stages, N=128.
__global__ __launch_bounds__(256, 2) void gemm_proj(
    const float* __restrict__ A1, const float* __restrict__ W1,
    const float* __restrict__ A2, const float* __restrict__ W2,
    const float* __restrict__ bias, float* __restrict__ out)
{
    extern __shared__ float sm[];
    float* AsP   = sm;                        // 2 x [128][36]
    float* BsP   = sm + 2 * 128 * 36;         // 2 x [32][132]
    float* biasP = BsP + 2 * 32 * 132;        // [16][128]

    const int tid = threadIdx.x;
    const int wid = tid >> 5;
    const int m0 = blockIdx.y * 128;
    const int n0 = blockIdx.x * 128;
    const int wm = wid >> 2;
    const int wn = wid & 3;

    // prologue: stage 0 tiles + bias
#pragma unroll
    for (int t = 0; t < 4; t++) {
        int i = tid + t * 256;
        int r = i >> 3, c = (i & 7) * 4;
        float4 a = *(const float4*)(A1 + (size_t)(m0 + r) * HCC + c);
        AsP[r * 36 + c + 0] = to_tf32(a.x);
        AsP[r * 36 + c + 1] = to_tf32(a.y);
        AsP[r * 36 + c + 2] = to_tf32(a.z);
        AsP[r * 36 + c + 3] = to_tf32(a.w);
    }
#pragma unroll
    for (int t = 0; t < 4; t++) {
        int i = tid + t * 256;
        int r = i >> 5, c = (i & 31) * 4;
        float4 b = *(const float4*)(W1 + (size_t)r * HIDD + n0 + c);
        BsP[r * 132 + c + 0] = to_tf32(b.x);
        BsP[r * 132 + c + 1] = to_tf32(b.y);
        BsP[r * 132 + c + 2] = to_tf32(b.z);
        BsP[r * 132 + c + 3] = to_tf32(b.w);
    }
#pragma unroll
    for (int i = tid; i < 2048; i += 256) biasP[i] = bias[n0 + (i & 127)];

    wmma::fragment<wmma::accumulator, 16, 16, 8, float> acc[4][2];
    float4 lda[4], ldb[4];

    __syncthreads();
#pragma unroll
    for (int i = 0; i < 4; i++)
#pragma unroll
        for (int j = 0; j < 2; j++)
            wmma::load_matrix_sync(acc[i][j], biasP + wn * 32 + j * 16, 128,
                                   wmma::mem_row_major);

    for (int s = 0; s < 20; s++) {
        if (s) __syncthreads();

        // LDG next stage
        if (s < 19) {
            int s1 = s + 1;
            const float* Ax; const float* Wx; int K; int k0;
            if (s1 < 16) { Ax = A1; Wx = W1; K = HCC;  k0 = s1 * 32; }
            else         { Ax = A2; Wx = W2; K = HIDD; k0 = (s1 - 16) * 32; }
#pragma unroll
            for (int t = 0; t < 4; t++) {
                int i = tid + t * 256;
                int r = i >> 3, c = (i & 7) * 4;
                lda[t] = *(const float4*)(Ax + (size_t)(m0 + r) * K + k0 + c);
            }
#pragma unroll
            for (int t = 0; t < 4; t++) {
                int i = tid + t * 256;
                int r = i >> 5, c = (i & 31) * 4;
                ldb[t] = *(const float4*)(Wx + (size_t)(k0 + r) * HIDD + n0 + c);
            }
        }

        // MMA current stage
        const float* Acur = AsP + (s & 1) * 128 * 36;
        const float* Bcur = BsP + (s & 1) * 32 * 132;
#pragma unroll
        for (int ks = 0; ks < 4; ks++) {
            wmma::fragment<wmma::matrix_a, 16, 16, 8, wmma::precision::tf32,
                           wmma::row_major> af[4];
            wmma::fragment<wmma::matrix_b, 16, 16, 8, wmma::precision::tf32,
                           wmma::row_major> bf[2];
#pragma unroll
            for (int i = 0; i < 4; i++)
                wmma::load_matrix_sync(af[i], Acur + (wm * 64 + i * 16) * 36 + ks * 8, 36);
#pragma unroll
            for (int j = 0; j < 2; j++)
                wmma::load_matrix_sync(bf[j], Bcur + (ks * 8) * 132 + wn * 32 + j * 16, 132);
#pragma unroll
            for (int i = 0; i < 4; i++)
#pragma unroll
                for (int j = 0; j < 2; j++)
                    wmma::mma_sync(acc[i][j], af[i], bf[j], acc[i][j]);
        }

        // STS next stage
        if (s < 19) {
            float* Anxt = AsP + ((s + 1) & 1) * 128 * 36;
            float* Bnxt = BsP + ((s + 1) & 1) * 32 * 132;
#pragma unroll
            for (int t = 0; t < 4; t++) {
                int i = tid + t * 256;
                int r = i >> 3, c = (i & 7) * 4;
                Anxt[r * 36 + c + 0] = to_tf32(lda[t].x);
                Anxt[r * 36 + c + 1] = to_tf32(lda[t].y);
                Anxt[r * 36 + c + 2] = to_tf32(lda[t].z);
                Anxt[r * 36 + c + 3] = to_tf32(lda[t].w);
            }
#pragma unroll
            for (int t = 0; t < 4; t++) {
                int i = tid + t * 256;
                int r = i >> 5, c = (i & 31) * 4;
                Bnxt[r * 132 + c + 0] = to_tf32(ldb[t].x);
                Bnxt[r * 132 + c + 1] = to_tf32(ldb[t].y);
                Bnxt[r * 132 + c + 2] = to_tf32(ldb[t].z);
                Bnxt[r * 132 + c + 3] = to_tf32(ldb[t].w);
            }
        }
    }

#pragma unroll
    for (int i = 0; i < 4; i++)
#pragma unroll
        for (int j = 0; j < 2; j++)
            wmma::store_matrix_sync(
                out + (size_t)(m0 + wm * 64 + i * 16) * HIDD + n0 + wn * 32 + j * 16,
                acc[i][j], HIDD, wmma::mem_row_major);
}

// ---------------- Precompute Wf = Wskip @ Wproj (per layer) ----------------
__global__ void wf_k(const float* __restrict__ Wskip, const float* __restrict__ Wproj,
                     float* __restrict__ Wf)
{
    int l = blockIdx.y;
    int e = blockIdx.x * 256 + threadIdx.x;    // 0..16383
    int i = e >> 7, j = e & 127;
    const float* ws = Wskip + (size_t)l * HIDD * HCC + (size_t)i * HCC;
    const float* wp = Wproj + (size_t)l * HCC * HIDD + j;
    float s = 0.f;
#pragma unroll 8
    for (int k = 0; k < HCC; k++) s = fmaf(ws[k], wp[(size_t)k * HIDD], s);
    Wf[(size_t)l * HIDD * HIDD + e] = s;
}

__global__ void bf_k(const float* __restrict__ bskip, const float* __restrict__ Wproj,
                     const float* __restrict__ bproj, float* __restrict__ bf)
{
    int l = blockIdx.x, j = threadIdx.x;
    const float* bs = bskip + (size_t)l * HCC;
    const float* wp = Wproj + (size_t)l * HCC * HIDD + j;
    float s = bproj[(size_t)l * HIDD + j];
#pragma unroll 8
    for (int k = 0; k < HCC; k++) s = fmaf(bs[k], wp[(size_t)k * HIDD], s);
    bf[l * HIDD + j] = s;
}

// ---------------- Edge pass 1 ----------------
__global__ __launch_bounds__(256) void edge_attn_k(
    const float* __restrict__ q, const float* __restrict__ k,
    const float* __restrict__ ea, const int* __restrict__ src,
    const int* __restrict__ dst, const float* __restrict__ We,
    float* __restrict__ p, float* __restrict__ den)
{
    int wg = blockIdx.x * 8 + (threadIdx.x >> 5);
    int lane = threadIdx.x & 31;
    int e = wg >> 2, h = wg & 3;
    int sN = src[e], dN = dst[e];
    float eav = ea[e];

    const float4 qv = *(const float4*)(q + (size_t)dN * HCC + h * CCC + lane * 4);
    const float4 kv = *(const float4*)(k + (size_t)sN * HCC + h * CCC + lane * 4);
    const float4 wv = *(const float4*)(We + h * CCC + lane * 4);

    float s = qv.x * fmaf(eav, wv.x, kv.x) + qv.y * fmaf(eav, wv.y, kv.y)
            + qv.z * fmaf(eav, wv.z, kv.z) + qv.w * fmaf(eav, wv.w, kv.w);
#pragma unroll
    for (int off = 16; off; off >>= 1) s += __shfl_xor_sync(0xffffffffu, s, off);

    if (lane == 0) {
        float pv = expf(s * 0.08838834764831845f);
        p[wg] = pv;
        atomicAdd(den + (size_t)dN * HH + h, pv);
    }
}

// ---------------- Edge pass 2 ----------------
__global__ __launch_bounds__(256) void edge_agg_k(
    const float* __restrict__ v, const float* __restrict__ ea,
    const int* __restrict__ src, const int* __restrict__ dst,
    const float* __restrict__ We, const float* __restrict__ p,
    const float* __restrict__ den, float* __restrict__ agg)
{
    int wg = blockIdx.x * 8 + (threadIdx.x >> 5);
    int lane = threadIdx.x & 31;
    int e = wg >> 2, h = wg & 3;
    int sN = src[e], dN = dst[e];
    float eav = ea[e];

    float a = p[wg] / (den[(size_t)dN * HH + h] + 1e-16f);

    const float4 vv = *(const float4*)(v + (size_t)sN * HCC + h * CCC + lane * 4);
    const float4 wv = *(const float4*)(We + h * CCC + lane * 4);
    float4 m;
    m.x = fmaf(eav, wv.x, vv.x) * a;
    m.y = fmaf(eav, wv.y, vv.y) * a;
    m.z = fmaf(eav, wv.z, vv.z) * a;
    m.w = fmaf(eav, wv.w, vv.w) * a;

    atomicAdd((float4*)(agg + (size_t)dN * HCC + h * CCC + lane * 4), m);
}

// ---------------- Fused ELU + residual + LayerNorm ----------------
__global__ __launch_bounds__(256) void ln_k(
    const float* __restrict__ x, const float* __restrict__ h,
    const float* __restrict__ gamma, const float* __restrict__ beta,
    float* __restrict__ out)
{
    int row = blockIdx.x * 8 + (threadIdx.x >> 5);
    int lane = threadIdx.x & 31;

    const float4 xv = *(const float4*)(x + (size_t)row * HIDD + lane * 4);
    const float4 hv = *(const float4*)(h + (size_t)row * HIDD + lane * 4);

    float4 y;
    y.x = xv.x + (hv.x > 0.f ? hv.x : expm1f(hv.x));
    y.y = xv.y + (hv.y > 0.f ? hv.y : expm1f(hv.y));
    y.z = xv.z + (hv.z > 0.f ? hv.z : expm1f(hv.z));
    y.w = xv.w + (hv.w > 0.f ? hv.w : expm1f(hv.w));

    float sum = y.x + y.y + y.z + y.w;
    float sq  = y.x * y.x + y.y * y.y + y.z * y.z + y.w * y.w;
#pragma unroll
    for (int off = 16; off; off >>= 1) {
        sum += __shfl_xor_sync(0xffffffffu, sum, off);
        sq  += __shfl_xor_sync(0xffffffffu, sq, off);
    }
    float mu = sum * (1.f / 128.f);
    float var = sq * (1.f / 128.f) - mu * mu;
    float inv = rsqrtf(var + 1e-5f);

    const float4 gv = *(const float4*)(gamma + lane * 4);
    const float4 bv = *(const float4*)(beta + lane * 4);
    float4 o;
    o.x = (y.x - mu) * inv * gv.x + bv.x;
    o.y = (y.y - mu) * inv * gv.y + bv.y;
    o.z = (y.z - mu) * inv * gv.z + bv.z;
    o.w = (y.w - mu) * inv * gv.w + bv.w;
    *(float4*)(out + (size_t)row * HIDD + lane * 4) = o;
}

// ---------------- host ----------------
extern "C" void kernel_launch(void* const* d_in, const int* in_sizes, int n_in,
                              void* d_out, int out_size)
{
    const float* x_in  = (const float*)d_in[0];
    const int*   ei    = (const int*)d_in[1];
    const float* ea    = (const float*)d_in[2];
    const float* Wq    = (const float*)d_in[3];
    const float* bq    = (const float*)d_in[4];
    const float* Wk    = (const float*)d_in[5];
    const float* bk    = (const float*)d_in[6];
    const float* Wv    = (const float*)d_in[7];
    const float* bv    = (const float*)d_in[8];
    const float* We    = (const float*)d_in[9];
    const float* Wskip = (const float*)d_in[10];
    const float* bskip = (const float*)d_in[11];
    const float* Wproj = (const float*)d_in[12];
    const float* bproj = (const float*)d_in[13];
    const float* gamma = (const float*)d_in[14];
    const float* beta  = (const float*)d_in[15];

    float *q, *k, *v, *agg, *h, *xbuf, *p, *den, *wf, *bfv;
    cudaGetSymbolAddress((void**)&q,    g_q);
    cudaGetSymbolAddress((void**)&k,    g_k);
    cudaGetSymbolAddress((void**)&v,    g_v);
    cudaGetSymbolAddress((void**)&agg,  g_agg);
    cudaGetSymbolAddress((void**)&h,    g_h);
    cudaGetSymbolAddress((void**)&xbuf, g_x);
    cudaGetSymbolAddress((void**)&p,    g_p);
    cudaGetSymbolAddress((void**)&den,  g_den);
    cudaGetSymbolAddress((void**)&wf,   g_wf);
    cudaGetSymbolAddress((void**)&bfv,  g_bf);

    cudaFuncSetAttribute(gemm_qkv,  cudaFuncAttributeMaxDynamicSharedMemorySize, QKV_SMEM);
    cudaFuncSetAttribute(gemm_proj, cudaFuncAttributeMaxDynamicSharedMemorySize, PRJ_SMEM);

    const int* src = ei;
    const int* dst = ei + EE;

    cudaMemcpyAsync(xbuf, x_in, (size_t)NN * HIDD * sizeof(float),
                    cudaMemcpyDeviceToDevice);

    // Precompute fused skip->proj weights/biases
    wf_k<<<dim3(64, 3), 256>>>(Wskip, Wproj, wf);
    bf_k<<<3, 128>>>(bskip, Wproj, bproj, bfv);

    dim3 gridQKV(4, NPAD / 128);    // (4, 391)
    dim3 gridPRJ(1, NPAD / 128);    // (1, 391)
    const int edgeBlocks = (EE * HH) / 8;
    const int lnBlocks = NN / 8;

    for (int l = 0; l < LLL; l++) {
        float* xo = (l == LLL - 1) ? (float*)d_out : xbuf;
        size_t wo = (size_t)l * HIDD * HCC;

        gemm_qkv<<<gridQKV, 256, QKV_SMEM>>>(
            xbuf, Wq + wo, Wk + wo, Wv + wo,
            bq + l * HCC, bk + l * HCC, bv + l * HCC, q, k, v);

        cudaMemsetAsync(den, 0, (size_t)NN * HH * sizeof(float));
        cudaMemsetAsync(agg, 0, (size_t)NN * HCC * sizeof(float));

        edge_attn_k<<<edgeBlocks, 256>>>(q, k, ea, src, dst, We + l * HCC, p, den);
        edge_agg_k<<<edgeBlocks, 256>>>(v, ea, src, dst, We + l * HCC, p, den, agg);

        gemm_proj<<<gridPRJ, 256, PRJ_SMEM>>>(
            agg, Wproj + (size_t)l * HCC * HIDD,
            xbuf, wf + (size_t)l * HIDD * HIDD,
            bfv + l * HIDD, h);

        ln_k<<<lnBlocks, 256>>>(xbuf, h, gamma + l * HIDD, beta + l * HIDD, xo);
    }
}

// round 6
// speedup vs baseline: 2.1602x; 1.3688x over previous
#include <cuda_runtime.h>
#include <math.h>
#include <stdint.h>

#define NN 50000
#define NPAD 50048          // 391 * 128
#define EE 100000
#define HIDD 128
#define HH 4
#define CCC 128
#define HCC 512
#define LLL 3

// ---------------- scratch ----------------
__device__ float g_q[(size_t)NPAD * HCC];
__device__ float g_k[(size_t)NPAD * HCC];
__device__ float g_v[(size_t)NPAD * HCC];
__device__ float g_agg[(size_t)NPAD * HCC];
__device__ float g_h[(size_t)NPAD * HIDD];
__device__ float g_x[(size_t)NPAD * HIDD];
__device__ float g_den[(size_t)NPAD * HH];
__device__ float g_wf[(size_t)LLL * HIDD * HIDD];   // Wskip @ Wproj
__device__ float g_bf[(size_t)LLL * HIDD];          // bskip @ Wproj + bproj

__device__ __forceinline__ float to_tf32(float x) {
    unsigned r;
    asm("cvt.rna.tf32.f32 %0, %1;" : "=r"(r) : "f"(x));
    return __uint_as_float(r);
}

// mma.m16n8k8 tf32: D += A*B (acc in-place)
__device__ __forceinline__ void mma168(float* d, const uint32_t* a, const uint32_t* b) {
    asm volatile("mma.sync.aligned.m16n8k8.row.col.f32.tf32.tf32.f32 "
        "{%0,%1,%2,%3}, {%4,%5,%6,%7}, {%8,%9}, {%0,%1,%2,%3};"
        : "+f"(d[0]), "+f"(d[1]), "+f"(d[2]), "+f"(d[3])
        : "r"(a[0]), "r"(a[1]), "r"(a[2]), "r"(a[3]), "r"(b[0]), "r"(b[1]));
}

// Fragment-order smem layouts (units: A 16B/lane, B 8B/lane), XOR-swizzled.
// A tile frag (m16 x k8): elem(r,c): lane=(r&7)*4+(c&3), reg=(r>>3)+2*(c>>2)
//   addr16(k8, m_tile, lane) = (k8*256 + m_tile*32 + lane) ^ (k8&7)
// B tile frag (k8 x n8):  elem(k,n): lane=(n&7)*4+(k&3), reg=k>>2
//   addr8(k8l, n_tile, lane) = ((k8l*16+n_tile)*32 + lane) ^ (n_tile&7)

#define QKV_SMEM_F (16384 + 2*4096)     // floats: A whole-K + B dbuf
#define PRJ_SMEM_F (2*4096 + 2*4096)    // floats: A dbuf + B dbuf

// ---------------- Fused QKV GEMM (tf32 mma, A whole-K resident) ----------------
__global__ __launch_bounds__(256, 2) void gemm_qkv_mma(
    const float* __restrict__ A,
    const float* __restrict__ W0, const float* __restrict__ W1, const float* __restrict__ W2,
    const float* __restrict__ b0, const float* __restrict__ b1, const float* __restrict__ b2,
    float* __restrict__ o0, float* __restrict__ o1, float* __restrict__ o2)
{
    extern __shared__ float sm[];
    float* As = sm;                 // 16384 floats (128m x 128k fragment-order)
    float* Bs = sm + 16384;         // 2 x 4096 floats (32k x 128n chunks)

    const int tid = threadIdx.x;
    const int wid = tid >> 5;
    const int lane = tid & 31;
    const int m0 = blockIdx.x * 128;
    const int wm = wid >> 2;        // 0..1
    const int wn = wid & 3;         // 0..3

    const float* Wp[3] = {W0, W1, W2};
    const float* bp[3] = {b0, b1, b2};
    float*       op[3] = {o0, o1, o2};

    // ---- A resident load (tf32, fragment-order scatter) ----
#pragma unroll
    for (int g = 0; g < 16; g++) {
        int i = tid + g * 256;
        int m = i >> 5, k4 = (i & 31) * 4;
        float4 a = *(const float4*)(A + (size_t)(m0 + m) * HIDD + k4);
        int m_tile = m >> 4, r = m & 15;
        float vals[4] = {a.x, a.y, a.z, a.w};
#pragma unroll
        for (int j = 0; j < 4; j++) {
            int kk = k4 + j;
            int c = kk & 7, k8 = kk >> 3;
            int lp = (r & 7) * 4 + (c & 3);
            int reg = (r >> 3) + 2 * (c >> 2);
            uint32_t u = (uint32_t)(k8 * 256 + m_tile * 32 + lp) ^ (uint32_t)(k8 & 7);
            As[u * 4 + reg] = to_tf32(vals[j]);
        }
    }

    float4 streg[4];
    auto ldgB = [&](const float* W, int ncol0, int k0) {
#pragma unroll
        for (int g = 0; g < 4; g++) {
            int i = tid + g * 256;
            int kl = i >> 5, n4 = (i & 31) * 4;
            streg[g] = *(const float4*)(W + (size_t)(k0 + kl) * HCC + ncol0 + n4);
        }
    };
    auto stsB = [&](int buf) {
        float* B = Bs + buf * 4096;
#pragma unroll
        for (int g = 0; g < 4; g++) {
            int i = tid + g * 256;
            int kl = i >> 5, n4 = (i & 31) * 4;
            int c = kl & 7, k8l = kl >> 3, reg = c >> 2;
            float vals[4] = {streg[g].x, streg[g].y, streg[g].z, streg[g].w};
#pragma unroll
            for (int j = 0; j < 4; j++) {
                int n = n4 + j;
                int n_tile = n >> 3;
                int lp = (n & 7) * 4 + (c & 3);
                uint32_t v = (uint32_t)((k8l * 16 + n_tile) * 32 + lp) ^ (uint32_t)(n_tile & 7);
                B[v * 2 + reg] = to_tf32(vals[j]);
            }
        }
    };

    float acc[4][4][4];
    auto initAcc = [&](int t) {
        const float* bias = bp[t >> 2] + (t & 3) * 128 + wn * 32;
#pragma unroll
        for (int j = 0; j < 4; j++) {
            float bv0 = __ldg(bias + j * 8 + 2 * (lane & 3));
            float bv1 = __ldg(bias + j * 8 + 2 * (lane & 3) + 1);
#pragma unroll
            for (int i = 0; i < 4; i++) {
                acc[i][j][0] = bv0; acc[i][j][1] = bv1;
                acc[i][j][2] = bv0; acc[i][j][3] = bv1;
            }
        }
    };
    auto epilogue = [&](int t) {
        float* out = op[t >> 2];
        int col = (t & 3) * 128 + wn * 32 + 2 * (lane & 3);
#pragma unroll
        for (int i = 0; i < 4; i++) {
            int row = m0 + wm * 64 + i * 16 + (lane >> 2);
#pragma unroll
            for (int j = 0; j < 4; j++) {
                *(float2*)(out + (size_t)row * HCC + col + j * 8) =
                    make_float2(acc[i][j][0], acc[i][j][1]);
                *(float2*)(out + (size_t)(row + 8) * HCC + col + j * 8) =
                    make_float2(acc[i][j][2], acc[i][j][3]);
            }
        }
    };
    auto mmaChunk = [&](int buf, int kc) {
        const float* B = Bs + buf * 4096;
#pragma unroll
        for (int k8l = 0; k8l < 4; k8l++) {
            int k8 = kc * 4 + k8l;
            uint32_t af[4][4];
#pragma unroll
            for (int i = 0; i < 4; i++) {
                uint32_t u = (uint32_t)(k8 * 256 + (wm * 4 + i) * 32 + lane) ^ (uint32_t)(k8 & 7);
                uint4 t4 = *(const uint4*)(As + u * 4);
                af[i][0] = t4.x; af[i][1] = t4.y; af[i][2] = t4.z; af[i][3] = t4.w;
            }
            uint32_t bf[4][2];
#pragma unroll
            for (int j = 0; j < 4; j++) {
                int n_tile = wn * 4 + j;
                uint32_t v = (uint32_t)((k8l * 16 + n_tile) * 32 + lane) ^ (uint32_t)(n_tile & 7);
                uint2 t2 = *(const uint2*)(B + v * 2);
                bf[j][0] = t2.x; bf[j][1] = t2.y;
            }
#pragma unroll
            for (int i = 0; i < 4; i++)
#pragma unroll
                for (int j = 0; j < 4; j++)
                    mma168(acc[i][j], af[i], bf[j]);
        }
    };

    // prologue
    ldgB(W0, 0, 0);
    stsB(0);
    initAcc(0);

    for (int s = 0; s < 48; s++) {
        __syncthreads();
        int t = s >> 2, kc = s & 3;
        if (s < 47) {
            int s1 = s + 1, t1 = s1 >> 2, kc1 = s1 & 3;
            ldgB(Wp[t1 >> 2], (t1 & 3) * 128, kc1 * 32);
        }
        mmaChunk(s & 1, kc);
        if (s < 47) stsB((s + 1) & 1);
        if (kc == 3) {
            epilogue(t);
            if (t < 11) initAcc(t + 1);
        }
    }
}

// ---------------- Proj GEMM (tf32 mma): out = (agg/den)@Wproj + x@Wf + bias ----------------
__global__ __launch_bounds__(256, 2) void gemm_proj_mma(
    const float* __restrict__ A1, const float* __restrict__ W1,
    const float* __restrict__ A2, const float* __restrict__ W2,
    const float* __restrict__ den, const float* __restrict__ bias,
    float* __restrict__ out)
{
    extern __shared__ float sm[];
    float* As = sm;                 // 2 x 4096 floats (128m x 32k chunks)
    float* Bs = sm + 8192;          // 2 x 4096 floats (32k x 128n chunks)

    const int tid = threadIdx.x;
    const int wid = tid >> 5;
    const int lane = tid & 31;
    const int m0 = blockIdx.x * 128;
    const int wm = wid >> 2;
    const int wn = wid & 3;

    float4 sa[4], sb[4];
    auto ldgStage = [&](int s1) {
        const float* Ax; const float* Wx; int K; int k0; bool norm;
        if (s1 < 16) { Ax = A1; Wx = W1; K = HCC;  k0 = s1 * 32;        norm = true;  }
        else         { Ax = A2; Wx = W2; K = HIDD; k0 = (s1 - 16) * 32; norm = false; }
#pragma unroll
        for (int g = 0; g < 4; g++) {
            int i = tid + g * 256;
            int r = i >> 3, c4 = (i & 7) * 4;
            float4 a = *(const float4*)(Ax + (size_t)(m0 + r) * K + k0 + c4);
            if (norm) {
                int hh = (k0 + c4) >> 7;
                float dsc = 1.f / (__ldg(den + (size_t)(m0 + r) * HH + hh) + 1e-16f);
                a.x *= dsc; a.y *= dsc; a.z *= dsc; a.w *= dsc;
            }
            sa[g] = a;
        }
#pragma unroll
        for (int g = 0; g < 4; g++) {
            int i = tid + g * 256;
            int kl = i >> 5, n4 = (i & 31) * 4;
            sb[g] = *(const float4*)(Wx + (size_t)(k0 + kl) * HIDD + n4);
        }
    };
    auto stsStage = [&](int buf) {
        float* Adst = As + buf * 4096;
        float* Bdst = Bs + buf * 4096;
#pragma unroll
        for (int g = 0; g < 4; g++) {
            int i = tid + g * 256;
            int r = i >> 3, c4 = (i & 7) * 4;
            int m_tile = r >> 4, rr = r & 15;
            float vals[4] = {sa[g].x, sa[g].y, sa[g].z, sa[g].w};
#pragma unroll
            for (int j = 0; j < 4; j++) {
                int kk = c4 + j;
                int c = kk & 7, k8l = kk >> 3;
                int lp = (rr & 7) * 4 + (c & 3);
                int reg = (rr >> 3) + 2 * (c >> 2);
                uint32_t u = (uint32_t)(k8l * 256 + m_tile * 32 + lp) ^ (uint32_t)(k8l & 7);
                Adst[u * 4 + reg] = to_tf32(vals[j]);
            }
        }
#pragma unroll
        for (int g = 0; g < 4; g++) {
            int i = tid + g * 256;
            int kl = i >> 5, n4 = (i & 31) * 4;
            int c = kl & 7, k8l = kl >> 3, reg = c >> 2;
            float vals[4] = {sb[g].x, sb[g].y, sb[g].z, sb[g].w};
#pragma unroll
            for (int j = 0; j < 4; j++) {
                int n = n4 + j;
                int n_tile = n >> 3;
                int lp = (n & 7) * 4 + (c & 3);
                uint32_t v = (uint32_t)((k8l * 16 + n_tile) * 32 + lp) ^ (uint32_t)(n_tile & 7);
                Bdst[v * 2 + reg] = to_tf32(vals[j]);
            }
        }
    };

    float acc[4][4][4];
    {
        const float* bp = bias + wn * 32;
#pragma unroll
        for (int j = 0; j < 4; j++) {
            float bv0 = __ldg(bp + j * 8 + 2 * (lane & 3));
            float bv1 = __ldg(bp + j * 8 + 2 * (lane & 3) + 1);
#pragma unroll
            for (int i = 0; i < 4; i++) {
                acc[i][j][0] = bv0; acc[i][j][1] = bv1;
                acc[i][j][2] = bv0; acc[i][j][3] = bv1;
            }
        }
    }

    ldgStage(0);
    stsStage(0);

    for (int s = 0; s < 20; s++) {
        __syncthreads();
        if (s < 19) ldgStage(s + 1);
        {
            const float* Ac = As + (s & 1) * 4096;
            const float* Bc = Bs + (s & 1) * 4096;
#pragma unroll
            for (int k8l = 0; k8l < 4; k8l++) {
                uint32_t af[4][4];
#pragma unroll
                for (int i = 0; i < 4; i++) {
                    uint32_t u = (uint32_t)(k8l * 256 + (wm * 4 + i) * 32 + lane) ^ (uint32_t)(k8l & 7);
                    uint4 t4 = *(const uint4*)(Ac + u * 4);
                    af[i][0] = t4.x; af[i][1] = t4.y; af[i][2] = t4.z; af[i][3] = t4.w;
                }
                uint32_t bf[4][2];
#pragma unroll
                for (int j = 0; j < 4; j++) {
                    int n_tile = wn * 4 + j;
                    uint32_t v = (uint32_t)((k8l * 16 + n_tile) * 32 + lane) ^ (uint32_t)(n_tile & 7);
                    uint2 t2 = *(const uint2*)(Bc + v * 2);
                    bf[j][0] = t2.x; bf[j][1] = t2.y;
                }
#pragma unroll
                for (int i = 0; i < 4; i++)
#pragma unroll
                    for (int j = 0; j < 4; j++)
                        mma168(acc[i][j], af[i], bf[j]);
            }
        }
        if (s < 19) stsStage((s + 1) & 1);
    }

    // epilogue
    int col = wn * 32 + 2 * (lane & 3);
#pragma unroll
    for (int i = 0; i < 4; i++) {
        int row = m0 + wm * 64 + i * 16 + (lane >> 2);
#pragma unroll
        for (int j = 0; j < 4; j++) {
            *(float2*)(out + (size_t)row * HIDD + col + j * 8) =
                make_float2(acc[i][j][0], acc[i][j][1]);
            *(float2*)(out + (size_t)(row + 8) * HIDD + col + j * 8) =
                make_float2(acc[i][j][2], acc[i][j][3]);
        }
    }
}

// ---------------- Precompute Wf = Wskip @ Wproj ----------------
__global__ void wf_k(const float* __restrict__ Wskip, const float* __restrict__ Wproj,
                     float* __restrict__ Wf)
{
    int l = blockIdx.y;
    int e = blockIdx.x * 256 + threadIdx.x;
    int i = e >> 7, j = e & 127;
    const float* ws = Wskip + (size_t)l * HIDD * HCC + (size_t)i * HCC;
    const float* wp = Wproj + (size_t)l * HCC * HIDD + j;
    float s = 0.f;
#pragma unroll 8
    for (int k = 0; k < HCC; k++) s = fmaf(ws[k], wp[(size_t)k * HIDD], s);
    Wf[(size_t)l * HIDD * HIDD + e] = s;
}

__global__ void bf_k(const float* __restrict__ bskip, const float* __restrict__ Wproj,
                     const float* __restrict__ bproj, float* __restrict__ bf)
{
    int l = blockIdx.x, j = threadIdx.x;
    const float* bs = bskip + (size_t)l * HCC;
    const float* wp = Wproj + (size_t)l * HCC * HIDD + j;
    float s = bproj[(size_t)l * HIDD + j];
#pragma unroll 8
    for (int k = 0; k < HCC; k++) s = fmaf(bs[k], wp[(size_t)k * HIDD], s);
    bf[l * HIDD + j] = s;
}

// ---------------- Single fused edge pass ----------------
// p = exp(scale*q[dst]·(k[src]+ea*We)); den[dst]+=p; agg[dst]+=p*(v[src]+ea*We)
__global__ __launch_bounds__(256) void edge_k(
    const float* __restrict__ q, const float* __restrict__ k,
    const float* __restrict__ v, const float* __restrict__ ea,
    const int* __restrict__ src, const int* __restrict__ dst,
    const float* __restrict__ We, float* __restrict__ den,
    float* __restrict__ agg)
{
    int wg = blockIdx.x * 8 + (threadIdx.x >> 5);
    int lane = threadIdx.x & 31;
    int e = wg >> 2, h = wg & 3;
    int sN = src[e], dN = dst[e];
    float eav = ea[e];

    const float4 qv = *(const float4*)(q + (size_t)dN * HCC + h * CCC + lane * 4);
    const float4 kv = *(const float4*)(k + (size_t)sN * HCC + h * CCC + lane * 4);
    const float4 wv = *(const float4*)(We + h * CCC + lane * 4);

    float s = qv.x * fmaf(eav, wv.x, kv.x) + qv.y * fmaf(eav, wv.y, kv.y)
            + qv.z * fmaf(eav, wv.z, kv.z) + qv.w * fmaf(eav, wv.w, kv.w);
#pragma unroll
    for (int off = 16; off; off >>= 1) s += __shfl_xor_sync(0xffffffffu, s, off);

    float pv = expf(s * 0.08838834764831845f);   // 1/sqrt(128)
    if (lane == 0) atomicAdd(den + (size_t)dN * HH + h, pv);

    const float4 vv = *(const float4*)(v + (size_t)sN * HCC + h * CCC + lane * 4);
    float4 m;
    m.x = fmaf(eav, wv.x, vv.x) * pv;
    m.y = fmaf(eav, wv.y, vv.y) * pv;
    m.z = fmaf(eav, wv.z, vv.z) * pv;
    m.w = fmaf(eav, wv.w, vv.w) * pv;
    atomicAdd((float4*)(agg + (size_t)dN * HCC + h * CCC + lane * 4), m);
}

// ---------------- Fused ELU + residual + LayerNorm ----------------
__global__ __launch_bounds__(256) void ln_k(
    const float* __restrict__ x, const float* __restrict__ h,
    const float* __restrict__ gamma, const float* __restrict__ beta,
    float* __restrict__ out)
{
    int row = blockIdx.x * 8 + (threadIdx.x >> 5);
    int lane = threadIdx.x & 31;

    const float4 xv = *(const float4*)(x + (size_t)row * HIDD + lane * 4);
    const float4 hv = *(const float4*)(h + (size_t)row * HIDD + lane * 4);

    float4 y;
    y.x = xv.x + (hv.x > 0.f ? hv.x : expm1f(hv.x));
    y.y = xv.y + (hv.y > 0.f ? hv.y : expm1f(hv.y));
    y.z = xv.z + (hv.z > 0.f ? hv.z : expm1f(hv.z));
    y.w = xv.w + (hv.w > 0.f ? hv.w : expm1f(hv.w));

    float sum = y.x + y.y + y.z + y.w;
    float sq  = y.x * y.x + y.y * y.y + y.z * y.z + y.w * y.w;
#pragma unroll
    for (int off = 16; off; off >>= 1) {
        sum += __shfl_xor_sync(0xffffffffu, sum, off);
        sq  += __shfl_xor_sync(0xffffffffu, sq, off);
    }
    float mu = sum * (1.f / 128.f);
    float var = sq * (1.f / 128.f) - mu * mu;
    float inv = rsqrtf(var + 1e-5f);

    const float4 gv = *(const float4*)(gamma + lane * 4);
    const float4 bv = *(const float4*)(beta + lane * 4);
    float4 o;
    o.x = (y.x - mu) * inv * gv.x + bv.x;
    o.y = (y.y - mu) * inv * gv.y + bv.y;
    o.z = (y.z - mu) * inv * gv.z + bv.z;
    o.w = (y.w - mu) * inv * gv.w + bv.w;
    *(float4*)(out + (size_t)row * HIDD + lane * 4) = o;
}

// ---------------- host ----------------
extern "C" void kernel_launch(void* const* d_in, const int* in_sizes, int n_in,
                              void* d_out, int out_size)
{
    const float* x_in  = (const float*)d_in[0];
    const int*   ei    = (const int*)d_in[1];
    const float* ea    = (const float*)d_in[2];
    const float* Wq    = (const float*)d_in[3];
    const float* bq    = (const float*)d_in[4];
    const float* Wk    = (const float*)d_in[5];
    const float* bk    = (const float*)d_in[6];
    const float* Wv    = (const float*)d_in[7];
    const float* bv    = (const float*)d_in[8];
    const float* We    = (const float*)d_in[9];
    const float* Wskip = (const float*)d_in[10];
    const float* bskip = (const float*)d_in[11];
    const float* Wproj = (const float*)d_in[12];
    const float* bproj = (const float*)d_in[13];
    const float* gamma = (const float*)d_in[14];
    const float* beta  = (const float*)d_in[15];

    float *q, *k, *v, *agg, *h, *xbuf, *den, *wf, *bfv;
    cudaGetSymbolAddress((void**)&q,    g_q);
    cudaGetSymbolAddress((void**)&k,    g_k);
    cudaGetSymbolAddress((void**)&v,    g_v);
    cudaGetSymbolAddress((void**)&agg,  g_agg);
    cudaGetSymbolAddress((void**)&h,    g_h);
    cudaGetSymbolAddress((void**)&xbuf, g_x);
    cudaGetSymbolAddress((void**)&den,  g_den);
    cudaGetSymbolAddress((void**)&wf,   g_wf);
    cudaGetSymbolAddress((void**)&bfv,  g_bf);

    cudaFuncSetAttribute(gemm_qkv_mma,  cudaFuncAttributeMaxDynamicSharedMemorySize,
                         QKV_SMEM_F * 4);
    cudaFuncSetAttribute(gemm_proj_mma, cudaFuncAttributeMaxDynamicSharedMemorySize,
                         PRJ_SMEM_F * 4);

    const int* src = ei;
    const int* dst = ei + EE;

    cudaMemcpyAsync(xbuf, x_in, (size_t)NN * HIDD * sizeof(float),
                    cudaMemcpyDeviceToDevice);

    wf_k<<<dim3(64, 3), 256>>>(Wskip, Wproj, wf);
    bf_k<<<3, 128>>>(bskip, Wproj, bproj, bfv);

    const int nBlocks = NPAD / 128;         // 391
    const int edgeBlocks = (EE * HH) / 8;   // 50000
    const int lnBlocks = NN / 8;            // 6250

    for (int l = 0; l < LLL; l++) {
        float* xo = (l == LLL - 1) ? (float*)d_out : xbuf;
        size_t wo = (size_t)l * HIDD * HCC;

        gemm_qkv_mma<<<nBlocks, 256, QKV_SMEM_F * 4>>>(
            xbuf, Wq + wo, Wk + wo, Wv + wo,
            bq + l * HCC, bk + l * HCC, bv + l * HCC, q, k, v);

        cudaMemsetAsync(den, 0, (size_t)NN * HH * sizeof(float));
        cudaMemsetAsync(agg, 0, (size_t)NN * HCC * sizeof(float));

        edge_k<<<edgeBlocks, 256>>>(q, k, v, ea, src, dst, We + l * HCC, den, agg);

        gemm_proj_mma<<<nBlocks, 256, PRJ_SMEM_F * 4>>>(
            agg, Wproj + (size_t)l * HCC * HIDD,
            xbuf, wf + (size_t)l * HIDD * HIDD,
            den, bfv + l * HIDD, h);

        ln_k<<<lnBlocks, 256>>>(xbuf, h, gamma + l * HIDD, beta + l * HIDD, xo);
    }
}

// round 7
// speedup vs baseline: 2.2005x; 1.0187x over previous
#include <cuda_runtime.h>
#include <cuda_bf16.h>
#include <math.h>
#include <stdint.h>

#define NN 50000
#define NPAD 50048          // 391 * 128
#define EE 100000
#define HIDD 128
#define HH 4
#define CCC 128
#define HCC 512
#define LLL 3

// ---------------- scratch ----------------
__device__ __nv_bfloat16 g_qb[(size_t)NPAD * HCC];
__device__ __nv_bfloat16 g_kb[(size_t)NPAD * HCC];
__device__ float g_v[(size_t)NPAD * HCC];
__device__ float g_agg[(size_t)NPAD * HCC];
__device__ float g_h[(size_t)NPAD * HIDD];
__device__ float g_x[(size_t)NPAD * HIDD];
__device__ float g_den[(size_t)NPAD * HH];
__device__ float g_wf[(size_t)LLL * HIDD * HIDD];   // Wskip @ Wproj
__device__ float g_bf[(size_t)LLL * HIDD];          // bskip @ Wproj + bproj

__device__ __forceinline__ float to_tf32(float x) {
    unsigned r;
    asm("cvt.rna.tf32.f32 %0, %1;" : "=r"(r) : "f"(x));
    return __uint_as_float(r);
}

// mma.m16n8k8 tf32: D += A*B (acc in-place)
__device__ __forceinline__ void mma168(float* d, const uint32_t* a, const uint32_t* b) {
    asm volatile("mma.sync.aligned.m16n8k8.row.col.f32.tf32.tf32.f32 "
        "{%0,%1,%2,%3}, {%4,%5,%6,%7}, {%8,%9}, {%0,%1,%2,%3};"
        : "+f"(d[0]), "+f"(d[1]), "+f"(d[2]), "+f"(d[3])
        : "r"(a[0]), "r"(a[1]), "r"(a[2]), "r"(a[3]), "r"(b[0]), "r"(b[1]));
}

// Fragment-order smem layouts (units: A 16B/lane, B 8B/lane), XOR-swizzled.
#define QKV_SMEM_F (16384 + 2*4096)     // floats: A whole-K + B dbuf
#define PRJ_SMEM_F (2*4096 + 2*4096)    // floats: A dbuf + B dbuf

// ---------------- Fused QKV GEMM (tf32 mma, A whole-K resident, N-split x2) ----------------
// grid (2, 391): blockIdx.x = N-half, blockIdx.y = M-slab. Each CTA: 6 N-tiles (24 stages).
__global__ __launch_bounds__(256, 2) void gemm_qkv_mma(
    const float* __restrict__ A,
    const float* __restrict__ W0, const float* __restrict__ W1, const float* __restrict__ W2,
    const float* __restrict__ b0, const float* __restrict__ b1, const float* __restrict__ b2,
    __nv_bfloat16* __restrict__ oq, __nv_bfloat16* __restrict__ ok,
    float* __restrict__ ov)
{
    extern __shared__ float sm[];
    float* As = sm;                 // 16384 floats (128m x 128k fragment-order)
    float* Bs = sm + 16384;         // 2 x 4096 floats (32k x 128n chunks)

    const int tid = threadIdx.x;
    const int wid = tid >> 5;
    const int lane = tid & 31;
    const int ny = blockIdx.x;            // 0 or 1
    const int m0 = blockIdx.y * 128;
    const int wm = wid >> 2;              // 0..1
    const int wn = wid & 3;               // 0..3
    const int t0 = ny * 6;                // first global N-tile

    const float* Wp[3] = {W0, W1, W2};
    const float* bp[3] = {b0, b1, b2};

    // ---- A resident load (tf32, fragment-order scatter) ----
#pragma unroll
    for (int g = 0; g < 16; g++) {
        int i = tid + g * 256;
        int m = i >> 5, k4 = (i & 31) * 4;
        float4 a = *(const float4*)(A + (size_t)(m0 + m) * HIDD + k4);
        int m_tile = m >> 4, r = m & 15;
        float vals[4] = {a.x, a.y, a.z, a.w};
#pragma unroll
        for (int j = 0; j < 4; j++) {
            int kk = k4 + j;
            int c = kk & 7, k8 = kk >> 3;
            int lp = (r & 7) * 4 + (c & 3);
            int reg = (r >> 3) + 2 * (c >> 2);
            uint32_t u = (uint32_t)(k8 * 256 + m_tile * 32 + lp) ^ (uint32_t)(k8 & 7);
            As[u * 4 + reg] = to_tf32(vals[j]);
        }
    }

    float4 streg[4];
    auto ldgB = [&](const float* W, int ncol0, int k0) {
#pragma unroll
        for (int g = 0; g < 4; g++) {
            int i = tid + g * 256;
            int kl = i >> 5, n4 = (i & 31) * 4;
            streg[g] = *(const float4*)(W + (size_t)(k0 + kl) * HCC + ncol0 + n4);
        }
    };
    auto stsB = [&](int buf) {
        float* B = Bs + buf * 4096;
#pragma unroll
        for (int g = 0; g < 4; g++) {
            int i = tid + g * 256;
            int kl = i >> 5, n4 = (i & 31) * 4;
            int c = kl & 7, k8l = kl >> 3, reg = c >> 2;
            float vals[4] = {streg[g].x, streg[g].y, streg[g].z, streg[g].w};
#pragma unroll
            for (int j = 0; j < 4; j++) {
                int n = n4 + j;
                int n_tile = n >> 3;
                int lp = (n & 7) * 4 + (c & 3);
                uint32_t v = (uint32_t)((k8l * 16 + n_tile) * 32 + lp) ^ (uint32_t)(n_tile & 7);
                B[v * 2 + reg] = to_tf32(vals[j]);
            }
        }
    };

    float acc[4][4][4];
    auto initAcc = [&](int tg) {
        const float* bias = bp[tg >> 2] + (tg & 3) * 128 + wn * 32;
#pragma unroll
        for (int j = 0; j < 4; j++) {
            float bv0 = __ldg(bias + j * 8 + 2 * (lane & 3));
            float bv1 = __ldg(bias + j * 8 + 2 * (lane & 3) + 1);
#pragma unroll
            for (int i = 0; i < 4; i++) {
                acc[i][j][0] = bv0; acc[i][j][1] = bv1;
                acc[i][j][2] = bv0; acc[i][j][3] = bv1;
            }
        }
    };
    auto epilogue = [&](int tg) {
        const int w = tg >> 2;   // 0=q (bf16), 1=k (bf16), 2=v (fp32)
        const int col = (tg & 3) * 128 + wn * 32 + 2 * (lane & 3);
        if (w < 2) {
            __nv_bfloat16* out = (w == 0) ? oq : ok;
#pragma unroll
            for (int i = 0; i < 4; i++) {
                int row = m0 + wm * 64 + i * 16 + (lane >> 2);
#pragma unroll
                for (int j = 0; j < 4; j++) {
                    *(__nv_bfloat162*)(out + (size_t)row * HCC + col + j * 8) =
                        __floats2bfloat162_rn(acc[i][j][0], acc[i][j][1]);
                    *(__nv_bfloat162*)(out + (size_t)(row + 8) * HCC + col + j * 8) =
                        __floats2bfloat162_rn(acc[i][j][2], acc[i][j][3]);
                }
            }
        } else {
#pragma unroll
            for (int i = 0; i < 4; i++) {
                int row = m0 + wm * 64 + i * 16 + (lane >> 2);
#pragma unroll
                for (int j = 0; j < 4; j++) {
                    *(float2*)(ov + (size_t)row * HCC + col + j * 8) =
                        make_float2(acc[i][j][0], acc[i][j][1]);
                    *(float2*)(ov + (size_t)(row + 8) * HCC + col + j * 8) =
                        make_float2(acc[i][j][2], acc[i][j][3]);
                }
            }
        }
    };
    auto mmaChunk = [&](int buf, int kc) {
        const float* B = Bs + buf * 4096;
#pragma unroll
        for (int k8l = 0; k8l < 4; k8l++) {
            int k8 = kc * 4 + k8l;
            uint32_t af[4][4];
#pragma unroll
            for (int i = 0; i < 4; i++) {
                uint32_t u = (uint32_t)(k8 * 256 + (wm * 4 + i) * 32 + lane) ^ (uint32_t)(k8 & 7);
                uint4 t4 = *(const uint4*)(As + u * 4);
                af[i][0] = t4.x; af[i][1] = t4.y; af[i][2] = t4.z; af[i][3] = t4.w;
            }
            uint32_t bf[4][2];
#pragma unroll
            for (int j = 0; j < 4; j++) {
                int n_tile = wn * 4 + j;
                uint32_t v = (uint32_t)((k8l * 16 + n_tile) * 32 + lane) ^ (uint32_t)(n_tile & 7);
                uint2 t2 = *(const uint2*)(B + v * 2);
                bf[j][0] = t2.x; bf[j][1] = t2.y;
            }
#pragma unroll
            for (int i = 0; i < 4; i++)
#pragma unroll
                for (int j = 0; j < 4; j++)
                    mma168(acc[i][j], af[i], bf[j]);
        }
    };

    // prologue (first tile of this N-half)
    ldgB(Wp[t0 >> 2], (t0 & 3) * 128, 0);
    stsB(0);
    initAcc(t0);

    for (int s = 0; s < 24; s++) {
        __syncthreads();
        int tg = t0 + (s >> 2), kc = s & 3;
        if (s < 23) {
            int s1 = s + 1, tg1 = t0 + (s1 >> 2), kc1 = s1 & 3;
            ldgB(Wp[tg1 >> 2], (tg1 & 3) * 128, kc1 * 32);
        }
        mmaChunk(s & 1, kc);
        if (s < 23) stsB((s + 1) & 1);
        if (kc == 3) {
            epilogue(tg);
            if ((s >> 2) < 5) initAcc(tg + 1);
        }
    }
}

// ---------------- Proj GEMM (tf32 mma): out = (agg/den)@Wproj + x@Wf + bias ----------------
__global__ __launch_bounds__(256, 2) void gemm_proj_mma(
    const float* __restrict__ A1, const float* __restrict__ W1,
    const float* __restrict__ A2, const float* __restrict__ W2,
    const float* __restrict__ den, const float* __restrict__ bias,
    float* __restrict__ out)
{
    extern __shared__ float sm[];
    float* As = sm;                 // 2 x 4096 floats
    float* Bs = sm + 8192;          // 2 x 4096 floats

    const int tid = threadIdx.x;
    const int wid = tid >> 5;
    const int lane = tid & 31;
    const int m0 = blockIdx.x * 128;
    const int wm = wid >> 2;
    const int wn = wid & 3;

    float4 sa[4], sb[4];
    auto ldgStage = [&](int s1) {
        const float* Ax; const float* Wx; int K; int k0; bool norm;
        if (s1 < 16) { Ax = A1; Wx = W1; K = HCC;  k0 = s1 * 32;        norm = true;  }
        else         { Ax = A2; Wx = W2; K = HIDD; k0 = (s1 - 16) * 32; norm = false; }
#pragma unroll
        for (int g = 0; g < 4; g++) {
            int i = tid + g * 256;
            int r = i >> 3, c4 = (i & 7) * 4;
            float4 a = *(const float4*)(Ax + (size_t)(m0 + r) * K + k0 + c4);
            if (norm) {
                int hh = (k0 + c4) >> 7;
                float dsc = 1.f / (__ldg(den + (size_t)(m0 + r) * HH + hh) + 1e-16f);
                a.x *= dsc; a.y *= dsc; a.z *= dsc; a.w *= dsc;
            }
            sa[g] = a;
        }
#pragma unroll
        for (int g = 0; g < 4; g++) {
            int i = tid + g * 256;
            int kl = i >> 5, n4 = (i & 31) * 4;
            sb[g] = *(const float4*)(Wx + (size_t)(k0 + kl) * HIDD + n4);
        }
    };
    auto stsStage = [&](int buf) {
        float* Adst = As + buf * 4096;
        float* Bdst = Bs + buf * 4096;
#pragma unroll
        for (int g = 0; g < 4; g++) {
            int i = tid + g * 256;
            int r = i >> 3, c4 = (i & 7) * 4;
            int m_tile = r >> 4, rr = r & 15;
            float vals[4] = {sa[g].x, sa[g].y, sa[g].z, sa[g].w};
#pragma unroll
            for (int j = 0; j < 4; j++) {
                int kk = c4 + j;
                int c = kk & 7, k8l = kk >> 3;
                int lp = (rr & 7) * 4 + (c & 3);
                int reg = (rr >> 3) + 2 * (c >> 2);
                uint32_t u = (uint32_t)(k8l * 256 + m_tile * 32 + lp) ^ (uint32_t)(k8l & 7);
                Adst[u * 4 + reg] = to_tf32(vals[j]);
            }
        }
#pragma unroll
        for (int g = 0; g < 4; g++) {
            int i = tid + g * 256;
            int kl = i >> 5, n4 = (i & 31) * 4;
            int c = kl & 7, k8l = kl >> 3, reg = c >> 2;
            float vals[4] = {sb[g].x, sb[g].y, sb[g].z, sb[g].w};
#pragma unroll
            for (int j = 0; j < 4; j++) {
                int n = n4 + j;
                int n_tile = n >> 3;
                int lp = (n & 7) * 4 + (c & 3);
                uint32_t v = (uint32_t)((k8l * 16 + n_tile) * 32 + lp) ^ (uint32_t)(n_tile & 7);
                Bdst[v * 2 + reg] = to_tf32(vals[j]);
            }
        }
    };

    float acc[4][4][4];
    {
        const float* bp = bias + wn * 32;
#pragma unroll
        for (int j = 0; j < 4; j++) {
            float bv0 = __ldg(bp + j * 8 + 2 * (lane & 3));
            float bv1 = __ldg(bp + j * 8 + 2 * (lane & 3) + 1);
#pragma unroll
            for (int i = 0; i < 4; i++) {
                acc[i][j][0] = bv0; acc[i][j][1] = bv1;
                acc[i][j][2] = bv0; acc[i][j][3] = bv1;
            }
        }
    }

    ldgStage(0);
    stsStage(0);

    for (int s = 0; s < 20; s++) {
        __syncthreads();
        if (s < 19) ldgStage(s + 1);
        {
            const float* Ac = As + (s & 1) * 4096;
            const float* Bc = Bs + (s & 1) * 4096;
#pragma unroll
            for (int k8l = 0; k8l < 4; k8l++) {
                uint32_t af[4][4];
#pragma unroll
                for (int i = 0; i < 4; i++) {
                    uint32_t u = (uint32_t)(k8l * 256 + (wm * 4 + i) * 32 + lane) ^ (uint32_t)(k8l & 7);
                    uint4 t4 = *(const uint4*)(Ac + u * 4);
                    af[i][0] = t4.x; af[i][1] = t4.y; af[i][2] = t4.z; af[i][3] = t4.w;
                }
                uint32_t bf[4][2];
#pragma unroll
                for (int j = 0; j < 4; j++) {
                    int n_tile = wn * 4 + j;
                    uint32_t v = (uint32_t)((k8l * 16 + n_tile) * 32 + lane) ^ (uint32_t)(n_tile & 7);
                    uint2 t2 = *(const uint2*)(Bc + v * 2);
                    bf[j][0] = t2.x; bf[j][1] = t2.y;
                }
#pragma unroll
                for (int i = 0; i < 4; i++)
#pragma unroll
                    for (int j = 0; j < 4; j++)
                        mma168(acc[i][j], af[i], bf[j]);
            }
        }
        if (s < 19) stsStage((s + 1) & 1);
    }

    int col = wn * 32 + 2 * (lane & 3);
#pragma unroll
    for (int i = 0; i < 4; i++) {
        int row = m0 + wm * 64 + i * 16 + (lane >> 2);
#pragma unroll
        for (int j = 0; j < 4; j++) {
            *(float2*)(out + (size_t)row * HIDD + col + j * 8) =
                make_float2(acc[i][j][0], acc[i][j][1]);
            *(float2*)(out + (size_t)(row + 8) * HIDD + col + j * 8) =
                make_float2(acc[i][j][2], acc[i][j][3]);
        }
    }
}

// ---------------- Precompute Wf = Wskip @ Wproj ----------------
__global__ void wf_k(const float* __restrict__ Wskip, const float* __restrict__ Wproj,
                     float* __restrict__ Wf)
{
    int l = blockIdx.y;
    int e = blockIdx.x * 256 + threadIdx.x;
    int i = e >> 7, j = e & 127;
    const float* ws = Wskip + (size_t)l * HIDD * HCC + (size_t)i * HCC;
    const float* wp = Wproj + (size_t)l * HCC * HIDD + j;
    float s = 0.f;
#pragma unroll 8
    for (int k = 0; k < HCC; k++) s = fmaf(ws[k], wp[(size_t)k * HIDD], s);
    Wf[(size_t)l * HIDD * HIDD + e] = s;
}

__global__ void bf_k(const float* __restrict__ bskip, const float* __restrict__ Wproj,
                     const float* __restrict__ bproj, float* __restrict__ bf)
{
    int l = blockIdx.x, j = threadIdx.x;
    const float* bs = bskip + (size_t)l * HCC;
    const float* wp = Wproj + (size_t)l * HCC * HIDD + j;
    float s = bproj[(size_t)l * HIDD + j];
#pragma unroll 8
    for (int k = 0; k < HCC; k++) s = fmaf(bs[k], wp[(size_t)k * HIDD], s);
    bf[l * HIDD + j] = s;
}

// ---------------- Single fused edge pass (q,k bf16; v fp32) ----------------
__global__ __launch_bounds__(256) void edge_k(
    const __nv_bfloat16* __restrict__ q, const __nv_bfloat16* __restrict__ k,
    const float* __restrict__ v, const float* __restrict__ ea,
    const int* __restrict__ src, const int* __restrict__ dst,
    const float* __restrict__ We, float* __restrict__ den,
    float* __restrict__ agg)
{
    int wg = blockIdx.x * 8 + (threadIdx.x >> 5);
    int lane = threadIdx.x & 31;
    int e = wg >> 2, h = wg & 3;
    int sN = src[e], dN = dst[e];
    float eav = ea[e];

    // 4 bf16 each for q[dst] and k[src] (8B loads)
    uint2 qraw = *(const uint2*)(q + (size_t)dN * HCC + h * CCC + lane * 4);
    uint2 kraw = *(const uint2*)(k + (size_t)sN * HCC + h * CCC + lane * 4);
    float2 q01 = __bfloat1622float2(*(__nv_bfloat162*)&qraw.x);
    float2 q23 = __bfloat1622float2(*(__nv_bfloat162*)&qraw.y);
    float2 k01 = __bfloat1622float2(*(__nv_bfloat162*)&kraw.x);
    float2 k23 = __bfloat1622float2(*(__nv_bfloat162*)&kraw.y);
    const float4 wv = *(const float4*)(We + h * CCC + lane * 4);

    float s = q01.x * fmaf(eav, wv.x, k01.x) + q01.y * fmaf(eav, wv.y, k01.y)
            + q23.x * fmaf(eav, wv.z, k23.x) + q23.y * fmaf(eav, wv.w, k23.y);
#pragma unroll
    for (int off = 16; off; off >>= 1) s += __shfl_xor_sync(0xffffffffu, s, off);

    float pv = expf(s * 0.08838834764831845f);   // 1/sqrt(128)
    if (lane == 0) atomicAdd(den + (size_t)dN * HH + h, pv);

    const float4 vv = *(const float4*)(v + (size_t)sN * HCC + h * CCC + lane * 4);
    float4 m;
    m.x = fmaf(eav, wv.x, vv.x) * pv;
    m.y = fmaf(eav, wv.y, vv.y) * pv;
    m.z = fmaf(eav, wv.z, vv.z) * pv;
    m.w = fmaf(eav, wv.w, vv.w) * pv;
    atomicAdd((float4*)(agg + (size_t)dN * HCC + h * CCC + lane * 4), m);
}

// ---------------- Fused ELU + residual + LayerNorm ----------------
__global__ __launch_bounds__(256) void ln_k(
    const float* __restrict__ x, const float* __restrict__ h,
    const float* __restrict__ gamma, const float* __restrict__ beta,
    float* __restrict__ out)
{
    int row = blockIdx.x * 8 + (threadIdx.x >> 5);
    int lane = threadIdx.x & 31;

    const float4 xv = *(const float4*)(x + (size_t)row * HIDD + lane * 4);
    const float4 hv = *(const float4*)(h + (size_t)row * HIDD + lane * 4);

    float4 y;
    y.x = xv.x + (hv.x > 0.f ? hv.x : expm1f(hv.x));
    y.y = xv.y + (hv.y > 0.f ? hv.y : expm1f(hv.y));
    y.z = xv.z + (hv.z > 0.f ? hv.z : expm1f(hv.z));
    y.w = xv.w + (hv.w > 0.f ? hv.w : expm1f(hv.w));

    float sum = y.x + y.y + y.z + y.w;
    float sq  = y.x * y.x + y.y * y.y + y.z * y.z + y.w * y.w;
#pragma unroll
    for (int off = 16; off; off >>= 1) {
        sum += __shfl_xor_sync(0xffffffffu, sum, off);
        sq  += __shfl_xor_sync(0xffffffffu, sq, off);
    }
    float mu = sum * (1.f / 128.f);
    float var = sq * (1.f / 128.f) - mu * mu;
    float inv = rsqrtf(var + 1e-5f);

    const float4 gv = *(const float4*)(gamma + lane * 4);
    const float4 bv = *(const float4*)(beta + lane * 4);
    float4 o;
    o.x = (y.x - mu) * inv * gv.x + bv.x;
    o.y = (y.y - mu) * inv * gv.y + bv.y;
    o.z = (y.z - mu) * inv * gv.z + bv.z;
    o.w = (y.w - mu) * inv * gv.w + bv.w;
    *(float4*)(out + (size_t)row * HIDD + lane * 4) = o;
}

// ---------------- host ----------------
extern "C" void kernel_launch(void* const* d_in, const int* in_sizes, int n_in,
                              void* d_out, int out_size)
{
    const float* x_in  = (const float*)d_in[0];
    const int*   ei    = (const int*)d_in[1];
    const float* ea    = (const float*)d_in[2];
    const float* Wq    = (const float*)d_in[3];
    const float* bq    = (const float*)d_in[4];
    const float* Wk    = (const float*)d_in[5];
    const float* bk    = (const float*)d_in[6];
    const float* Wv    = (const float*)d_in[7];
    const float* bv    = (const float*)d_in[8];
    const float* We    = (const float*)d_in[9];
    const float* Wskip = (const float*)d_in[10];
    const float* bskip = (const float*)d_in[11];
    const float* Wproj = (const float*)d_in[12];
    const float* bproj = (const float*)d_in[13];
    const float* gamma = (const float*)d_in[14];
    const float* beta  = (const float*)d_in[15];

    __nv_bfloat16 *qb, *kb;
    float *v, *agg, *h, *xbuf, *den, *wf, *bfv;
    cudaGetSymbolAddress((void**)&qb,   g_qb);
    cudaGetSymbolAddress((void**)&kb,   g_kb);
    cudaGetSymbolAddress((void**)&v,    g_v);
    cudaGetSymbolAddress((void**)&agg,  g_agg);
    cudaGetSymbolAddress((void**)&h,    g_h);
    cudaGetSymbolAddress((void**)&xbuf, g_x);
    cudaGetSymbolAddress((void**)&den,  g_den);
    cudaGetSymbolAddress((void**)&wf,   g_wf);
    cudaGetSymbolAddress((void**)&bfv,  g_bf);

    cudaFuncSetAttribute(gemm_qkv_mma,  cudaFuncAttributeMaxDynamicSharedMemorySize,
                         QKV_SMEM_F * 4);
    cudaFuncSetAttribute(gemm_proj_mma, cudaFuncAttributeMaxDynamicSharedMemorySize,
                         PRJ_SMEM_F * 4);

    const int* src = ei;
    const int* dst = ei + EE;

    cudaMemcpyAsync(xbuf, x_in, (size_t)NN * HIDD * sizeof(float),
                    cudaMemcpyDeviceToDevice);

    wf_k<<<dim3(64, 3), 256>>>(Wskip, Wproj, wf);
    bf_k<<<3, 128>>>(bskip, Wproj, bproj, bfv);

    const int nBlocks = NPAD / 128;         // 391
    const int edgeBlocks = (EE * HH) / 8;   // 50000
    const int lnBlocks = NN / 8;            // 6250

    for (int l = 0; l < LLL; l++) {
        float* xo = (l == LLL - 1) ? (float*)d_out : xbuf;
        size_t wo = (size_t)l * HIDD * HCC;

        gemm_qkv_mma<<<dim3(2, nBlocks), 256, QKV_SMEM_F * 4>>>(
            xbuf, Wq + wo, Wk + wo, Wv + wo,
            bq + l * HCC, bk + l * HCC, bv + l * HCC, qb, kb, v);

        cudaMemsetAsync(den, 0, (size_t)NN * HH * sizeof(float));
        cudaMemsetAsync(agg, 0, (size_t)NN * HCC * sizeof(float));

        edge_k<<<edgeBlocks, 256>>>(qb, kb, v, ea, src, dst, We + l * HCC, den, agg);

        gemm_proj_mma<<<nBlocks, 256, PRJ_SMEM_F * 4>>>(
            agg, Wproj + (size_t)l * HCC * HIDD,
            xbuf, wf + (size_t)l * HIDD * HIDD,
            den, bfv + l * HIDD, h);

        ln_k<<<lnBlocks, 256>>>(xbuf, h, gamma + l * HIDD, beta + l * HIDD, xo);
    }
}

// round 8
// speedup vs baseline: 2.5159x; 1.1433x over previous
#include <cuda_runtime.h>
#include <cuda_bf16.h>
#include <math.h>
#include <stdint.h>

#define NN 50000
#define NPAD 50048          // 391 * 128
#define EE 100000
#define HIDD 128
#define HH 4
#define CCC 128
#define HCC 512
#define LLL 3

// ---------------- scratch ----------------
__device__ __nv_bfloat16 g_qb[(size_t)NPAD * HCC];
__device__ __nv_bfloat16 g_kb[(size_t)NPAD * HCC];
__device__ float g_v[(size_t)NPAD * HCC];
__device__ float g_agg[(size_t)NPAD * HCC];
__device__ float g_h[(size_t)NPAD * HIDD];
__device__ float g_x[(size_t)NPAD * HIDD];
__device__ float g_wf[(size_t)LLL * HIDD * HIDD];   // Wskip @ Wproj
__device__ float g_bf[(size_t)LLL * HIDD];          // bskip @ Wproj + bproj

// CSR (built once per launch; dst fixed across layers)
__device__ int   g_deg[NN];
__device__ int   g_off[NN + 1];
__device__ int   g_cur[NN];
__device__ int   g_blk[256];
__device__ int   g_srcs[EE];
__device__ float g_eas[EE];

__device__ __forceinline__ float to_tf32(float x) {
    unsigned r;
    asm("cvt.rna.tf32.f32 %0, %1;" : "=r"(r) : "f"(x));
    return __uint_as_float(r);
}

__device__ __forceinline__ void mma168(float* d, const uint32_t* a, const uint32_t* b) {
    asm volatile("mma.sync.aligned.m16n8k8.row.col.f32.tf32.tf32.f32 "
        "{%0,%1,%2,%3}, {%4,%5,%6,%7}, {%8,%9}, {%0,%1,%2,%3};"
        : "+f"(d[0]), "+f"(d[1]), "+f"(d[2]), "+f"(d[3])
        : "r"(a[0]), "r"(a[1]), "r"(a[2]), "r"(a[3]), "r"(b[0]), "r"(b[1]));
}

#define QKV_SMEM_F (16384 + 2*4096)
#define PRJ_SMEM_F (2*4096 + 2*4096)

// ---------------- Fused QKV GEMM (tf32 mma, A whole-K resident, N-split x2) ----------------
__global__ __launch_bounds__(256, 2) void gemm_qkv_mma(
    const float* __restrict__ A,
    const float* __restrict__ W0, const float* __restrict__ W1, const float* __restrict__ W2,
    const float* __restrict__ b0, const float* __restrict__ b1, const float* __restrict__ b2,
    __nv_bfloat16* __restrict__ oq, __nv_bfloat16* __restrict__ ok,
    float* __restrict__ ov)
{
    extern __shared__ float sm[];
    float* As = sm;
    float* Bs = sm + 16384;

    const int tid = threadIdx.x;
    const int wid = tid >> 5;
    const int lane = tid & 31;
    const int ny = blockIdx.x;
    const int m0 = blockIdx.y * 128;
    const int wm = wid >> 2;
    const int wn = wid & 3;
    const int t0 = ny * 6;

    const float* Wp[3] = {W0, W1, W2};
    const float* bp[3] = {b0, b1, b2};

#pragma unroll
    for (int g = 0; g < 16; g++) {
        int i = tid + g * 256;
        int m = i >> 5, k4 = (i & 31) * 4;
        float4 a = *(const float4*)(A + (size_t)(m0 + m) * HIDD + k4);
        int m_tile = m >> 4, r = m & 15;
        float vals[4] = {a.x, a.y, a.z, a.w};
#pragma unroll
        for (int j = 0; j < 4; j++) {
            int kk = k4 + j;
            int c = kk & 7, k8 = kk >> 3;
            int lp = (r & 7) * 4 + (c & 3);
            int reg = (r >> 3) + 2 * (c >> 2);
            uint32_t u = (uint32_t)(k8 * 256 + m_tile * 32 + lp) ^ (uint32_t)(k8 & 7);
            As[u * 4 + reg] = to_tf32(vals[j]);
        }
    }

    float4 streg[4];
    auto ldgB = [&](const float* W, int ncol0, int k0) {
#pragma unroll
        for (int g = 0; g < 4; g++) {
            int i = tid + g * 256;
            int kl = i >> 5, n4 = (i & 31) * 4;
            streg[g] = *(const float4*)(W + (size_t)(k0 + kl) * HCC + ncol0 + n4);
        }
    };
    auto stsB = [&](int buf) {
        float* B = Bs + buf * 4096;
#pragma unroll
        for (int g = 0; g < 4; g++) {
            int i = tid + g * 256;
            int kl = i >> 5, n4 = (i & 31) * 4;
            int c = kl & 7, k8l = kl >> 3, reg = c >> 2;
            float vals[4] = {streg[g].x, streg[g].y, streg[g].z, streg[g].w};
#pragma unroll
            for (int j = 0; j < 4; j++) {
                int n = n4 + j;
                int n_tile = n >> 3;
                int lp = (n & 7) * 4 + (c & 3);
                uint32_t v = (uint32_t)((k8l * 16 + n_tile) * 32 + lp) ^ (uint32_t)(n_tile & 7);
                B[v * 2 + reg] = to_tf32(vals[j]);
            }
        }
    };

    float acc[4][4][4];
    auto initAcc = [&](int tg) {
        const float* bias = bp[tg >> 2] + (tg & 3) * 128 + wn * 32;
#pragma unroll
        for (int j = 0; j < 4; j++) {
            float bv0 = __ldg(bias + j * 8 + 2 * (lane & 3));
            float bv1 = __ldg(bias + j * 8 + 2 * (lane & 3) + 1);
#pragma unroll
            for (int i = 0; i < 4; i++) {
                acc[i][j][0] = bv0; acc[i][j][1] = bv1;
                acc[i][j][2] = bv0; acc[i][j][3] = bv1;
            }
        }
    };
    auto epilogue = [&](int tg) {
        const int w = tg >> 2;
        const int col = (tg & 3) * 128 + wn * 32 + 2 * (lane & 3);
        if (w < 2) {
            __nv_bfloat16* out = (w == 0) ? oq : ok;
#pragma unroll
            for (int i = 0; i < 4; i++) {
                int row = m0 + wm * 64 + i * 16 + (lane >> 2);
#pragma unroll
                for (int j = 0; j < 4; j++) {
                    *(__nv_bfloat162*)(out + (size_t)row * HCC + col + j * 8) =
                        __floats2bfloat162_rn(acc[i][j][0], acc[i][j][1]);
                    *(__nv_bfloat162*)(out + (size_t)(row + 8) * HCC + col + j * 8) =
                        __floats2bfloat162_rn(acc[i][j][2], acc[i][j][3]);
                }
            }
        } else {
#pragma unroll
            for (int i = 0; i < 4; i++) {
                int row = m0 + wm * 64 + i * 16 + (lane >> 2);
#pragma unroll
                for (int j = 0; j < 4; j++) {
                    *(float2*)(ov + (size_t)row * HCC + col + j * 8) =
                        make_float2(acc[i][j][0], acc[i][j][1]);
                    *(float2*)(ov + (size_t)(row + 8) * HCC + col + j * 8) =
                        make_float2(acc[i][j][2], acc[i][j][3]);
                }
            }
        }
    };
    auto mmaChunk = [&](int buf, int kc) {
        const float* B = Bs + buf * 4096;
#pragma unroll
        for (int k8l = 0; k8l < 4; k8l++) {
            int k8 = kc * 4 + k8l;
            uint32_t af[4][4];
#pragma unroll
            for (int i = 0; i < 4; i++) {
                uint32_t u = (uint32_t)(k8 * 256 + (wm * 4 + i) * 32 + lane) ^ (uint32_t)(k8 & 7);
                uint4 t4 = *(const uint4*)(As + u * 4);
                af[i][0] = t4.x; af[i][1] = t4.y; af[i][2] = t4.z; af[i][3] = t4.w;
            }
            uint32_t bf[4][2];
#pragma unroll
            for (int j = 0; j < 4; j++) {
                int n_tile = wn * 4 + j;
                uint32_t v = (uint32_t)((k8l * 16 + n_tile) * 32 + lane) ^ (uint32_t)(n_tile & 7);
                uint2 t2 = *(const uint2*)(B + v * 2);
                bf[j][0] = t2.x; bf[j][1] = t2.y;
            }
#pragma unroll
            for (int i = 0; i < 4; i++)
#pragma unroll
                for (int j = 0; j < 4; j++)
                    mma168(acc[i][j], af[i], bf[j]);
        }
    };

    ldgB(Wp[t0 >> 2], (t0 & 3) * 128, 0);
    stsB(0);
    initAcc(t0);

    for (int s = 0; s < 24; s++) {
        __syncthreads();
        int tg = t0 + (s >> 2), kc = s & 3;
        if (s < 23) {
            int s1 = s + 1, tg1 = t0 + (s1 >> 2), kc1 = s1 & 3;
            ldgB(Wp[tg1 >> 2], (tg1 & 3) * 128, kc1 * 32);
        }
        mmaChunk(s & 1, kc);
        if (s < 23) stsB((s + 1) & 1);
        if (kc == 3) {
            epilogue(tg);
            if ((s >> 2) < 5) initAcc(tg + 1);
        }
    }
}

// ---------------- Proj GEMM (tf32 mma): out = agg@Wproj + x@Wf + bias ----------------
__global__ __launch_bounds__(256, 2) void gemm_proj_mma(
    const float* __restrict__ A1, const float* __restrict__ W1,
    const float* __restrict__ A2, const float* __restrict__ W2,
    const float* __restrict__ bias, float* __restrict__ out)
{
    extern __shared__ float sm[];
    float* As = sm;
    float* Bs = sm + 8192;

    const int tid = threadIdx.x;
    const int wid = tid >> 5;
    const int lane = tid & 31;
    const int m0 = blockIdx.x * 128;
    const int wm = wid >> 2;
    const int wn = wid & 3;

    float4 sa[4], sb[4];
    auto ldgStage = [&](int s1) {
        const float* Ax; const float* Wx; int K; int k0;
        if (s1 < 16) { Ax = A1; Wx = W1; K = HCC;  k0 = s1 * 32; }
        else         { Ax = A2; Wx = W2; K = HIDD; k0 = (s1 - 16) * 32; }
#pragma unroll
        for (int g = 0; g < 4; g++) {
            int i = tid + g * 256;
            int r = i >> 3, c4 = (i & 7) * 4;
            sa[g] = *(const float4*)(Ax + (size_t)(m0 + r) * K + k0 + c4);
        }
#pragma unroll
        for (int g = 0; g < 4; g++) {
            int i = tid + g * 256;
            int kl = i >> 5, n4 = (i & 31) * 4;
            sb[g] = *(const float4*)(Wx + (size_t)(k0 + kl) * HIDD + n4);
        }
    };
    auto stsStage = [&](int buf) {
        float* Adst = As + buf * 4096;
        float* Bdst = Bs + buf * 4096;
#pragma unroll
        for (int g = 0; g < 4; g++) {
            int i = tid + g * 256;
            int r = i >> 3, c4 = (i & 7) * 4;
            int m_tile = r >> 4, rr = r & 15;
            float vals[4] = {sa[g].x, sa[g].y, sa[g].z, sa[g].w};
#pragma unroll
            for (int j = 0; j < 4; j++) {
                int kk = c4 + j;
                int c = kk & 7, k8l = kk >> 3;
                int lp = (rr & 7) * 4 + (c & 3);
                int reg = (rr >> 3) + 2 * (c >> 2);
                uint32_t u = (uint32_t)(k8l * 256 + m_tile * 32 + lp) ^ (uint32_t)(k8l & 7);
                Adst[u * 4 + reg] = to_tf32(vals[j]);
            }
        }
#pragma unroll
        for (int g = 0; g < 4; g++) {
            int i = tid + g * 256;
            int kl = i >> 5, n4 = (i & 31) * 4;
            int c = kl & 7, k8l = kl >> 3, reg = c >> 2;
            float vals[4] = {sb[g].x, sb[g].y, sb[g].z, sb[g].w};
#pragma unroll
            for (int j = 0; j < 4; j++) {
                int n = n4 + j;
                int n_tile = n >> 3;
                int lp = (n & 7) * 4 + (c & 3);
                uint32_t v = (uint32_t)((k8l * 16 + n_tile) * 32 + lp) ^ (uint32_t)(n_tile & 7);
                Bdst[v * 2 + reg] = to_tf32(vals[j]);
            }
        }
    };

    float acc[4][4][4];
    {
        const float* bp = bias + wn * 32;
#pragma unroll
        for (int j = 0; j < 4; j++) {
            float bv0 = __ldg(bp + j * 8 + 2 * (lane & 3));
            float bv1 = __ldg(bp + j * 8 + 2 * (lane & 3) + 1);
#pragma unroll
            for (int i = 0; i < 4; i++) {
                acc[i][j][0] = bv0; acc[i][j][1] = bv1;
                acc[i][j][2] = bv0; acc[i][j][3] = bv1;
            }
        }
    }

    ldgStage(0);
    stsStage(0);

    for (int s = 0; s < 20; s++) {
        __syncthreads();
        if (s < 19) ldgStage(s + 1);
        {
            const float* Ac = As + (s & 1) * 4096;
            const float* Bc = Bs + (s & 1) * 4096;
#pragma unroll
            for (int k8l = 0; k8l < 4; k8l++) {
                uint32_t af[4][4];
#pragma unroll
                for (int i = 0; i < 4; i++) {
                    uint32_t u = (uint32_t)(k8l * 256 + (wm * 4 + i) * 32 + lane) ^ (uint32_t)(k8l & 7);
                    uint4 t4 = *(const uint4*)(Ac + u * 4);
                    af[i][0] = t4.x; af[i][1] = t4.y; af[i][2] = t4.z; af[i][3] = t4.w;
                }
                uint32_t bf[4][2];
#pragma unroll
                for (int j = 0; j < 4; j++) {
                    int n_tile = wn * 4 + j;
                    uint32_t v = (uint32_t)((k8l * 16 + n_tile) * 32 + lane) ^ (uint32_t)(n_tile & 7);
                    uint2 t2 = *(const uint2*)(Bc + v * 2);
                    bf[j][0] = t2.x; bf[j][1] = t2.y;
                }
#pragma unroll
                for (int i = 0; i < 4; i++)
#pragma unroll
                    for (int j = 0; j < 4; j++)
                        mma168(acc[i][j], af[i], bf[j]);
            }
        }
        if (s < 19) stsStage((s + 1) & 1);
    }

    int col = wn * 32 + 2 * (lane & 3);
#pragma unroll
    for (int i = 0; i < 4; i++) {
        int row = m0 + wm * 64 + i * 16 + (lane >> 2);
#pragma unroll
        for (int j = 0; j < 4; j++) {
            *(float2*)(out + (size_t)row * HIDD + col + j * 8) =
                make_float2(acc[i][j][0], acc[i][j][1]);
            *(float2*)(out + (size_t)(row + 8) * HIDD + col + j * 8) =
                make_float2(acc[i][j][2], acc[i][j][3]);
        }
    }
}

// ---------------- Precompute Wf = Wskip @ Wproj ----------------
__global__ void wf_k(const float* __restrict__ Wskip, const float* __restrict__ Wproj,
                     float* __restrict__ Wf)
{
    int l = blockIdx.y;
    int e = blockIdx.x * 256 + threadIdx.x;
    int i = e >> 7, j = e & 127;
    const float* ws = Wskip + (size_t)l * HIDD * HCC + (size_t)i * HCC;
    const float* wp = Wproj + (size_t)l * HCC * HIDD + j;
    float s = 0.f;
#pragma unroll 8
    for (int k = 0; k < HCC; k++) s = fmaf(ws[k], wp[(size_t)k * HIDD], s);
    Wf[(size_t)l * HIDD * HIDD + e] = s;
}

__global__ void bf_k(const float* __restrict__ bskip, const float* __restrict__ Wproj,
                     const float* __restrict__ bproj, float* __restrict__ bf)
{
    int l = blockIdx.x, j = threadIdx.x;
    const float* bs = bskip + (size_t)l * HCC;
    const float* wp = Wproj + (size_t)l * HCC * HIDD + j;
    float s = bproj[(size_t)l * HIDD + j];
#pragma unroll 8
    for (int k = 0; k < HCC; k++) s = fmaf(bs[k], wp[(size_t)k * HIDD], s);
    bf[l * HIDD + j] = s;
}

// ---------------- CSR build (once per launch) ----------------
__global__ void hist_k(const int* __restrict__ dst, int* __restrict__ deg) {
    int e = blockIdx.x * 256 + threadIdx.x;
    if (e < EE) atomicAdd(deg + dst[e], 1);
}

__global__ void scanA_k(const int* __restrict__ deg, int* __restrict__ off,
                        int* __restrict__ blk) {
    __shared__ int sh[256];
    int t = threadIdx.x;
    int idx = blockIdx.x * 256 + t;
    int val = (idx < NN) ? deg[idx] : 0;
    sh[t] = val;
    __syncthreads();
#pragma unroll
    for (int d = 1; d < 256; d <<= 1) {
        int add = (t >= d) ? sh[t - d] : 0;
        __syncthreads();
        sh[t] += add;
        __syncthreads();
    }
    if (idx < NN) off[idx] = sh[t] - val;       // local exclusive
    if (t == 255) blk[blockIdx.x] = sh[255];    // block total
}

__global__ void scanB_k(int* __restrict__ blk) {
    __shared__ int sh[256];
    int t = threadIdx.x;
    int val = (t < 196) ? blk[t] : 0;
    sh[t] = val;
    __syncthreads();
#pragma unroll
    for (int d = 1; d < 256; d <<= 1) {
        int add = (t >= d) ? sh[t - d] : 0;
        __syncthreads();
        sh[t] += add;
        __syncthreads();
    }
    if (t < 196) blk[t] = sh[t] - val;          // exclusive over block totals
}

__global__ void scanC_k(int* __restrict__ off, const int* __restrict__ blk,
                        int* __restrict__ cur) {
    int idx = blockIdx.x * 256 + threadIdx.x;
    if (idx < NN) {
        int o = off[idx] + blk[blockIdx.x];
        off[idx] = o;
        cur[idx] = o;
    }
    if (idx == 0) off[NN] = EE;
}

__global__ void scatter_k(const int* __restrict__ src, const int* __restrict__ dst,
                          const float* __restrict__ ea, int* __restrict__ cur,
                          int* __restrict__ srcs, float* __restrict__ eas) {
    int e = blockIdx.x * 256 + threadIdx.x;
    if (e < EE) {
        int p = atomicAdd(cur + dst[e], 1);
        srcs[p] = src[e];
        eas[p] = ea[e];
    }
}

// ---------------- Node-centric fused attention (warp per (dst,head)) ----------------
// agg[d,h,:] = sum_e p_e*(v[src_e]+ea_e*We) / (sum_e p_e + 1e-16), single pass.
__global__ __launch_bounds__(256) void attn_node_k(
    const __nv_bfloat16* __restrict__ q, const __nv_bfloat16* __restrict__ k,
    const float* __restrict__ v, const int* __restrict__ off,
    const int* __restrict__ srcs, const float* __restrict__ eas,
    const float* __restrict__ We, float* __restrict__ agg)
{
    int wg = blockIdx.x * 8 + (threadIdx.x >> 5);
    int lane = threadIdx.x & 31;
    int d = wg >> 2, h = wg & 3;

    int beg = __ldg(off + d), end = __ldg(off + d + 1);

    uint2 qraw = *(const uint2*)(q + (size_t)d * HCC + h * CCC + lane * 4);
    float2 q01 = __bfloat1622float2(*(__nv_bfloat162*)&qraw.x);
    float2 q23 = __bfloat1622float2(*(__nv_bfloat162*)&qraw.y);
    const float4 wv = *(const float4*)(We + h * CCC + lane * 4);

    float a0 = 0.f, a1 = 0.f, a2 = 0.f, a3 = 0.f, den = 0.f;

    for (int i = beg; i < end; i++) {
        int sN = __ldg(srcs + i);
        float eav = __ldg(eas + i);

        uint2 kraw = *(const uint2*)(k + (size_t)sN * HCC + h * CCC + lane * 4);
        float2 k01 = __bfloat1622float2(*(__nv_bfloat162*)&kraw.x);
        float2 k23 = __bfloat1622float2(*(__nv_bfloat162*)&kraw.y);

        float s = q01.x * fmaf(eav, wv.x, k01.x) + q01.y * fmaf(eav, wv.y, k01.y)
                + q23.x * fmaf(eav, wv.z, k23.x) + q23.y * fmaf(eav, wv.w, k23.y);
#pragma unroll
        for (int o = 16; o; o >>= 1) s += __shfl_xor_sync(0xffffffffu, s, o);

        float pv = expf(s * 0.08838834764831845f);   // 1/sqrt(128)
        den += pv;

        const float4 vv = *(const float4*)(v + (size_t)sN * HCC + h * CCC + lane * 4);
        a0 = fmaf(fmaf(eav, wv.x, vv.x), pv, a0);
        a1 = fmaf(fmaf(eav, wv.y, vv.y), pv, a1);
        a2 = fmaf(fmaf(eav, wv.z, vv.z), pv, a2);
        a3 = fmaf(fmaf(eav, wv.w, vv.w), pv, a3);
    }

    float inv = 1.f / (den + 1e-16f);
    float4 o4 = make_float4(a0 * inv, a1 * inv, a2 * inv, a3 * inv);
    *(float4*)(agg + (size_t)d * HCC + h * CCC + lane * 4) = o4;
}

// ---------------- Fused ELU + residual + LayerNorm ----------------
__global__ __launch_bounds__(256) void ln_k(
    const float* __restrict__ x, const float* __restrict__ h,
    const float* __restrict__ gamma, const float* __restrict__ beta,
    float* __restrict__ out)
{
    int row = blockIdx.x * 8 + (threadIdx.x >> 5);
    int lane = threadIdx.x & 31;

    const float4 xv = *(const float4*)(x + (size_t)row * HIDD + lane * 4);
    const float4 hv = *(const float4*)(h + (size_t)row * HIDD + lane * 4);

    float4 y;
    y.x = xv.x + (hv.x > 0.f ? hv.x : expm1f(hv.x));
    y.y = xv.y + (hv.y > 0.f ? hv.y : expm1f(hv.y));
    y.z = xv.z + (hv.z > 0.f ? hv.z : expm1f(hv.z));
    y.w = xv.w + (hv.w > 0.f ? hv.w : expm1f(hv.w));

    float sum = y.x + y.y + y.z + y.w;
    float sq  = y.x * y.x + y.y * y.y + y.z * y.z + y.w * y.w;
#pragma unroll
    for (int off = 16; off; off >>= 1) {
        sum += __shfl_xor_sync(0xffffffffu, sum, off);
        sq  += __shfl_xor_sync(0xffffffffu, sq, off);
    }
    float mu = sum * (1.f / 128.f);
    float var = sq * (1.f / 128.f) - mu * mu;
    float inv = rsqrtf(var + 1e-5f);

    const float4 gv = *(const float4*)(gamma + lane * 4);
    const float4 bv = *(const float4*)(beta + lane * 4);
    float4 o;
    o.x = (y.x - mu) * inv * gv.x + bv.x;
    o.y = (y.y - mu) * inv * gv.y + bv.y;
    o.z = (y.z - mu) * inv * gv.z + bv.z;
    o.w = (y.w - mu) * inv * gv.w + bv.w;
    *(float4*)(out + (size_t)row * HIDD + lane * 4) = o;
}

// ---------------- host ----------------
extern "C" void kernel_launch(void* const* d_in, const int* in_sizes, int n_in,
                              void* d_out, int out_size)
{
    const float* x_in  = (const float*)d_in[0];
    const int*   ei    = (const int*)d_in[1];
    const float* ea    = (const float*)d_in[2];
    const float* Wq    = (const float*)d_in[3];
    const float* bq    = (const float*)d_in[4];
    const float* Wk    = (const float*)d_in[5];
    const float* bk    = (const float*)d_in[6];
    const float* Wv    = (const float*)d_in[7];
    const float* bv    = (const float*)d_in[8];
    const float* We    = (const float*)d_in[9];
    const float* Wskip = (const float*)d_in[10];
    const float* bskip = (const float*)d_in[11];
    const float* Wproj = (const float*)d_in[12];
    const float* bproj = (const float*)d_in[13];
    const float* gamma = (const float*)d_in[14];
    const float* beta  = (const float*)d_in[15];

    __nv_bfloat16 *qb, *kb;
    float *v, *agg, *h, *xbuf, *wf, *bfv, *eas;
    int *deg, *off, *cur, *blk, *srcs;
    cudaGetSymbolAddress((void**)&qb,   g_qb);
    cudaGetSymbolAddress((void**)&kb,   g_kb);
    cudaGetSymbolAddress((void**)&v,    g_v);
    cudaGetSymbolAddress((void**)&agg,  g_agg);
    cudaGetSymbolAddress((void**)&h,    g_h);
    cudaGetSymbolAddress((void**)&xbuf, g_x);
    cudaGetSymbolAddress((void**)&wf,   g_wf);
    cudaGetSymbolAddress((void**)&bfv,  g_bf);
    cudaGetSymbolAddress((void**)&deg,  g_deg);
    cudaGetSymbolAddress((void**)&off,  g_off);
    cudaGetSymbolAddress((void**)&cur,  g_cur);
    cudaGetSymbolAddress((void**)&blk,  g_blk);
    cudaGetSymbolAddress((void**)&srcs, g_srcs);
    cudaGetSymbolAddress((void**)&eas,  g_eas);

    cudaFuncSetAttribute(gemm_qkv_mma,  cudaFuncAttributeMaxDynamicSharedMemorySize,
                         QKV_SMEM_F * 4);
    cudaFuncSetAttribute(gemm_proj_mma, cudaFuncAttributeMaxDynamicSharedMemorySize,
                         PRJ_SMEM_F * 4);

    const int* src = ei;
    const int* dst = ei + EE;

    cudaMemcpyAsync(xbuf, x_in, (size_t)NN * HIDD * sizeof(float),
                    cudaMemcpyDeviceToDevice);

    // precompute fused skip weights + CSR
    wf_k<<<dim3(64, 3), 256>>>(Wskip, Wproj, wf);
    bf_k<<<3, 128>>>(bskip, Wproj, bproj, bfv);

    cudaMemsetAsync(deg, 0, NN * sizeof(int));
    hist_k<<<(EE + 255) / 256, 256>>>(dst, deg);
    scanA_k<<<(NN + 255) / 256, 256>>>(deg, off, blk);
    scanB_k<<<1, 256>>>(blk);
    scanC_k<<<(NN + 255) / 256, 256>>>(off, blk, cur);
    scatter_k<<<(EE + 255) / 256, 256>>>(src, dst, ea, cur, srcs, eas);

    const int nBlocks = NPAD / 128;           // 391
    const int attnBlocks = (NN * HH) / 8;     // 25000
    const int lnBlocks = NN / 8;              // 6250

    for (int l = 0; l < LLL; l++) {
        float* xo = (l == LLL - 1) ? (float*)d_out : xbuf;
        size_t wo = (size_t)l * HIDD * HCC;

        gemm_qkv_mma<<<dim3(2, nBlocks), 256, QKV_SMEM_F * 4>>>(
            xbuf, Wq + wo, Wk + wo, Wv + wo,
            bq + l * HCC, bk + l * HCC, bv + l * HCC, qb, kb, v);

        attn_node_k<<<attnBlocks, 256>>>(qb, kb, v, off, srcs, eas,
                                         We + l * HCC, agg);

        gemm_proj_mma<<<nBlocks, 256, PRJ_SMEM_F * 4>>>(
            agg, Wproj + (size_t)l * HCC * HIDD,
            xbuf, wf + (size_t)l * HIDD * HIDD,
            bfv + l * HIDD, h);

        ln_k<<<lnBlocks, 256>>>(xbuf, h, gamma + l * HIDD, beta + l * HIDD, xo);
    }
}

// round 9
// speedup vs baseline: 2.6897x; 1.0691x over previous
#include <cuda_runtime.h>
#include <cuda_bf16.h>
#include <math.h>
#include <stdint.h>

#define NN 50000
#define NPAD 50048          // 391 * 128
#define NSLAB 391
#define EE 100000
#define HIDD 128
#define HH 4
#define CCC 128
#define HCC 512
#define LLL 3

// ---------------- scratch ----------------
__device__ __nv_bfloat16 g_qb[(size_t)NPAD * HCC];
__device__ __nv_bfloat16 g_kb[(size_t)NPAD * HCC];
__device__ float g_v[(size_t)NPAD * HCC];
__device__ float g_h[(size_t)NPAD * HIDD];
__device__ float g_x[(size_t)NPAD * HIDD];
// fragment-order buffers
__device__ float g_xf[(size_t)NSLAB * 16384];        // x, frag order (4 chunks/slab)
__device__ float g_aggf[(size_t)NSLAB * 65536];      // agg, frag order (16 chunks/slab)
__device__ float g_wqkvf[(size_t)LLL * 3 * 65536];   // Wq/Wk/Wv frag
__device__ float g_wpf[(size_t)LLL * 65536];         // Wproj frag
__device__ float g_wff[(size_t)LLL * 16384];         // Wskip@Wproj frag
__device__ float g_bf[(size_t)LLL * HIDD];           // bskip@Wproj + bproj

// CSR (built once per launch; dst fixed across layers)
__device__ int   g_deg[NN];
__device__ int   g_off[NN + 1];
__device__ int   g_cur[NN];
__device__ int   g_blk[256];
__device__ int   g_srcs[EE];
__device__ float g_eas[EE];

__device__ __forceinline__ float to_tf32(float x) {
    unsigned r;
    asm("cvt.rna.tf32.f32 %0, %1;" : "=r"(r) : "f"(x));
    return __uint_as_float(r);
}

__device__ __forceinline__ void mma168(float* d, const uint32_t* a, const uint32_t* b) {
    asm volatile("mma.sync.aligned.m16n8k8.row.col.f32.tf32.tf32.f32 "
        "{%0,%1,%2,%3}, {%4,%5,%6,%7}, {%8,%9}, {%0,%1,%2,%3};"
        : "+f"(d[0]), "+f"(d[1]), "+f"(d[2]), "+f"(d[3])
        : "r"(a[0]), "r"(a[1]), "r"(a[2]), "r"(a[3]), "r"(b[0]), "r"(b[1]));
}

// frag-order index helpers (per 128x32 A-chunk / 32x128 B-chunk, 4096 floats each)
__device__ __forceinline__ int aidx(int m, int kl) {
    int m_tile = m >> 4, r = m & 15;
    int c = kl & 7, k8l = kl >> 3;
    int lp = (r & 7) * 4 + (c & 3);
    int reg = (r >> 3) + 2 * (c >> 2);
    int u = k8l * 256 + m_tile * 32 + lp;
    return u * 4 + reg;
}
__device__ __forceinline__ int bidx(int kl, int nn) {
    int c = kl & 7, k8l = kl >> 3, reg = c >> 2;
    int n_tile = nn >> 3, lp = (nn & 7) * 4 + (c & 3);
    int v = (k8l * 16 + n_tile) * 32 + lp;
    return v * 2 + reg;
}

#define QKV_SMEM_F (16384 + 2*4096)
#define PRJ_SMEM_F (2*4096 + 2*4096)

// ---------------- Fused QKV GEMM (tf32 mma, frag-order identity loads) ----------------
// grid (2, 391): blockIdx.x = N-half, blockIdx.y = M-slab. 6 N-tiles / CTA (24 stages).
__global__ __launch_bounds__(256, 2) void gemm_qkv_mma(
    const float* __restrict__ xf, const float* __restrict__ wf,
    const float* __restrict__ b0, const float* __restrict__ b1, const float* __restrict__ b2,
    __nv_bfloat16* __restrict__ oq, __nv_bfloat16* __restrict__ ok,
    float* __restrict__ ov)
{
    extern __shared__ float sm[];
    float* As = sm;                 // 16384 floats (4 A-chunks)
    float* Bs = sm + 16384;         // 2 x 4096

    const int tid = threadIdx.x;
    const int wid = tid >> 5;
    const int lane = tid & 31;
    const int ny = blockIdx.x;
    const int m0 = blockIdx.y * 128;
    const int wm = wid >> 2;
    const int wn = wid & 3;
    const int t0 = ny * 6;

    const float* bp[3] = {b0, b1, b2};

    // A slab: identity copy from frag-order global
    {
        const float* asrc = xf + (size_t)blockIdx.y * 16384;
#pragma unroll
        for (int g = 0; g < 16; g++) {
            int o = (g * 256 + tid) * 4;
            *(float4*)(As + o) = *(const float4*)(asrc + o);
        }
    }

    float4 streg[4];
    auto ldgB = [&](const float* chunk) {
#pragma unroll
        for (int g = 0; g < 4; g++)
            streg[g] = *(const float4*)(chunk + (g * 256 + tid) * 4);
    };
    auto stsB = [&](int buf) {
        float* B = Bs + buf * 4096;
#pragma unroll
        for (int g = 0; g < 4; g++)
            *(float4*)(B + (g * 256 + tid) * 4) = streg[g];
    };
    auto chunkPtr = [&](int s) {   // stage -> weight frag chunk
        int tg = t0 + (s >> 2);
        return wf + (size_t)(tg >> 2) * 65536 + (size_t)(((tg & 3) * 4) + (s & 3)) * 4096;
    };

    float acc[4][4][4];
    auto initAcc = [&](int tg) {
        const float* bias = bp[tg >> 2] + (tg & 3) * 128 + wn * 32;
#pragma unroll
        for (int j = 0; j < 4; j++) {
            float bv0 = __ldg(bias + j * 8 + 2 * (lane & 3));
            float bv1 = __ldg(bias + j * 8 + 2 * (lane & 3) + 1);
#pragma unroll
            for (int i = 0; i < 4; i++) {
                acc[i][j][0] = bv0; acc[i][j][1] = bv1;
                acc[i][j][2] = bv0; acc[i][j][3] = bv1;
            }
        }
    };
    auto epilogue = [&](int tg) {
        const int w = tg >> 2;
        const int col = (tg & 3) * 128 + wn * 32 + 2 * (lane & 3);
        if (w < 2) {
            __nv_bfloat16* out = (w == 0) ? oq : ok;
#pragma unroll
            for (int i = 0; i < 4; i++) {
                int row = m0 + wm * 64 + i * 16 + (lane >> 2);
#pragma unroll
                for (int j = 0; j < 4; j++) {
                    *(__nv_bfloat162*)(out + (size_t)row * HCC + col + j * 8) =
                        __floats2bfloat162_rn(acc[i][j][0], acc[i][j][1]);
                    *(__nv_bfloat162*)(out + (size_t)(row + 8) * HCC + col + j * 8) =
                        __floats2bfloat162_rn(acc[i][j][2], acc[i][j][3]);
                }
            }
        } else {
#pragma unroll
            for (int i = 0; i < 4; i++) {
                int row = m0 + wm * 64 + i * 16 + (lane >> 2);
#pragma unroll
                for (int j = 0; j < 4; j++) {
                    *(float2*)(ov + (size_t)row * HCC + col + j * 8) =
                        make_float2(acc[i][j][0], acc[i][j][1]);
                    *(float2*)(ov + (size_t)(row + 8) * HCC + col + j * 8) =
                        make_float2(acc[i][j][2], acc[i][j][3]);
                }
            }
        }
    };
    auto mmaChunk = [&](int buf, int kc) {
        const float* B = Bs + buf * 4096;
        const float* Ac = As + kc * 4096;
#pragma unroll
        for (int k8l = 0; k8l < 4; k8l++) {
            uint32_t af[4][4];
#pragma unroll
            for (int i = 0; i < 4; i++) {
                uint32_t u = (uint32_t)(k8l * 256 + (wm * 4 + i) * 32 + lane);
                uint4 t4 = *(const uint4*)(Ac + u * 4);
                af[i][0] = t4.x; af[i][1] = t4.y; af[i][2] = t4.z; af[i][3] = t4.w;
            }
            uint32_t bf[4][2];
#pragma unroll
            for (int j = 0; j < 4; j++) {
                uint32_t v = (uint32_t)((k8l * 16 + wn * 4 + j) * 32 + lane);
                uint2 t2 = *(const uint2*)(B + v * 2);
                bf[j][0] = t2.x; bf[j][1] = t2.y;
            }
#pragma unroll
            for (int i = 0; i < 4; i++)
#pragma unroll
                for (int j = 0; j < 4; j++)
                    mma168(acc[i][j], af[i], bf[j]);
        }
    };

    ldgB(chunkPtr(0));
    stsB(0);
    initAcc(t0);

    for (int s = 0; s < 24; s++) {
        __syncthreads();
        int tg = t0 + (s >> 2), kc = s & 3;
        if (s < 23) ldgB(chunkPtr(s + 1));
        mmaChunk(s & 1, kc);
        if (s < 23) stsB((s + 1) & 1);
        if (kc == 3) {
            epilogue(tg);
            if ((s >> 2) < 5) initAcc(tg + 1);
        }
    }
}

// ---------------- Proj GEMM: out = agg@Wproj + x@Wf + bias (frag-order identity) ----------------
__global__ __launch_bounds__(256, 2) void gemm_proj_mma(
    const float* __restrict__ aggf, const float* __restrict__ wpf,
    const float* __restrict__ xf, const float* __restrict__ wff,
    const float* __restrict__ bias, float* __restrict__ out)
{
    extern __shared__ float sm[];
    float* As = sm;
    float* Bs = sm + 8192;

    const int tid = threadIdx.x;
    const int wid = tid >> 5;
    const int lane = tid & 31;
    const int slab = blockIdx.x;
    const int m0 = slab * 128;
    const int wm = wid >> 2;
    const int wn = wid & 3;

    float4 sa[4], sb[4];
    auto ldgStage = [&](int s1) {
        const float *Asrc, *Bsrc;
        if (s1 < 16) {
            Asrc = aggf + (size_t)slab * 65536 + (size_t)s1 * 4096;
            Bsrc = wpf + (size_t)s1 * 4096;
        } else {
            Asrc = xf + (size_t)slab * 16384 + (size_t)(s1 - 16) * 4096;
            Bsrc = wff + (size_t)(s1 - 16) * 4096;
        }
#pragma unroll
        for (int g = 0; g < 4; g++)
            sa[g] = *(const float4*)(Asrc + (g * 256 + tid) * 4);
#pragma unroll
        for (int g = 0; g < 4; g++)
            sb[g] = *(const float4*)(Bsrc + (g * 256 + tid) * 4);
    };
    auto stsStage = [&](int buf) {
        float* Adst = As + buf * 4096;
        float* Bdst = Bs + buf * 4096;
#pragma unroll
        for (int g = 0; g < 4; g++)
            *(float4*)(Adst + (g * 256 + tid) * 4) = sa[g];
#pragma unroll
        for (int g = 0; g < 4; g++)
            *(float4*)(Bdst + (g * 256 + tid) * 4) = sb[g];
    };

    float acc[4][4][4];
    {
        const float* bp = bias + wn * 32;
#pragma unroll
        for (int j = 0; j < 4; j++) {
            float bv0 = __ldg(bp + j * 8 + 2 * (lane & 3));
            float bv1 = __ldg(bp + j * 8 + 2 * (lane & 3) + 1);
#pragma unroll
            for (int i = 0; i < 4; i++) {
                acc[i][j][0] = bv0; acc[i][j][1] = bv1;
                acc[i][j][2] = bv0; acc[i][j][3] = bv1;
            }
        }
    }

    ldgStage(0);
    stsStage(0);

    for (int s = 0; s < 20; s++) {
        __syncthreads();
        if (s < 19) ldgStage(s + 1);
        {
            const float* Ac = As + (s & 1) * 4096;
            const float* Bc = Bs + (s & 1) * 4096;
#pragma unroll
            for (int k8l = 0; k8l < 4; k8l++) {
                uint32_t af[4][4];
#pragma unroll
                for (int i = 0; i < 4; i++) {
                    uint32_t u = (uint32_t)(k8l * 256 + (wm * 4 + i) * 32 + lane);
                    uint4 t4 = *(const uint4*)(Ac + u * 4);
                    af[i][0] = t4.x; af[i][1] = t4.y; af[i][2] = t4.z; af[i][3] = t4.w;
                }
                uint32_t bf[4][2];
#pragma unroll
                for (int j = 0; j < 4; j++) {
                    uint32_t v = (uint32_t)((k8l * 16 + wn * 4 + j) * 32 + lane);
                    uint2 t2 = *(const uint2*)(Bc + v * 2);
                    bf[j][0] = t2.x; bf[j][1] = t2.y;
                }
#pragma unroll
                for (int i = 0; i < 4; i++)
#pragma unroll
                    for (int j = 0; j < 4; j++)
                        mma168(acc[i][j], af[i], bf[j]);
            }
        }
        if (s < 19) stsStage((s + 1) & 1);
    }

    int col = wn * 32 + 2 * (lane & 3);
#pragma unroll
    for (int i = 0; i < 4; i++) {
        int row = m0 + wm * 64 + i * 16 + (lane >> 2);
#pragma unroll
        for (int j = 0; j < 4; j++) {
            *(float2*)(out + (size_t)row * HIDD + col + j * 8) =
                make_float2(acc[i][j][0], acc[i][j][1]);
            *(float2*)(out + (size_t)(row + 8) * HIDD + col + j * 8) =
                make_float2(acc[i][j][2], acc[i][j][3]);
        }
    }
}

// ---------------- Weight prep: frag-order + tf32 rounding (once per launch) ----------------
__global__ void prep_qkv_w(const float* __restrict__ Wq, const float* __restrict__ Wk,
                           const float* __restrict__ Wv, float* __restrict__ dst)
{
    int t = blockIdx.x * 256 + threadIdx.x;          // 3L*3*65536 = 589824
    int l = t / 196608;
    int r = t - l * 196608;
    int w = r >> 16;
    int e = r & 65535;
    int k = e >> 9, n = e & 511;                     // W [128][512]
    const float* W = (w == 0 ? Wq : (w == 1 ? Wk : Wv)) + (size_t)l * 65536;
    float val = W[k * 512 + n];
    int nc = n >> 7, nn = n & 127, kc = k >> 5, kl = k & 31;
    dst[(size_t)(l * 3 + w) * 65536 + (size_t)(nc * 4 + kc) * 4096 + bidx(kl, nn)] =
        to_tf32(val);
}

__global__ void prep_proj_w(const float* __restrict__ Wproj, float* __restrict__ dst)
{
    int t = blockIdx.x * 256 + threadIdx.x;          // 3*65536 = 196608
    int l = t >> 16, e = t & 65535;
    int k = e >> 7, n = e & 127;                     // W [512][128]
    float val = Wproj[(size_t)l * 65536 + k * 128 + n];
    dst[(size_t)l * 65536 + (size_t)(k >> 5) * 4096 + bidx(k & 31, n)] = to_tf32(val);
}

// Wf = Wskip @ Wproj, written directly in frag order
__global__ void wf_k(const float* __restrict__ Wskip, const float* __restrict__ Wproj,
                     float* __restrict__ wff)
{
    int l = blockIdx.y;
    int e = blockIdx.x * 256 + threadIdx.x;          // 16384
    int i = e >> 7, j = e & 127;
    const float* ws = Wskip + (size_t)l * HIDD * HCC + (size_t)i * HCC;
    const float* wp = Wproj + (size_t)l * HCC * HIDD + j;
    float s = 0.f;
#pragma unroll 8
    for (int k = 0; k < HCC; k++) s = fmaf(ws[k], wp[(size_t)k * HIDD], s);
    wff[(size_t)l * 16384 + (size_t)(i >> 5) * 4096 + bidx(i & 31, j)] = to_tf32(s);
}

__global__ void bf_k(const float* __restrict__ bskip, const float* __restrict__ Wproj,
                     const float* __restrict__ bproj, float* __restrict__ bf)
{
    int l = blockIdx.x, j = threadIdx.x;
    const float* bs = bskip + (size_t)l * HCC;
    const float* wp = Wproj + (size_t)l * HCC * HIDD + j;
    float s = bproj[(size_t)l * HIDD + j];
#pragma unroll 8
    for (int k = 0; k < HCC; k++) s = fmaf(bs[k], wp[(size_t)k * HIDD], s);
    bf[l * HIDD + j] = s;
}

// x_in -> frag order (layer 0)
__global__ void init_xfrag_k(const float* __restrict__ x, float* __restrict__ xf)
{
    int t = blockIdx.x * 256 + threadIdx.x;          // NN*32 = 1.6M
    int row = t >> 5, lane = t & 31;
    float4 v = *(const float4*)(x + (size_t)row * HIDD + lane * 4);
    int slab = row >> 7, m = row & 127;
    float vals[4] = {v.x, v.y, v.z, v.w};
#pragma unroll
    for (int j = 0; j < 4; j++) {
        int k = lane * 4 + j;
        xf[(size_t)slab * 16384 + (size_t)(k >> 5) * 4096 + aidx(m, k & 31)] =
            to_tf32(vals[j]);
    }
}

// ---------------- CSR build (once per launch) ----------------
__global__ void hist_k(const int* __restrict__ dst, int* __restrict__ deg) {
    int e = blockIdx.x * 256 + threadIdx.x;
    if (e < EE) atomicAdd(deg + dst[e], 1);
}

__global__ void scanA_k(const int* __restrict__ deg, int* __restrict__ off,
                        int* __restrict__ blk) {
    __shared__ int sh[256];
    int t = threadIdx.x;
    int idx = blockIdx.x * 256 + t;
    int val = (idx < NN) ? deg[idx] : 0;
    sh[t] = val;
    __syncthreads();
#pragma unroll
    for (int d = 1; d < 256; d <<= 1) {
        int add = (t >= d) ? sh[t - d] : 0;
        __syncthreads();
        sh[t] += add;
        __syncthreads();
    }
    if (idx < NN) off[idx] = sh[t] - val;
    if (t == 255) blk[blockIdx.x] = sh[255];
}

__global__ void scanB_k(int* __restrict__ blk) {
    __shared__ int sh[256];
    int t = threadIdx.x;
    int val = (t < 196) ? blk[t] : 0;
    sh[t] = val;
    __syncthreads();
#pragma unroll
    for (int d = 1; d < 256; d <<= 1) {
        int add = (t >= d) ? sh[t - d] : 0;
        __syncthreads();
        sh[t] += add;
        __syncthreads();
    }
    if (t < 196) blk[t] = sh[t] - val;
}

__global__ void scanC_k(int* __restrict__ off, const int* __restrict__ blk,
                        int* __restrict__ cur) {
    int idx = blockIdx.x * 256 + threadIdx.x;
    if (idx < NN) {
        int o = off[idx] + blk[blockIdx.x];
        off[idx] = o;
        cur[idx] = o;
    }
    if (idx == 0) off[NN] = EE;
}

__global__ void scatter_k(const int* __restrict__ src, const int* __restrict__ dst,
                          const float* __restrict__ ea, int* __restrict__ cur,
                          int* __restrict__ srcs, float* __restrict__ eas) {
    int e = blockIdx.x * 256 + threadIdx.x;
    if (e < EE) {
        int p = atomicAdd(cur + dst[e], 1);
        srcs[p] = src[e];
        eas[p] = ea[e];
    }
}

// ---------------- Node-centric fused attention (warp per (dst,head)) ----------------
// Writes agg directly in fragment order (tf32-rounded) for the proj GEMM.
__global__ __launch_bounds__(256) void attn_node_k(
    const __nv_bfloat16* __restrict__ q, const __nv_bfloat16* __restrict__ k,
    const float* __restrict__ v, const int* __restrict__ off,
    const int* __restrict__ srcs, const float* __restrict__ eas,
    const float* __restrict__ We, float* __restrict__ aggf)
{
    int wg = blockIdx.x * 8 + (threadIdx.x >> 5);
    int lane = threadIdx.x & 31;
    int d = wg >> 2, h = wg & 3;

    int beg = __ldg(off + d), end = __ldg(off + d + 1);

    uint2 qraw = *(const uint2*)(q + (size_t)d * HCC + h * CCC + lane * 4);
    float2 q01 = __bfloat1622float2(*(__nv_bfloat162*)&qraw.x);
    float2 q23 = __bfloat1622float2(*(__nv_bfloat162*)&qraw.y);
    const float4 wv = *(const float4*)(We + h * CCC + lane * 4);

    float a0 = 0.f, a1 = 0.f, a2 = 0.f, a3 = 0.f, den = 0.f;

    for (int i = beg; i < end; i++) {
        int sN = __ldg(srcs + i);
        float eav = __ldg(eas + i);

        uint2 kraw = *(const uint2*)(k + (size_t)sN * HCC + h * CCC + lane * 4);
        float2 k01 = __bfloat1622float2(*(__nv_bfloat162*)&kraw.x);
        float2 k23 = __bfloat1622float2(*(__nv_bfloat162*)&kraw.y);

        float s = q01.x * fmaf(eav, wv.x, k01.x) + q01.y * fmaf(eav, wv.y, k01.y)
                + q23.x * fmaf(eav, wv.z, k23.x) + q23.y * fmaf(eav, wv.w, k23.y);
#pragma unroll
        for (int o = 16; o; o >>= 1) s += __shfl_xor_sync(0xffffffffu, s, o);

        float pv = expf(s * 0.08838834764831845f);   // 1/sqrt(128)
        den += pv;

        const float4 vv = *(const float4*)(v + (size_t)sN * HCC + h * CCC + lane * 4);
        a0 = fmaf(fmaf(eav, wv.x, vv.x), pv, a0);
        a1 = fmaf(fmaf(eav, wv.y, vv.y), pv, a1);
        a2 = fmaf(fmaf(eav, wv.z, vv.z), pv, a2);
        a3 = fmaf(fmaf(eav, wv.w, vv.w), pv, a3);
    }

    float inv = 1.f / (den + 1e-16f);
    float vals[4] = {a0 * inv, a1 * inv, a2 * inv, a3 * inv};

    int slab = d >> 7, m = d & 127;
    float* base = aggf + (size_t)slab * 65536;
#pragma unroll
    for (int j = 0; j < 4; j++) {
        int kk = h * 128 + lane * 4 + j;
        base[(size_t)(kk >> 5) * 4096 + aidx(m, kk & 31)] = to_tf32(vals[j]);
    }
}

// ---------------- Fused ELU + residual + LayerNorm (+ frag-order x output) ----------------
__global__ __launch_bounds__(256) void ln_k(
    const float* __restrict__ x, const float* __restrict__ h,
    const float* __restrict__ gamma, const float* __restrict__ beta,
    float* __restrict__ out, float* __restrict__ xf)
{
    int row = blockIdx.x * 8 + (threadIdx.x >> 5);
    int lane = threadIdx.x & 31;

    const float4 xv = *(const float4*)(x + (size_t)row * HIDD + lane * 4);
    const float4 hv = *(const float4*)(h + (size_t)row * HIDD + lane * 4);

    float4 y;
    y.x = xv.x + (hv.x > 0.f ? hv.x : expm1f(hv.x));
    y.y = xv.y + (hv.y > 0.f ? hv.y : expm1f(hv.y));
    y.z = xv.z + (hv.z > 0.f ? hv.z : expm1f(hv.z));
    y.w = xv.w + (hv.w > 0.f ? hv.w : expm1f(hv.w));

    float sum = y.x + y.y + y.z + y.w;
    float sq  = y.x * y.x + y.y * y.y + y.z * y.z + y.w * y.w;
#pragma unroll
    for (int off = 16; off; off >>= 1) {
        sum += __shfl_xor_sync(0xffffffffu, sum, off);
        sq  += __shfl_xor_sync(0xffffffffu, sq, off);
    }
    float mu = sum * (1.f / 128.f);
    float var = sq * (1.f / 128.f) - mu * mu;
    float inv = rsqrtf(var + 1e-5f);

    const float4 gv = *(const float4*)(gamma + lane * 4);
    const float4 bv = *(const float4*)(beta + lane * 4);
    float4 o;
    o.x = (y.x - mu) * inv * gv.x + bv.x;
    o.y = (y.y - mu) * inv * gv.y + bv.y;
    o.z = (y.z - mu) * inv * gv.z + bv.z;
    o.w = (y.w - mu) * inv * gv.w + bv.w;
    *(float4*)(out + (size_t)row * HIDD + lane * 4) = o;

    if (xf) {
        int slab = row >> 7, m = row & 127;
        float vals[4] = {o.x, o.y, o.z, o.w};
#pragma unroll
        for (int j = 0; j < 4; j++) {
            int k = lane * 4 + j;
            xf[(size_t)slab * 16384 + (size_t)(k >> 5) * 4096 + aidx(m, k & 31)] =
                to_tf32(vals[j]);
        }
    }
}

// ---------------- host ----------------
extern "C" void kernel_launch(void* const* d_in, const int* in_sizes, int n_in,
                              void* d_out, int out_size)
{
    const float* x_in  = (const float*)d_in[0];
    const int*   ei    = (const int*)d_in[1];
    const float* ea    = (const float*)d_in[2];
    const float* Wq    = (const float*)d_in[3];
    const float* bq    = (const float*)d_in[4];
    const float* Wk    = (const float*)d_in[5];
    const float* bk    = (const float*)d_in[6];
    const float* Wv    = (const float*)d_in[7];
    const float* bv    = (const float*)d_in[8];
    const float* We    = (const float*)d_in[9];
    const float* Wskip = (const float*)d_in[10];
    const float* bskip = (const float*)d_in[11];
    const float* Wproj = (const float*)d_in[12];
    const float* bproj = (const float*)d_in[13];
    const float* gamma = (const float*)d_in[14];
    const float* beta  = (const float*)d_in[15];

    __nv_bfloat16 *qb, *kb;
    float *v, *h, *xbuf, *xf, *aggf, *wqkvf, *wpf, *wff, *bfv, *eas;
    int *deg, *off, *cur, *blk, *srcs;
    cudaGetSymbolAddress((void**)&qb,    g_qb);
    cudaGetSymbolAddress((void**)&kb,    g_kb);
    cudaGetSymbolAddress((void**)&v,     g_v);
    cudaGetSymbolAddress((void**)&h,     g_h);
    cudaGetSymbolAddress((void**)&xbuf,  g_x);
    cudaGetSymbolAddress((void**)&xf,    g_xf);
    cudaGetSymbolAddress((void**)&aggf,  g_aggf);
    cudaGetSymbolAddress((void**)&wqkvf, g_wqkvf);
    cudaGetSymbolAddress((void**)&wpf,   g_wpf);
    cudaGetSymbolAddress((void**)&wff,   g_wff);
    cudaGetSymbolAddress((void**)&bfv,   g_bf);
    cudaGetSymbolAddress((void**)&deg,   g_deg);
    cudaGetSymbolAddress((void**)&off,   g_off);
    cudaGetSymbolAddress((void**)&cur,   g_cur);
    cudaGetSymbolAddress((void**)&blk,   g_blk);
    cudaGetSymbolAddress((void**)&srcs,  g_srcs);
    cudaGetSymbolAddress((void**)&eas,   g_eas);

    cudaFuncSetAttribute(gemm_qkv_mma,  cudaFuncAttributeMaxDynamicSharedMemorySize,
                         QKV_SMEM_F * 4);
    cudaFuncSetAttribute(gemm_proj_mma, cudaFuncAttributeMaxDynamicSharedMemorySize,
                         PRJ_SMEM_F * 4);

    const int* src = ei;
    const int* dst = ei + EE;

    cudaMemcpyAsync(xbuf, x_in, (size_t)NN * HIDD * sizeof(float),
                    cudaMemcpyDeviceToDevice);
    init_xfrag_k<<<(NN * 32) / 256, 256>>>(x_in, xf);

    // weight prep (frag order) + CSR
    prep_qkv_w<<<2304, 256>>>(Wq, Wk, Wv, wqkvf);
    prep_proj_w<<<768, 256>>>(Wproj, wpf);
    wf_k<<<dim3(64, 3), 256>>>(Wskip, Wproj, wff);
    bf_k<<<3, 128>>>(bskip, Wproj, bproj, bfv);

    cudaMemsetAsync(deg, 0, NN * sizeof(int));
    hist_k<<<(EE + 255) / 256, 256>>>(dst, deg);
    scanA_k<<<(NN + 255) / 256, 256>>>(deg, off, blk);
    scanB_k<<<1, 256>>>(blk);
    scanC_k<<<(NN + 255) / 256, 256>>>(off, blk, cur);
    scatter_k<<<(EE + 255) / 256, 256>>>(src, dst, ea, cur, srcs, eas);

    const int nBlocks = NSLAB;               // 391
    const int attnBlocks = (NN * HH) / 8;    // 25000
    const int lnBlocks = NN / 8;             // 6250

    for (int l = 0; l < LLL; l++) {
        float* xo = (l == LLL - 1) ? (float*)d_out : xbuf;
        float* xfo = (l == LLL - 1) ? nullptr : xf;

        gemm_qkv_mma<<<dim3(2, nBlocks), 256, QKV_SMEM_F * 4>>>(
            xf, wqkvf + (size_t)l * 3 * 65536,
            bq + l * HCC, bk + l * HCC, bv + l * HCC, qb, kb, v);

        attn_node_k<<<attnBlocks, 256>>>(qb, kb, v, off, srcs, eas,
                                         We + l * HCC, aggf);

        gemm_proj_mma<<<nBlocks, 256, PRJ_SMEM_F * 4>>>(
            aggf, wpf + (size_t)l * 65536,
            xf, wff + (size_t)l * 16384,
            bfv + l * HIDD, h);

        ln_k<<<lnBlocks, 256>>>(xbuf, h, gamma + l * HIDD, beta + l * HIDD, xo, xfo);
    }
}

// round 10
// speedup vs baseline: 2.7022x; 1.0046x over previous
#include <cuda_runtime.h>
#include <cuda_bf16.h>
#include <math.h>
#include <stdint.h>

#define NN 50000
#define NPAD 50048          // 391 * 128
#define NSLAB 391
#define EE 100000
#define HIDD 128
#define HH 4
#define CCC 128
#define HCC 512
#define LLL 3

// ---------------- scratch ----------------
__device__ __nv_bfloat16 g_qb[(size_t)NPAD * HCC];
__device__ __nv_bfloat16 g_kb[(size_t)NPAD * HCC];
__device__ float g_v[(size_t)NPAD * HCC];
__device__ float g_x[(size_t)NPAD * HIDD];
// fragment-order buffers
__device__ float g_xf[(size_t)NSLAB * 16384];        // x, frag order
__device__ float g_aggf[(size_t)NSLAB * 65536];      // agg, frag order
__device__ float g_wqkvf[(size_t)LLL * 3 * 65536];   // Wq/Wk/Wv frag
__device__ float g_wpf[(size_t)LLL * 65536];         // Wproj frag
__device__ float g_wff[(size_t)LLL * 16384];         // Wskip@Wproj frag
__device__ float g_bf[(size_t)LLL * HIDD];           // bskip@Wproj + bproj

// CSR
__device__ int   g_deg[NN];
__device__ int   g_off[NN + 1];
__device__ int   g_cur[NN];
__device__ int   g_blk[256];
__device__ int   g_srcs[EE];
__device__ float g_eas[EE];

__device__ __forceinline__ float to_tf32(float x) {
    unsigned r;
    asm("cvt.rna.tf32.f32 %0, %1;" : "=r"(r) : "f"(x));
    return __uint_as_float(r);
}

__device__ __forceinline__ void mma168(float* d, const uint32_t* a, const uint32_t* b) {
    asm volatile("mma.sync.aligned.m16n8k8.row.col.f32.tf32.tf32.f32 "
        "{%0,%1,%2,%3}, {%4,%5,%6,%7}, {%8,%9}, {%0,%1,%2,%3};"
        : "+f"(d[0]), "+f"(d[1]), "+f"(d[2]), "+f"(d[3])
        : "r"(a[0]), "r"(a[1]), "r"(a[2]), "r"(a[3]), "r"(b[0]), "r"(b[1]));
}

__device__ __forceinline__ int aidx(int m, int kl) {
    int m_tile = m >> 4, r = m & 15;
    int c = kl & 7, k8l = kl >> 3;
    int lp = (r & 7) * 4 + (c & 3);
    int reg = (r >> 3) + 2 * (c >> 2);
    int u = k8l * 256 + m_tile * 32 + lp;
    return u * 4 + reg;
}
__device__ __forceinline__ int bidx(int kl, int nn) {
    int c = kl & 7, k8l = kl >> 3, reg = c >> 2;
    int n_tile = nn >> 3, lp = (nn & 7) * 4 + (c & 3);
    int v = (k8l * 16 + n_tile) * 32 + lp;
    return v * 2 + reg;
}

#define QKV_SMEM_B ((16384 + 2*4096) * 4)
#define PRJ_SMEM_B (128 * 132 * 4)       // 67584 >= mma phase's 65536

// ---------------- Fused QKV GEMM (tf32 mma, frag-order identity loads, N-split x4) ----------------
// grid (4, 391): 3 N-tiles / CTA, 12 stages.
__global__ __launch_bounds__(256, 2) void gemm_qkv_mma(
    const float* __restrict__ xf, const float* __restrict__ wf,
    const float* __restrict__ b0, const float* __restrict__ b1, const float* __restrict__ b2,
    __nv_bfloat16* __restrict__ oq, __nv_bfloat16* __restrict__ ok,
    float* __restrict__ ov)
{
    extern __shared__ float sm[];
    float* As = sm;                 // 16384 floats (4 A-chunks)
    float* Bs = sm + 16384;         // 2 x 4096

    const int tid = threadIdx.x;
    const int wid = tid >> 5;
    const int lane = tid & 31;
    const int m0 = blockIdx.y * 128;
    const int wm = wid >> 2;
    const int wn = wid & 3;
    const int t0 = blockIdx.x * 3;

    const float* bp[3] = {b0, b1, b2};

    {
        const float* asrc = xf + (size_t)blockIdx.y * 16384;
#pragma unroll
        for (int g = 0; g < 16; g++) {
            int o = (g * 256 + tid) * 4;
            *(float4*)(As + o) = *(const float4*)(asrc + o);
        }
    }

    float4 streg[4];
    auto ldgB = [&](const float* chunk) {
#pragma unroll
        for (int g = 0; g < 4; g++)
            streg[g] = *(const float4*)(chunk + (g * 256 + tid) * 4);
    };
    auto stsB = [&](int buf) {
        float* B = Bs + buf * 4096;
#pragma unroll
        for (int g = 0; g < 4; g++)
            *(float4*)(B + (g * 256 + tid) * 4) = streg[g];
    };
    auto chunkPtr = [&](int s) {
        int tg = t0 + (s >> 2);
        return wf + (size_t)(tg >> 2) * 65536 + (size_t)(((tg & 3) * 4) + (s & 3)) * 4096;
    };

    float acc[4][4][4];
    auto initAcc = [&](int tg) {
        const float* bias = bp[tg >> 2] + (tg & 3) * 128 + wn * 32;
#pragma unroll
        for (int j = 0; j < 4; j++) {
            float bv0 = __ldg(bias + j * 8 + 2 * (lane & 3));
            float bv1 = __ldg(bias + j * 8 + 2 * (lane & 3) + 1);
#pragma unroll
            for (int i = 0; i < 4; i++) {
                acc[i][j][0] = bv0; acc[i][j][1] = bv1;
                acc[i][j][2] = bv0; acc[i][j][3] = bv1;
            }
        }
    };
    auto epilogue = [&](int tg) {
        const int w = tg >> 2;
        const int col = (tg & 3) * 128 + wn * 32 + 2 * (lane & 3);
        if (w < 2) {
            __nv_bfloat16* out = (w == 0) ? oq : ok;
#pragma unroll
            for (int i = 0; i < 4; i++) {
                int row = m0 + wm * 64 + i * 16 + (lane >> 2);
#pragma unroll
                for (int j = 0; j < 4; j++) {
                    *(__nv_bfloat162*)(out + (size_t)row * HCC + col + j * 8) =
                        __floats2bfloat162_rn(acc[i][j][0], acc[i][j][1]);
                    *(__nv_bfloat162*)(out + (size_t)(row + 8) * HCC + col + j * 8) =
                        __floats2bfloat162_rn(acc[i][j][2], acc[i][j][3]);
                }
            }
        } else {
#pragma unroll
            for (int i = 0; i < 4; i++) {
                int row = m0 + wm * 64 + i * 16 + (lane >> 2);
#pragma unroll
                for (int j = 0; j < 4; j++) {
                    *(float2*)(ov + (size_t)row * HCC + col + j * 8) =
                        make_float2(acc[i][j][0], acc[i][j][1]);
                    *(float2*)(ov + (size_t)(row + 8) * HCC + col + j * 8) =
                        make_float2(acc[i][j][2], acc[i][j][3]);
                }
            }
        }
    };
    auto mmaChunk = [&](int buf, int kc) {
        const float* B = Bs + buf * 4096;
        const float* Ac = As + kc * 4096;
#pragma unroll
        for (int k8l = 0; k8l < 4; k8l++) {
            uint32_t af[4][4];
#pragma unroll
            for (int i = 0; i < 4; i++) {
                uint32_t u = (uint32_t)(k8l * 256 + (wm * 4 + i) * 32 + lane);
                uint4 t4 = *(const uint4*)(Ac + u * 4);
                af[i][0] = t4.x; af[i][1] = t4.y; af[i][2] = t4.z; af[i][3] = t4.w;
            }
            uint32_t bf[4][2];
#pragma unroll
            for (int j = 0; j < 4; j++) {
                uint32_t v = (uint32_t)((k8l * 16 + wn * 4 + j) * 32 + lane);
                uint2 t2 = *(const uint2*)(B + v * 2);
                bf[j][0] = t2.x; bf[j][1] = t2.y;
            }
#pragma unroll
            for (int i = 0; i < 4; i++)
#pragma unroll
                for (int j = 0; j < 4; j++)
                    mma168(acc[i][j], af[i], bf[j]);
        }
    };

    ldgB(chunkPtr(0));
    stsB(0);
    initAcc(t0);

    for (int s = 0; s < 12; s++) {
        __syncthreads();
        int tg = t0 + (s >> 2), kc = s & 3;
        if (s < 11) ldgB(chunkPtr(s + 1));
        mmaChunk(s & 1, kc);
        if (s < 11) stsB((s + 1) & 1);
        if (kc == 3) {
            epilogue(tg);
            if ((s >> 2) < 2) initAcc(tg + 1);
        }
    }
}

// ---------------- Proj GEMM + ELU + residual + LayerNorm (fully fused) ----------------
// out_row = LN(x + elu(agg@Wproj + x@Wf + bias)); also emits frag-order xf for next layer.
__global__ __launch_bounds__(256, 2) void gemm_proj_ln(
    const float* __restrict__ aggf, const float* __restrict__ wpf,
    const float* __restrict__ xf, const float* __restrict__ wff,
    const float* __restrict__ bias,
    const float* __restrict__ x, const float* __restrict__ gamma,
    const float* __restrict__ beta,
    float* __restrict__ out, float* __restrict__ xfo)
{
    extern __shared__ float sm[];
    float* As = sm;                 // mma phase: 2x4096 A + 2x4096 B
    float* Bs = sm + 8192;

    const int tid = threadIdx.x;
    const int wid = tid >> 5;
    const int lane = tid & 31;
    const int slab = blockIdx.x;
    const int m0 = slab * 128;
    const int wm = wid >> 2;
    const int wn = wid & 3;

    float4 sa[4], sb[4];
    auto ldgStage = [&](int s1) {
        const float *Asrc, *Bsrc;
        if (s1 < 16) {
            Asrc = aggf + (size_t)slab * 65536 + (size_t)s1 * 4096;
            Bsrc = wpf + (size_t)s1 * 4096;
        } else {
            Asrc = xf + (size_t)slab * 16384 + (size_t)(s1 - 16) * 4096;
            Bsrc = wff + (size_t)(s1 - 16) * 4096;
        }
#pragma unroll
        for (int g = 0; g < 4; g++)
            sa[g] = *(const float4*)(Asrc + (g * 256 + tid) * 4);
#pragma unroll
        for (int g = 0; g < 4; g++)
            sb[g] = *(const float4*)(Bsrc + (g * 256 + tid) * 4);
    };
    auto stsStage = [&](int buf) {
        float* Adst = As + buf * 4096;
        float* Bdst = Bs + buf * 4096;
#pragma unroll
        for (int g = 0; g < 4; g++)
            *(float4*)(Adst + (g * 256 + tid) * 4) = sa[g];
#pragma unroll
        for (int g = 0; g < 4; g++)
            *(float4*)(Bdst + (g * 256 + tid) * 4) = sb[g];
    };

    float acc[4][4][4];
    {
        const float* bp = bias + wn * 32;
#pragma unroll
        for (int j = 0; j < 4; j++) {
            float bv0 = __ldg(bp + j * 8 + 2 * (lane & 3));
            float bv1 = __ldg(bp + j * 8 + 2 * (lane & 3) + 1);
#pragma unroll
            for (int i = 0; i < 4; i++) {
                acc[i][j][0] = bv0; acc[i][j][1] = bv1;
                acc[i][j][2] = bv0; acc[i][j][3] = bv1;
            }
        }
    }

    ldgStage(0);
    stsStage(0);

    for (int s = 0; s < 20; s++) {
        __syncthreads();
        if (s < 19) ldgStage(s + 1);
        {
            const float* Ac = As + (s & 1) * 4096;
            const float* Bc = Bs + (s & 1) * 4096;
#pragma unroll
            for (int k8l = 0; k8l < 4; k8l++) {
                uint32_t af[4][4];
#pragma unroll
                for (int i = 0; i < 4; i++) {
                    uint32_t u = (uint32_t)(k8l * 256 + (wm * 4 + i) * 32 + lane);
                    uint4 t4 = *(const uint4*)(Ac + u * 4);
                    af[i][0] = t4.x; af[i][1] = t4.y; af[i][2] = t4.z; af[i][3] = t4.w;
                }
                uint32_t bf[4][2];
#pragma unroll
                for (int j = 0; j < 4; j++) {
                    uint32_t v = (uint32_t)((k8l * 16 + wn * 4 + j) * 32 + lane);
                    uint2 t2 = *(const uint2*)(Bc + v * 2);
                    bf[j][0] = t2.x; bf[j][1] = t2.y;
                }
#pragma unroll
                for (int i = 0; i < 4; i++)
#pragma unroll
                    for (int j = 0; j < 4; j++)
                        mma168(acc[i][j], af[i], bf[j]);
            }
        }
        if (s < 19) stsStage((s + 1) & 1);
    }

    // ---- fused epilogue: stage elu(h) in smem tile [128][132], then LN per row ----
    __syncthreads();
    float* ht = sm;
    {
        int col = wn * 32 + 2 * (lane & 3);
#pragma unroll
        for (int i = 0; i < 4; i++) {
            int r0 = wm * 64 + i * 16 + (lane >> 2);
#pragma unroll
            for (int j = 0; j < 4; j++) {
                float e0 = acc[i][j][0], e1 = acc[i][j][1];
                float e2 = acc[i][j][2], e3 = acc[i][j][3];
                ht[r0 * 132 + col + j * 8]           = e0 > 0.f ? e0 : expm1f(e0);
                ht[r0 * 132 + col + j * 8 + 1]       = e1 > 0.f ? e1 : expm1f(e1);
                ht[(r0 + 8) * 132 + col + j * 8]     = e2 > 0.f ? e2 : expm1f(e2);
                ht[(r0 + 8) * 132 + col + j * 8 + 1] = e3 > 0.f ? e3 : expm1f(e3);
            }
        }
    }
    __syncthreads();

    const float4 gv = *(const float4*)(gamma + lane * 4);
    const float4 bv = *(const float4*)(beta + lane * 4);

#pragma unroll
    for (int r = 0; r < 16; r++) {
        int row = wid * 16 + r;
        int grow = m0 + row;
        float4 h4 = *(const float4*)(ht + row * 132 + lane * 4);
        float4 x4 = *(const float4*)(x + (size_t)grow * HIDD + lane * 4);
        float4 y;
        y.x = x4.x + h4.x; y.y = x4.y + h4.y;
        y.z = x4.z + h4.z; y.w = x4.w + h4.w;

        float sum = y.x + y.y + y.z + y.w;
        float sq  = y.x * y.x + y.y * y.y + y.z * y.z + y.w * y.w;
#pragma unroll
        for (int off = 16; off; off >>= 1) {
            sum += __shfl_xor_sync(0xffffffffu, sum, off);
            sq  += __shfl_xor_sync(0xffffffffu, sq, off);
        }
        float mu = sum * (1.f / 128.f);
        float var = sq * (1.f / 128.f) - mu * mu;
        float inv = rsqrtf(var + 1e-5f);

        float4 o;
        o.x = (y.x - mu) * inv * gv.x + bv.x;
        o.y = (y.y - mu) * inv * gv.y + bv.y;
        o.z = (y.z - mu) * inv * gv.z + bv.z;
        o.w = (y.w - mu) * inv * gv.w + bv.w;

        if (grow < NN)
            *(float4*)(out + (size_t)grow * HIDD + lane * 4) = o;

        if (xfo) {
            float vals[4] = {o.x, o.y, o.z, o.w};
            float* dst = xfo + (size_t)slab * 16384;
#pragma unroll
            for (int j = 0; j < 4; j++) {
                int k = lane * 4 + j;
                dst[(size_t)(k >> 5) * 4096 + aidx(row, k & 31)] = to_tf32(vals[j]);
            }
        }
    }
}

// ---------------- Weight prep ----------------
__global__ void prep_qkv_w(const float* __restrict__ Wq, const float* __restrict__ Wk,
                           const float* __restrict__ Wv, float* __restrict__ dst)
{
    int t = blockIdx.x * 256 + threadIdx.x;
    int l = t / 196608;
    int r = t - l * 196608;
    int w = r >> 16;
    int e = r & 65535;
    int k = e >> 9, n = e & 511;
    const float* W = (w == 0 ? Wq : (w == 1 ? Wk : Wv)) + (size_t)l * 65536;
    float val = W[k * 512 + n];
    int nc = n >> 7, nn = n & 127, kc = k >> 5, kl = k & 31;
    dst[(size_t)(l * 3 + w) * 65536 + (size_t)(nc * 4 + kc) * 4096 + bidx(kl, nn)] =
        to_tf32(val);
}

__global__ void prep_proj_w(const float* __restrict__ Wproj, float* __restrict__ dst)
{
    int t = blockIdx.x * 256 + threadIdx.x;
    int l = t >> 16, e = t & 65535;
    int k = e >> 7, n = e & 127;
    float val = Wproj[(size_t)l * 65536 + k * 128 + n];
    dst[(size_t)l * 65536 + (size_t)(k >> 5) * 4096 + bidx(k & 31, n)] = to_tf32(val);
}

// Wf = Wskip @ Wproj (4 independent accumulator chains)
__global__ void wf_k(const float* __restrict__ Wskip, const float* __restrict__ Wproj,
                     float* __restrict__ wff)
{
    int l = blockIdx.y;
    int e = blockIdx.x * 256 + threadIdx.x;
    int i = e >> 7, j = e & 127;
    const float* ws = Wskip + (size_t)l * HIDD * HCC + (size_t)i * HCC;
    const float* wp = Wproj + (size_t)l * HCC * HIDD + j;
    float s0 = 0.f, s1 = 0.f, s2 = 0.f, s3 = 0.f;
#pragma unroll 8
    for (int k = 0; k < HCC; k += 4) {
        s0 = fmaf(ws[k],     wp[(size_t)k * HIDD],           s0);
        s1 = fmaf(ws[k + 1], wp[(size_t)(k + 1) * HIDD],     s1);
        s2 = fmaf(ws[k + 2], wp[(size_t)(k + 2) * HIDD],     s2);
        s3 = fmaf(ws[k + 3], wp[(size_t)(k + 3) * HIDD],     s3);
    }
    float s = (s0 + s1) + (s2 + s3);
    wff[(size_t)l * 16384 + (size_t)(i >> 5) * 4096 + bidx(i & 31, j)] = to_tf32(s);
}

__global__ void bf_k(const float* __restrict__ bskip, const float* __restrict__ Wproj,
                     const float* __restrict__ bproj, float* __restrict__ bf)
{
    int l = blockIdx.x, j = threadIdx.x;
    const float* bs = bskip + (size_t)l * HCC;
    const float* wp = Wproj + (size_t)l * HCC * HIDD + j;
    float s0 = 0.f, s1 = 0.f, s2 = 0.f, s3 = 0.f;
#pragma unroll 8
    for (int k = 0; k < HCC; k += 4) {
        s0 = fmaf(bs[k],     wp[(size_t)k * HIDD],       s0);
        s1 = fmaf(bs[k + 1], wp[(size_t)(k + 1) * HIDD], s1);
        s2 = fmaf(bs[k + 2], wp[(size_t)(k + 2) * HIDD], s2);
        s3 = fmaf(bs[k + 3], wp[(size_t)(k + 3) * HIDD], s3);
    }
    bf[l * HIDD + j] = bproj[(size_t)l * HIDD + j] + (s0 + s1) + (s2 + s3);
}

// x_in -> frag order (layer 0)
__global__ void init_xfrag_k(const float* __restrict__ x, float* __restrict__ xf)
{
    int t = blockIdx.x * 256 + threadIdx.x;
    int row = t >> 5, lane = t & 31;
    float4 v = *(const float4*)(x + (size_t)row * HIDD + lane * 4);
    int slab = row >> 7, m = row & 127;
    float vals[4] = {v.x, v.y, v.z, v.w};
#pragma unroll
    for (int j = 0; j < 4; j++) {
        int k = lane * 4 + j;
        xf[(size_t)slab * 16384 + (size_t)(k >> 5) * 4096 + aidx(m, k & 31)] =
            to_tf32(vals[j]);
    }
}

// ---------------- CSR build ----------------
__global__ void hist_k(const int* __restrict__ dst, int* __restrict__ deg) {
    int e = blockIdx.x * 256 + threadIdx.x;
    if (e < EE) atomicAdd(deg + dst[e], 1);
}

__global__ void scanA_k(const int* __restrict__ deg, int* __restrict__ off,
                        int* __restrict__ blk) {
    __shared__ int sh[256];
    int t = threadIdx.x;
    int idx = blockIdx.x * 256 + t;
    int val = (idx < NN) ? deg[idx] : 0;
    sh[t] = val;
    __syncthreads();
#pragma unroll
    for (int d = 1; d < 256; d <<= 1) {
        int add = (t >= d) ? sh[t - d] : 0;
        __syncthreads();
        sh[t] += add;
        __syncthreads();
    }
    if (idx < NN) off[idx] = sh[t] - val;
    if (t == 255) blk[blockIdx.x] = sh[255];
}

__global__ void scanB_k(int* __restrict__ blk) {
    __shared__ int sh[256];
    int t = threadIdx.x;
    int val = (t < 196) ? blk[t] : 0;
    sh[t] = val;
    __syncthreads();
#pragma unroll
    for (int d = 1; d < 256; d <<= 1) {
        int add = (t >= d) ? sh[t - d] : 0;
        __syncthreads();
        sh[t] += add;
        __syncthreads();
    }
    if (t < 196) blk[t] = sh[t] - val;
}

__global__ void scanC_k(int* __restrict__ off, const int* __restrict__ blk,
                        int* __restrict__ cur) {
    int idx = blockIdx.x * 256 + threadIdx.x;
    if (idx < NN) {
        int o = off[idx] + blk[blockIdx.x];
        off[idx] = o;
        cur[idx] = o;
    }
    if (idx == 0) off[NN] = EE;
}

__global__ void scatter_k(const int* __restrict__ src, const int* __restrict__ dst,
                          const float* __restrict__ ea, int* __restrict__ cur,
                          int* __restrict__ srcs, float* __restrict__ eas) {
    int e = blockIdx.x * 256 + threadIdx.x;
    if (e < EE) {
        int p = atomicAdd(cur + dst[e], 1);
        srcs[p] = src[e];
        eas[p] = ea[e];
    }
}

// ---------------- Node-centric fused attention ----------------
__global__ __launch_bounds__(256) void attn_node_k(
    const __nv_bfloat16* __restrict__ q, const __nv_bfloat16* __restrict__ k,
    const float* __restrict__ v, const int* __restrict__ off,
    const int* __restrict__ srcs, const float* __restrict__ eas,
    const float* __restrict__ We, float* __restrict__ aggf)
{
    int wg = blockIdx.x * 8 + (threadIdx.x >> 5);
    int lane = threadIdx.x & 31;
    int d = wg >> 2, h = wg & 3;

    int beg = __ldg(off + d), end = __ldg(off + d + 1);

    uint2 qraw = *(const uint2*)(q + (size_t)d * HCC + h * CCC + lane * 4);
    float2 q01 = __bfloat1622float2(*(__nv_bfloat162*)&qraw.x);
    float2 q23 = __bfloat1622float2(*(__nv_bfloat162*)&qraw.y);
    const float4 wv = *(const float4*)(We + h * CCC + lane * 4);

    float a0 = 0.f, a1 = 0.f, a2 = 0.f, a3 = 0.f, den = 0.f;

    for (int i = beg; i < end; i++) {
        int sN = __ldg(srcs + i);
        float eav = __ldg(eas + i);

        uint2 kraw = *(const uint2*)(k + (size_t)sN * HCC + h * CCC + lane * 4);
        float2 k01 = __bfloat1622float2(*(__nv_bfloat162*)&kraw.x);
        float2 k23 = __bfloat1622float2(*(__nv_bfloat162*)&kraw.y);

        float s = q01.x * fmaf(eav, wv.x, k01.x) + q01.y * fmaf(eav, wv.y, k01.y)
                + q23.x * fmaf(eav, wv.z, k23.x) + q23.y * fmaf(eav, wv.w, k23.y);
#pragma unroll
        for (int o = 16; o; o >>= 1) s += __shfl_xor_sync(0xffffffffu, s, o);

        float pv = expf(s * 0.08838834764831845f);
        den += pv;

        const float4 vv = *(const float4*)(v + (size_t)sN * HCC + h * CCC + lane * 4);
        a0 = fmaf(fmaf(eav, wv.x, vv.x), pv, a0);
        a1 = fmaf(fmaf(eav, wv.y, vv.y), pv, a1);
        a2 = fmaf(fmaf(eav, wv.z, vv.z), pv, a2);
        a3 = fmaf(fmaf(eav, wv.w, vv.w), pv, a3);
    }

    float inv = 1.f / (den + 1e-16f);
    float vals[4] = {a0 * inv, a1 * inv, a2 * inv, a3 * inv};

    int slab = d >> 7, m = d & 127;
    float* base = aggf + (size_t)slab * 65536;
#pragma unroll
    for (int j = 0; j < 4; j++) {
        int kk = h * 128 + lane * 4 + j;
        base[(size_t)(kk >> 5) * 4096 + aidx(m, kk & 31)] = to_tf32(vals[j]);
    }
}

// ---------------- host ----------------
extern "C" void kernel_launch(void* const* d_in, const int* in_sizes, int n_in,
                              void* d_out, int out_size)
{
    const float* x_in  = (const float*)d_in[0];
    const int*   ei    = (const int*)d_in[1];
    const float* ea    = (const float*)d_in[2];
    const float* Wq    = (const float*)d_in[3];
    const float* bq    = (const float*)d_in[4];
    const float* Wk    = (const float*)d_in[5];
    const float* bk    = (const float*)d_in[6];
    const float* Wv    = (const float*)d_in[7];
    const float* bv    = (const float*)d_in[8];
    const float* We    = (const float*)d_in[9];
    const float* Wskip = (const float*)d_in[10];
    const float* bskip = (const float*)d_in[11];
    const float* Wproj = (const float*)d_in[12];
    const float* bproj = (const float*)d_in[13];
    const float* gamma = (const float*)d_in[14];
    const float* beta  = (const float*)d_in[15];

    __nv_bfloat16 *qb, *kb;
    float *v, *xbuf, *xf, *aggf, *wqkvf, *wpf, *wff, *bfv, *eas;
    int *deg, *off, *cur, *blk, *srcs;
    cudaGetSymbolAddress((void**)&qb,    g_qb);
    cudaGetSymbolAddress((void**)&kb,    g_kb);
    cudaGetSymbolAddress((void**)&v,     g_v);
    cudaGetSymbolAddress((void**)&xbuf,  g_x);
    cudaGetSymbolAddress((void**)&xf,    g_xf);
    cudaGetSymbolAddress((void**)&aggf,  g_aggf);
    cudaGetSymbolAddress((void**)&wqkvf, g_wqkvf);
    cudaGetSymbolAddress((void**)&wpf,   g_wpf);
    cudaGetSymbolAddress((void**)&wff,   g_wff);
    cudaGetSymbolAddress((void**)&bfv,   g_bf);
    cudaGetSymbolAddress((void**)&deg,   g_deg);
    cudaGetSymbolAddress((void**)&off,   g_off);
    cudaGetSymbolAddress((void**)&cur,   g_cur);
    cudaGetSymbolAddress((void**)&blk,   g_blk);
    cudaGetSymbolAddress((void**)&srcs,  g_srcs);
    cudaGetSymbolAddress((void**)&eas,   g_eas);

    cudaFuncSetAttribute(gemm_qkv_mma, cudaFuncAttributeMaxDynamicSharedMemorySize,
                         QKV_SMEM_B);
    cudaFuncSetAttribute(gemm_proj_ln, cudaFuncAttributeMaxDynamicSharedMemorySize,
                         PRJ_SMEM_B);

    const int* src = ei;
    const int* dst = ei + EE;

    cudaMemcpyAsync(xbuf, x_in, (size_t)NN * HIDD * sizeof(float),
                    cudaMemcpyDeviceToDevice);
    init_xfrag_k<<<(NN * 32) / 256, 256>>>(x_in, xf);

    prep_qkv_w<<<2304, 256>>>(Wq, Wk, Wv, wqkvf);
    prep_proj_w<<<768, 256>>>(Wproj, wpf);
    wf_k<<<dim3(64, 3), 256>>>(Wskip, Wproj, wff);
    bf_k<<<3, 128>>>(bskip, Wproj, bproj, bfv);

    cudaMemsetAsync(deg, 0, NN * sizeof(int));
    hist_k<<<(EE + 255) / 256, 256>>>(dst, deg);
    scanA_k<<<(NN + 255) / 256, 256>>>(deg, off, blk);
    scanB_k<<<1, 256>>>(blk);
    scanC_k<<<(NN + 255) / 256, 256>>>(off, blk, cur);
    scatter_k<<<(EE + 255) / 256, 256>>>(src, dst, ea, cur, srcs, eas);

    const int attnBlocks = (NN * HH) / 8;    // 25000

    for (int l = 0; l < LLL; l++) {
        float* xo = (l == LLL - 1) ? (float*)d_out : xbuf;
        float* xfo = (l == LLL - 1) ? nullptr : xf;

        gemm_qkv_mma<<<dim3(4, NSLAB), 256, QKV_SMEM_B>>>(
            xf, wqkvf + (size_t)l * 3 * 65536,
            bq + l * HCC, bk + l * HCC, bv + l * HCC, qb, kb, v);

        attn_node_k<<<attnBlocks, 256>>>(qb, kb, v, off, srcs, eas,
                                         We + l * HCC, aggf);

        gemm_proj_ln<<<NSLAB, 256, PRJ_SMEM_B>>>(
            aggf, wpf + (size_t)l * 65536,
            xf, wff + (size_t)l * 16384,
            bfv + l * HIDD,
            xbuf, gamma + l * HIDD, beta + l * HIDD,
            xo, xfo);
    }
}

// round 11
// speedup vs baseline: 3.6336x; 1.3447x over previous
#include <cuda_runtime.h>
#include <cuda_bf16.h>
#include <cuda_fp16.h>
#include <math.h>
#include <stdint.h>

#define NN 50000
#define NPAD 50048          // 391 * 128
#define NSLAB 391
#define EE 100000
#define HIDD 128
#define HH 4
#define CCC 128
#define HCC 512
#define LLL 3

// ---------------- scratch ----------------
__device__ __nv_bfloat16 g_qb[(size_t)NPAD * HCC];
__device__ __nv_bfloat16 g_kb[(size_t)NPAD * HCC];
__device__ float g_v[(size_t)NPAD * HCC];
__device__ float g_x[(size_t)NPAD * HIDD];
// fragment-order fp16 buffers (uint32 views; 1 chunk = 2048 u32 = 4096 halves)
__device__ uint32_t g_xf[(size_t)NSLAB * 8192];          // x frag (4 chunks/slab)
__device__ uint32_t g_aggf[(size_t)NSLAB * 32768];       // agg frag (16 chunks/slab)
__device__ uint32_t g_wqkvf[(size_t)LLL * 3 * 32768];    // Wq/Wk/Wv frag
__device__ uint32_t g_wpf[(size_t)LLL * 32768];          // Wproj frag
__device__ uint32_t g_wff[(size_t)LLL * 8192];           // Wskip@Wproj frag
__device__ float g_bf[(size_t)LLL * HIDD];               // bskip@Wproj + bproj

// CSR
__device__ int   g_deg[NN];
__device__ int   g_off[NN + 1];
__device__ int   g_cur[NN];
__device__ int   g_blk[256];
__device__ int   g_srcs[EE];
__device__ float g_eas[EE];

// fp16 mma m16n8k16: D += A*B (fp32 acc in-place)
__device__ __forceinline__ void mma16816(float* d, const uint32_t* a, const uint32_t* b) {
    asm volatile("mma.sync.aligned.m16n8k16.row.col.f32.f16.f16.f32 "
        "{%0,%1,%2,%3}, {%4,%5,%6,%7}, {%8,%9}, {%0,%1,%2,%3};"
        : "+f"(d[0]), "+f"(d[1]), "+f"(d[2]), "+f"(d[3])
        : "r"(a[0]), "r"(a[1]), "r"(a[2]), "r"(a[3]), "r"(b[0]), "r"(b[1]));
}

// half-index within one A chunk (128m x 32k fp16, 4096 halves)
__device__ __forceinline__ int aidx_h(int m, int kk) {
    int m_tile = m >> 4, r = m & 15;
    int k16 = kk >> 4, kw = kk & 15;
    int lane = (r & 7) * 4 + ((kw & 7) >> 1);
    int reg = ((kw >> 3) << 1) + (r >> 3);
    int u = ((k16 * 8 + m_tile) * 32 + lane) * 4 + reg;
    return u * 2 + (kw & 1);
}
// half-index within one B chunk (32k x 128n fp16, 4096 halves)
__device__ __forceinline__ int bidx_h(int kk, int n) {
    int k16 = kk >> 4, kw = kk & 15;
    int n_tile = n >> 3, nn = n & 7;
    int tg = (kw & 7) >> 1;
    int lane = nn * 4 + tg;
    int reg = kw >> 3;
    int u = ((k16 * 16 + n_tile) * 32 + lane) * 2 + reg;
    return u * 2 + (kw & 1);
}

#define QKV_SMEM_B ((8192 + 2*2048) * 4)     // 49152
#define PRJ_SMEM_B (128 * 132 * 4)           // 67584 (LN tile; > mma phase's 32768)

// ---------------- Fused QKV GEMM (fp16 mma, frag-order identity, N-split x4) ----------------
// grid (4, 391): 3 N-tiles / CTA, 12 stages of 32-k.
__global__ __launch_bounds__(256, 2) void gemm_qkv_mma(
    const uint32_t* __restrict__ xf, const uint32_t* __restrict__ wf,
    const float* __restrict__ b0, const float* __restrict__ b1, const float* __restrict__ b2,
    __nv_bfloat16* __restrict__ oq, __nv_bfloat16* __restrict__ ok,
    float* __restrict__ ov)
{
    extern __shared__ uint32_t smu[];
    uint32_t* As = smu;              // 4 chunks x 2048 u32
    uint32_t* Bs = smu + 8192;       // 2 x 2048 u32

    const int tid = threadIdx.x;
    const int wid = tid >> 5;
    const int lane = tid & 31;
    const int m0 = blockIdx.y * 128;
    const int wm = wid >> 2;
    const int wn = wid & 3;
    const int t0 = blockIdx.x * 3;

    const float* bp[3] = {b0, b1, b2};

    {
        const uint32_t* asrc = xf + (size_t)blockIdx.y * 8192;
#pragma unroll
        for (int g = 0; g < 8; g++) {
            int o = (g * 256 + tid) * 4;
            *(uint4*)(As + o) = *(const uint4*)(asrc + o);
        }
    }

    uint4 streg[2];
    auto ldgB = [&](const uint32_t* chunk) {
#pragma unroll
        for (int g = 0; g < 2; g++)
            streg[g] = *(const uint4*)(chunk + (g * 256 + tid) * 4);
    };
    auto stsB = [&](int buf) {
        uint32_t* B = Bs + buf * 2048;
#pragma unroll
        for (int g = 0; g < 2; g++)
            *(uint4*)(B + (g * 256 + tid) * 4) = streg[g];
    };
    auto chunkPtr = [&](int s) {
        int tg = t0 + (s >> 2);
        return wf + (size_t)(tg >> 2) * 32768 + (size_t)(((tg & 3) * 4) + (s & 3)) * 2048;
    };

    float acc[4][4][4];
    auto initAcc = [&](int tg) {
        const float* bias = bp[tg >> 2] + (tg & 3) * 128 + wn * 32;
#pragma unroll
        for (int j = 0; j < 4; j++) {
            float bv0 = __ldg(bias + j * 8 + 2 * (lane & 3));
            float bv1 = __ldg(bias + j * 8 + 2 * (lane & 3) + 1);
#pragma unroll
            for (int i = 0; i < 4; i++) {
                acc[i][j][0] = bv0; acc[i][j][1] = bv1;
                acc[i][j][2] = bv0; acc[i][j][3] = bv1;
            }
        }
    };
    auto epilogue = [&](int tg) {
        const int w = tg >> 2;
        const int col = (tg & 3) * 128 + wn * 32 + 2 * (lane & 3);
        if (w < 2) {
            __nv_bfloat16* out = (w == 0) ? oq : ok;
#pragma unroll
            for (int i = 0; i < 4; i++) {
                int row = m0 + wm * 64 + i * 16 + (lane >> 2);
#pragma unroll
                for (int j = 0; j < 4; j++) {
                    *(__nv_bfloat162*)(out + (size_t)row * HCC + col + j * 8) =
                        __floats2bfloat162_rn(acc[i][j][0], acc[i][j][1]);
                    *(__nv_bfloat162*)(out + (size_t)(row + 8) * HCC + col + j * 8) =
                        __floats2bfloat162_rn(acc[i][j][2], acc[i][j][3]);
                }
            }
        } else {
#pragma unroll
            for (int i = 0; i < 4; i++) {
                int row = m0 + wm * 64 + i * 16 + (lane >> 2);
#pragma unroll
                for (int j = 0; j < 4; j++) {
                    *(float2*)(ov + (size_t)row * HCC + col + j * 8) =
                        make_float2(acc[i][j][0], acc[i][j][1]);
                    *(float2*)(ov + (size_t)(row + 8) * HCC + col + j * 8) =
                        make_float2(acc[i][j][2], acc[i][j][3]);
                }
            }
        }
    };
    auto mmaChunk = [&](int buf, int kc) {
        const uint32_t* B = Bs + buf * 2048;
        const uint32_t* Ac = As + kc * 2048;
#pragma unroll
        for (int k16 = 0; k16 < 2; k16++) {
            uint32_t af[4][4];
#pragma unroll
            for (int i = 0; i < 4; i++) {
                uint32_t u = (uint32_t)(((k16 * 8 + wm * 4 + i) * 32 + lane) * 4);
                uint4 t4 = *(const uint4*)(Ac + u);
                af[i][0] = t4.x; af[i][1] = t4.y; af[i][2] = t4.z; af[i][3] = t4.w;
            }
            uint32_t bf[4][2];
#pragma unroll
            for (int j = 0; j < 4; j++) {
                uint32_t v = (uint32_t)(((k16 * 16 + wn * 4 + j) * 32 + lane) * 2);
                uint2 t2 = *(const uint2*)(B + v);
                bf[j][0] = t2.x; bf[j][1] = t2.y;
            }
#pragma unroll
            for (int i = 0; i < 4; i++)
#pragma unroll
                for (int j = 0; j < 4; j++)
                    mma16816(acc[i][j], af[i], bf[j]);
        }
    };

    ldgB(chunkPtr(0));
    stsB(0);
    initAcc(t0);

    for (int s = 0; s < 12; s++) {
        __syncthreads();
        int tg = t0 + (s >> 2), kc = s & 3;
        if (s < 11) ldgB(chunkPtr(s + 1));
        mmaChunk(s & 1, kc);
        if (s < 11) stsB((s + 1) & 1);
        if (kc == 3) {
            epilogue(tg);
            if ((s >> 2) < 2) initAcc(tg + 1);
        }
    }
}

// ---------------- Proj GEMM + ELU + residual + LayerNorm (fp16 mma, fused) ----------------
__global__ __launch_bounds__(256, 2) void gemm_proj_ln(
    const uint32_t* __restrict__ aggf, const uint32_t* __restrict__ wpf,
    const uint32_t* __restrict__ xf, const uint32_t* __restrict__ wff,
    const float* __restrict__ bias,
    const float* __restrict__ x, const float* __restrict__ gamma,
    const float* __restrict__ beta,
    float* __restrict__ out, uint32_t* __restrict__ xfo)
{
    extern __shared__ uint32_t smu[];
    uint32_t* As = smu;              // 2 x 2048
    uint32_t* Bs = smu + 4096;       // 2 x 2048

    const int tid = threadIdx.x;
    const int wid = tid >> 5;
    const int lane = tid & 31;
    const int slab = blockIdx.x;
    const int m0 = slab * 128;
    const int wm = wid >> 2;
    const int wn = wid & 3;

    uint4 sa[2], sb[2];
    auto ldgStage = [&](int s1) {
        const uint32_t *Asrc, *Bsrc;
        if (s1 < 16) {
            Asrc = aggf + (size_t)slab * 32768 + (size_t)s1 * 2048;
            Bsrc = wpf + (size_t)s1 * 2048;
        } else {
            Asrc = xf + (size_t)slab * 8192 + (size_t)(s1 - 16) * 2048;
            Bsrc = wff + (size_t)(s1 - 16) * 2048;
        }
#pragma unroll
        for (int g = 0; g < 2; g++)
            sa[g] = *(const uint4*)(Asrc + (g * 256 + tid) * 4);
#pragma unroll
        for (int g = 0; g < 2; g++)
            sb[g] = *(const uint4*)(Bsrc + (g * 256 + tid) * 4);
    };
    auto stsStage = [&](int buf) {
        uint32_t* Adst = As + buf * 2048;
        uint32_t* Bdst = Bs + buf * 2048;
#pragma unroll
        for (int g = 0; g < 2; g++)
            *(uint4*)(Adst + (g * 256 + tid) * 4) = sa[g];
#pragma unroll
        for (int g = 0; g < 2; g++)
            *(uint4*)(Bdst + (g * 256 + tid) * 4) = sb[g];
    };

    float acc[4][4][4];
    {
        const float* bp = bias + wn * 32;
#pragma unroll
        for (int j = 0; j < 4; j++) {
            float bv0 = __ldg(bp + j * 8 + 2 * (lane & 3));
            float bv1 = __ldg(bp + j * 8 + 2 * (lane & 3) + 1);
#pragma unroll
            for (int i = 0; i < 4; i++) {
                acc[i][j][0] = bv0; acc[i][j][1] = bv1;
                acc[i][j][2] = bv0; acc[i][j][3] = bv1;
            }
        }
    }

    ldgStage(0);
    stsStage(0);

    for (int s = 0; s < 20; s++) {
        __syncthreads();
        if (s < 19) ldgStage(s + 1);
        {
            const uint32_t* Ac = As + (s & 1) * 2048;
            const uint32_t* Bc = Bs + (s & 1) * 2048;
#pragma unroll
            for (int k16 = 0; k16 < 2; k16++) {
                uint32_t af[4][4];
#pragma unroll
                for (int i = 0; i < 4; i++) {
                    uint32_t u = (uint32_t)(((k16 * 8 + wm * 4 + i) * 32 + lane) * 4);
                    uint4 t4 = *(const uint4*)(Ac + u);
                    af[i][0] = t4.x; af[i][1] = t4.y; af[i][2] = t4.z; af[i][3] = t4.w;
                }
                uint32_t bf[4][2];
#pragma unroll
                for (int j = 0; j < 4; j++) {
                    uint32_t v = (uint32_t)(((k16 * 16 + wn * 4 + j) * 32 + lane) * 2);
                    uint2 t2 = *(const uint2*)(Bc + v);
                    bf[j][0] = t2.x; bf[j][1] = t2.y;
                }
#pragma unroll
                for (int i = 0; i < 4; i++)
#pragma unroll
                    for (int j = 0; j < 4; j++)
                        mma16816(acc[i][j], af[i], bf[j]);
            }
        }
        if (s < 19) stsStage((s + 1) & 1);
    }

    // ---- fused epilogue: elu(h) staged in smem [128][132], LN per row ----
    __syncthreads();
    float* ht = (float*)smu;
    {
        int col = wn * 32 + 2 * (lane & 3);
#pragma unroll
        for (int i = 0; i < 4; i++) {
            int r0 = wm * 64 + i * 16 + (lane >> 2);
#pragma unroll
            for (int j = 0; j < 4; j++) {
                float e0 = acc[i][j][0], e1 = acc[i][j][1];
                float e2 = acc[i][j][2], e3 = acc[i][j][3];
                ht[r0 * 132 + col + j * 8]           = e0 > 0.f ? e0 : expm1f(e0);
                ht[r0 * 132 + col + j * 8 + 1]       = e1 > 0.f ? e1 : expm1f(e1);
                ht[(r0 + 8) * 132 + col + j * 8]     = e2 > 0.f ? e2 : expm1f(e2);
                ht[(r0 + 8) * 132 + col + j * 8 + 1] = e3 > 0.f ? e3 : expm1f(e3);
            }
        }
    }
    __syncthreads();

    const float4 gv = *(const float4*)(gamma + lane * 4);
    const float4 bv = *(const float4*)(beta + lane * 4);
    __half* xfoh = (__half*)xfo;

#pragma unroll
    for (int r = 0; r < 16; r++) {
        int row = wid * 16 + r;
        int grow = m0 + row;
        float4 h4 = *(const float4*)(ht + row * 132 + lane * 4);
        float4 x4 = *(const float4*)(x + (size_t)grow * HIDD + lane * 4);
        float4 y;
        y.x = x4.x + h4.x; y.y = x4.y + h4.y;
        y.z = x4.z + h4.z; y.w = x4.w + h4.w;

        float sum = y.x + y.y + y.z + y.w;
        float sq  = y.x * y.x + y.y * y.y + y.z * y.z + y.w * y.w;
#pragma unroll
        for (int off = 16; off; off >>= 1) {
            sum += __shfl_xor_sync(0xffffffffu, sum, off);
            sq  += __shfl_xor_sync(0xffffffffu, sq, off);
        }
        float mu = sum * (1.f / 128.f);
        float var = sq * (1.f / 128.f) - mu * mu;
        float inv = rsqrtf(var + 1e-5f);

        float4 o;
        o.x = (y.x - mu) * inv * gv.x + bv.x;
        o.y = (y.y - mu) * inv * gv.y + bv.y;
        o.z = (y.z - mu) * inv * gv.z + bv.z;
        o.w = (y.w - mu) * inv * gv.w + bv.w;

        if (grow < NN)
            *(float4*)(out + (size_t)grow * HIDD + lane * 4) = o;

        if (xfo) {
            float vals[4] = {o.x, o.y, o.z, o.w};
            __half* dst = xfoh + (size_t)slab * 16384;
#pragma unroll
            for (int j = 0; j < 4; j++) {
                int k = lane * 4 + j;
                dst[(size_t)(k >> 5) * 4096 + aidx_h(row, k & 31)] = __float2half_rn(vals[j]);
            }
        }
    }
}

// ---------------- Weight prep (fp16 frag order) ----------------
__global__ void prep_qkv_w(const float* __restrict__ Wq, const float* __restrict__ Wk,
                           const float* __restrict__ Wv, uint32_t* __restrict__ dst)
{
    int t = blockIdx.x * 256 + threadIdx.x;          // 3L*3*65536
    int l = t / 196608;
    int r = t - l * 196608;
    int w = r >> 16;
    int e = r & 65535;
    int k = e >> 9, n = e & 511;
    const float* W = (w == 0 ? Wq : (w == 1 ? Wk : Wv)) + (size_t)l * 65536;
    float val = W[k * 512 + n];
    __half* dh = (__half*)dst;
    dh[(size_t)((l * 3 + w) * 16 + (n >> 7) * 4 + (k >> 5)) * 4096 +
       bidx_h(k & 31, n & 127)] = __float2half_rn(val);
}

__global__ void prep_proj_w(const float* __restrict__ Wproj, uint32_t* __restrict__ dst)
{
    int t = blockIdx.x * 256 + threadIdx.x;
    int l = t >> 16, e = t & 65535;
    int k = e >> 7, n = e & 127;
    float val = Wproj[(size_t)l * 65536 + k * 128 + n];
    __half* dh = (__half*)dst;
    dh[(size_t)(l * 16 + (k >> 5)) * 4096 + bidx_h(k & 31, n)] = __float2half_rn(val);
}

// Wf = Wskip @ Wproj — coalesced: block = (i-row, layer), 512 thr = 4 k-quarters x 128 j
__global__ __launch_bounds__(512) void wf_k(const float* __restrict__ Wskip,
                                            const float* __restrict__ Wproj,
                                            uint32_t* __restrict__ wff)
{
    __shared__ float red[4][128];
    int i = blockIdx.x, l = blockIdx.y;
    int j = threadIdx.x & 127, q = threadIdx.x >> 7;
    const float* ws = Wskip + (size_t)l * HIDD * HCC + (size_t)i * HCC + q * 128;
    const float* wp = Wproj + (size_t)l * HCC * HIDD + (size_t)(q * 128) * HIDD + j;
    float s0 = 0.f, s1 = 0.f, s2 = 0.f, s3 = 0.f;
#pragma unroll 8
    for (int k = 0; k < 128; k += 4) {
        s0 = fmaf(ws[k],     wp[(size_t)k * HIDD],       s0);
        s1 = fmaf(ws[k + 1], wp[(size_t)(k + 1) * HIDD], s1);
        s2 = fmaf(ws[k + 2], wp[(size_t)(k + 2) * HIDD], s2);
        s3 = fmaf(ws[k + 3], wp[(size_t)(k + 3) * HIDD], s3);
    }
    red[q][j] = (s0 + s1) + (s2 + s3);
    __syncthreads();
    if (q == 0) {
        float s = red[0][j] + red[1][j] + red[2][j] + red[3][j];
        __half* dh = (__half*)wff;
        dh[(size_t)(l * 4 + (i >> 5)) * 4096 + bidx_h(i & 31, j)] = __float2half_rn(s);
    }
}

__global__ void bf_k(const float* __restrict__ bskip, const float* __restrict__ Wproj,
                     const float* __restrict__ bproj, float* __restrict__ bf)
{
    int l = blockIdx.x, j = threadIdx.x;
    const float* bs = bskip + (size_t)l * HCC;
    const float* wp = Wproj + (size_t)l * HCC * HIDD + j;
    float s0 = 0.f, s1 = 0.f, s2 = 0.f, s3 = 0.f;
#pragma unroll 8
    for (int k = 0; k < HCC; k += 4) {
        s0 = fmaf(bs[k],     wp[(size_t)k * HIDD],       s0);
        s1 = fmaf(bs[k + 1], wp[(size_t)(k + 1) * HIDD], s1);
        s2 = fmaf(bs[k + 2], wp[(size_t)(k + 2) * HIDD], s2);
        s3 = fmaf(bs[k + 3], wp[(size_t)(k + 3) * HIDD], s3);
    }
    bf[l * HIDD + j] = bproj[(size_t)l * HIDD + j] + (s0 + s1) + (s2 + s3);
}

// x_in -> fp16 frag order (layer 0)
__global__ void init_xfrag_k(const float* __restrict__ x, uint32_t* __restrict__ xf)
{
    int t = blockIdx.x * 256 + threadIdx.x;
    int row = t >> 5, lane = t & 31;
    float4 v = *(const float4*)(x + (size_t)row * HIDD + lane * 4);
    int slab = row >> 7, m = row & 127;
    float vals[4] = {v.x, v.y, v.z, v.w};
    __half* xfh = (__half*)xf;
#pragma unroll
    for (int j = 0; j < 4; j++) {
        int k = lane * 4 + j;
        xfh[(size_t)slab * 16384 + (size_t)(k >> 5) * 4096 + aidx_h(m, k & 31)] =
            __float2half_rn(vals[j]);
    }
}

// ---------------- CSR build ----------------
__global__ void hist_k(const int* __restrict__ dst, int* __restrict__ deg) {
    int e = blockIdx.x * 256 + threadIdx.x;
    if (e < EE) atomicAdd(deg + dst[e], 1);
}

__global__ void scanA_k(const int* __restrict__ deg, int* __restrict__ off,
                        int* __restrict__ blk) {
    __shared__ int sh[256];
    int t = threadIdx.x;
    int idx = blockIdx.x * 256 + t;
    int val = (idx < NN) ? deg[idx] : 0;
    sh[t] = val;
    __syncthreads();
#pragma unroll
    for (int d = 1; d < 256; d <<= 1) {
        int add = (t >= d) ? sh[t - d] : 0;
        __syncthreads();
        sh[t] += add;
        __syncthreads();
    }
    if (idx < NN) off[idx] = sh[t] - val;
    if (t == 255) blk[blockIdx.x] = sh[255];
}

__global__ void scanB_k(int* __restrict__ blk) {
    __shared__ int sh[256];
    int t = threadIdx.x;
    int val = (t < 196) ? blk[t] : 0;
    sh[t] = val;
    __syncthreads();
#pragma unroll
    for (int d = 1; d < 256; d <<= 1) {
        int add = (t >= d) ? sh[t - d] : 0;
        __syncthreads();
        sh[t] += add;
        __syncthreads();
    }
    if (t < 196) blk[t] = sh[t] - val;
}

__global__ void scanC_k(int* __restrict__ off, const int* __restrict__ blk,
                        int* __restrict__ cur) {
    int idx = blockIdx.x * 256 + threadIdx.x;
    if (idx < NN) {
        int o = off[idx] + blk[blockIdx.x];
        off[idx] = o;
        cur[idx] = o;
    }
    if (idx == 0) off[NN] = EE;
}

__global__ void scatter_k(const int* __restrict__ src, const int* __restrict__ dst,
                          const float* __restrict__ ea, int* __restrict__ cur,
                          int* __restrict__ srcs, float* __restrict__ eas) {
    int e = blockIdx.x * 256 + threadIdx.x;
    if (e < EE) {
        int p = atomicAdd(cur + dst[e], 1);
        srcs[p] = src[e];
        eas[p] = ea[e];
    }
}

// ---------------- Node-centric fused attention (writes fp16 frag agg) ----------------
__global__ __launch_bounds__(256) void attn_node_k(
    const __nv_bfloat16* __restrict__ q, const __nv_bfloat16* __restrict__ k,
    const float* __restrict__ v, const int* __restrict__ off,
    const int* __restrict__ srcs, const float* __restrict__ eas,
    const float* __restrict__ We, uint32_t* __restrict__ aggf)
{
    int wg = blockIdx.x * 8 + (threadIdx.x >> 5);
    int lane = threadIdx.x & 31;
    int d = wg >> 2, h = wg & 3;

    int beg = __ldg(off + d), end = __ldg(off + d + 1);

    uint2 qraw = *(const uint2*)(q + (size_t)d * HCC + h * CCC + lane * 4);
    float2 q01 = __bfloat1622float2(*(__nv_bfloat162*)&qraw.x);
    float2 q23 = __bfloat1622float2(*(__nv_bfloat162*)&qraw.y);
    const float4 wv = *(const float4*)(We + h * CCC + lane * 4);

    float a0 = 0.f, a1 = 0.f, a2 = 0.f, a3 = 0.f, den = 0.f;

    for (int i = beg; i < end; i++) {
        int sN = __ldg(srcs + i);
        float eav = __ldg(eas + i);

        uint2 kraw = *(const uint2*)(k + (size_t)sN * HCC + h * CCC + lane * 4);
        float2 k01 = __bfloat1622float2(*(__nv_bfloat162*)&kraw.x);
        float2 k23 = __bfloat1622float2(*(__nv_bfloat162*)&kraw.y);

        float s = q01.x * fmaf(eav, wv.x, k01.x) + q01.y * fmaf(eav, wv.y, k01.y)
                + q23.x * fmaf(eav, wv.z, k23.x) + q23.y * fmaf(eav, wv.w, k23.y);
#pragma unroll
        for (int o = 16; o; o >>= 1) s += __shfl_xor_sync(0xffffffffu, s, o);

        float pv = expf(s * 0.08838834764831845f);
        den += pv;

        const float4 vv = *(const float4*)(v + (size_t)sN * HCC + h * CCC + lane * 4);
        a0 = fmaf(fmaf(eav, wv.x, vv.x), pv, a0);
        a1 = fmaf(fmaf(eav, wv.y, vv.y), pv, a1);
        a2 = fmaf(fmaf(eav, wv.z, vv.z), pv, a2);
        a3 = fmaf(fmaf(eav, wv.w, vv.w), pv, a3);
    }

    float inv = 1.f / (den + 1e-16f);
    float vals[4] = {a0 * inv, a1 * inv, a2 * inv, a3 * inv};

    int slab = d >> 7, m = d & 127;
    __half* base = (__half*)aggf + (size_t)slab * 65536;
#pragma unroll
    for (int j = 0; j < 4; j++) {
        int kk = h * 128 + lane * 4 + j;
        base[(size_t)(kk >> 5) * 4096 + aidx_h(m, kk & 31)] = __float2half_rn(vals[j]);
    }
}

// ---------------- host ----------------
extern "C" void kernel_launch(void* const* d_in, const int* in_sizes, int n_in,
                              void* d_out, int out_size)
{
    const float* x_in  = (const float*)d_in[0];
    const int*   ei    = (const int*)d_in[1];
    const float* ea    = (const float*)d_in[2];
    const float* Wq    = (const float*)d_in[3];
    const float* bq    = (const float*)d_in[4];
    const float* Wk    = (const float*)d_in[5];
    const float* bk    = (const float*)d_in[6];
    const float* Wv    = (const float*)d_in[7];
    const float* bv    = (const float*)d_in[8];
    const float* We    = (const float*)d_in[9];
    const float* Wskip = (const float*)d_in[10];
    const float* bskip = (const float*)d_in[11];
    const float* Wproj = (const float*)d_in[12];
    const float* bproj = (const float*)d_in[13];
    const float* gamma = (const float*)d_in[14];
    const float* beta  = (const float*)d_in[15];

    __nv_bfloat16 *qb, *kb;
    float *v, *xbuf, *bfv, *eas;
    uint32_t *xf, *aggf, *wqkvf, *wpf, *wff;
    int *deg, *off, *cur, *blk, *srcs;
    cudaGetSymbolAddress((void**)&qb,    g_qb);
    cudaGetSymbolAddress((void**)&kb,    g_kb);
    cudaGetSymbolAddress((void**)&v,     g_v);
    cudaGetSymbolAddress((void**)&xbuf,  g_x);
    cudaGetSymbolAddress((void**)&xf,    g_xf);
    cudaGetSymbolAddress((void**)&aggf,  g_aggf);
    cudaGetSymbolAddress((void**)&wqkvf, g_wqkvf);
    cudaGetSymbolAddress((void**)&wpf,   g_wpf);
    cudaGetSymbolAddress((void**)&wff,   g_wff);
    cudaGetSymbolAddress((void**)&bfv,   g_bf);
    cudaGetSymbolAddress((void**)&deg,   g_deg);
    cudaGetSymbolAddress((void**)&off,   g_off);
    cudaGetSymbolAddress((void**)&cur,   g_cur);
    cudaGetSymbolAddress((void**)&blk,   g_blk);
    cudaGetSymbolAddress((void**)&srcs,  g_srcs);
    cudaGetSymbolAddress((void**)&eas,   g_eas);

    cudaFuncSetAttribute(gemm_qkv_mma, cudaFuncAttributeMaxDynamicSharedMemorySize,
                         QKV_SMEM_B);
    cudaFuncSetAttribute(gemm_proj_ln, cudaFuncAttributeMaxDynamicSharedMemorySize,
                         PRJ_SMEM_B);

    const int* src = ei;
    const int* dst = ei + EE;

    cudaMemcpyAsync(xbuf, x_in, (size_t)NN * HIDD * sizeof(float),
                    cudaMemcpyDeviceToDevice);
    init_xfrag_k<<<(NN * 32) / 256, 256>>>(x_in, xf);

    prep_qkv_w<<<2304, 256>>>(Wq, Wk, Wv, wqkvf);
    prep_proj_w<<<768, 256>>>(Wproj, wpf);
    wf_k<<<dim3(128, 3), 512>>>(Wskip, Wproj, wff);
    bf_k<<<3, 128>>>(bskip, Wproj, bproj, bfv);

    cudaMemsetAsync(deg, 0, NN * sizeof(int));
    hist_k<<<(EE + 255) / 256, 256>>>(dst, deg);
    scanA_k<<<(NN + 255) / 256, 256>>>(deg, off, blk);
    scanB_k<<<1, 256>>>(blk);
    scanC_k<<<(NN + 255) / 256, 256>>>(off, blk, cur);
    scatter_k<<<(EE + 255) / 256, 256>>>(src, dst, ea, cur, srcs, eas);

    const int attnBlocks = (NN * HH) / 8;

    for (int l = 0; l < LLL; l++) {
        float* xo = (l == LLL - 1) ? (float*)d_out : xbuf;
        uint32_t* xfo = (l == LLL - 1) ? nullptr : xf;

        gemm_qkv_mma<<<dim3(4, NSLAB), 256, QKV_SMEM_B>>>(
            xf, wqkvf + (size_t)l * 3 * 32768,
            bq + l * HCC, bk + l * HCC, bv + l * HCC, qb, kb, v);

        attn_node_k<<<attnBlocks, 256>>>(qb, kb, v, off, srcs, eas,
                                         We + l * HCC, aggf);

        gemm_proj_ln<<<NSLAB, 256, PRJ_SMEM_B>>>(
            aggf, wpf + (size_t)l * 32768,
            xf, wff + (size_t)l * 8192,
            bfv + l * HIDD,
            xbuf, gamma + l * HIDD, beta + l * HIDD,
            xo, xfo);
    }
}

// round 12
// speedup vs baseline: 3.6902x; 1.0156x over previous
#include <cuda_runtime.h>
#include <cuda_bf16.h>
#include <cuda_fp16.h>
#include <math.h>
#include <stdint.h>

#define NN 50000
#define NPAD 50048          // 391 * 128
#define NSLAB 391
#define EE 100000
#define HIDD 128
#define HH 4
#define CCC 128
#define HCC 512
#define LLL 3

// ---------------- scratch ----------------
__device__ __nv_bfloat16 g_qb[(size_t)NPAD * HCC];
__device__ __nv_bfloat16 g_kb[(size_t)NPAD * HCC];
__device__ __half g_v[(size_t)NPAD * HCC];
__device__ float g_x[(size_t)NPAD * HIDD];
// fragment-order fp16 buffers (uint32 views; 1 chunk = 2048 u32 = 4096 halves)
__device__ uint32_t g_xf[(size_t)NSLAB * 8192];
__device__ uint32_t g_aggf[(size_t)NSLAB * 32768];
__device__ uint32_t g_wqkvf[(size_t)LLL * 3 * 32768];
__device__ uint32_t g_wpf[(size_t)LLL * 32768];
__device__ uint32_t g_wff[(size_t)LLL * 8192];
__device__ float g_bf[(size_t)LLL * HIDD];

// CSR
__device__ int   g_deg[NN];
__device__ int   g_off[NN + 1];
__device__ int   g_cur[NN];
__device__ int   g_blk[256];
__device__ int   g_srcs[EE];
__device__ float g_eas[EE];

__device__ __forceinline__ uint32_t cvta_sm(const void* p) {
    uint32_t a;
    asm("{ .reg .u64 t; cvta.to.shared.u64 t, %1; cvt.u32.u64 %0, t; }" : "=r"(a) : "l"(p));
    return a;
}
__device__ __forceinline__ void cp16(uint32_t smem, const void* g) {
    asm volatile("cp.async.cg.shared.global [%0], [%1], 16;" :: "r"(smem), "l"(g));
}
#define CP_COMMIT() asm volatile("cp.async.commit_group;" ::: "memory")
#define CP_WAIT0()  asm volatile("cp.async.wait_group 0;" ::: "memory")

// fp16 mma m16n8k16: D += A*B (fp32 acc in-place)
__device__ __forceinline__ void mma16816(float* d, const uint32_t* a, const uint32_t* b) {
    asm volatile("mma.sync.aligned.m16n8k16.row.col.f32.f16.f16.f32 "
        "{%0,%1,%2,%3}, {%4,%5,%6,%7}, {%8,%9}, {%0,%1,%2,%3};"
        : "+f"(d[0]), "+f"(d[1]), "+f"(d[2]), "+f"(d[3])
        : "r"(a[0]), "r"(a[1]), "r"(a[2]), "r"(a[3]), "r"(b[0]), "r"(b[1]));
}

// half-index within one A chunk (128m x 32k fp16, 4096 halves)
__device__ __forceinline__ int aidx_h(int m, int kk) {
    int m_tile = m >> 4, r = m & 15;
    int k16 = kk >> 4, kw = kk & 15;
    int lane = (r & 7) * 4 + ((kw & 7) >> 1);
    int reg = ((kw >> 3) << 1) + (r >> 3);
    int u = ((k16 * 8 + m_tile) * 32 + lane) * 4 + reg;
    return u * 2 + (kw & 1);
}
// half-index within one B chunk (32k x 128n fp16, 4096 halves)
__device__ __forceinline__ int bidx_h(int kk, int n) {
    int k16 = kk >> 4, kw = kk & 15;
    int n_tile = n >> 3, nn = n & 7;
    int tg = (kw & 7) >> 1;
    int lane = nn * 4 + tg;
    int reg = kw >> 3;
    int u = ((k16 * 16 + n_tile) * 32 + lane) * 2 + reg;
    return u * 2 + (kw & 1);
}

#define QKV_SMEM_B ((8192 + 2*2048) * 4)     // 49152
#define PRJ_SMEM_B (128 * 132 * 4)           // 67584

// ---------------- Fused QKV GEMM (fp16 mma, cp.async, N-split x4) ----------------
__global__ __launch_bounds__(256, 2) void gemm_qkv_mma(
    const uint32_t* __restrict__ xf, const uint32_t* __restrict__ wf,
    const float* __restrict__ b0, const float* __restrict__ b1, const float* __restrict__ b2,
    __nv_bfloat16* __restrict__ oq, __nv_bfloat16* __restrict__ ok,
    __half* __restrict__ ov)
{
    extern __shared__ uint32_t smu[];
    uint32_t* As = smu;              // 4 chunks x 2048 u32
    uint32_t* Bs = smu + 8192;       // 2 x 2048 u32
    const uint32_t As_a = cvta_sm(As);
    const uint32_t Bs_a = cvta_sm(Bs);

    const int tid = threadIdx.x;
    const int wid = tid >> 5;
    const int lane = tid & 31;
    const int m0 = blockIdx.y * 128;
    const int wm = wid >> 2;
    const int wn = wid & 3;
    const int t0 = blockIdx.x * 3;

    const float* bp[3] = {b0, b1, b2};

    auto chunkPtr = [&](int s) {
        int tg = t0 + (s >> 2);
        return wf + (size_t)(tg >> 2) * 32768 + (size_t)(((tg & 3) * 4) + (s & 3)) * 2048;
    };
    auto cpB = [&](const uint32_t* chunk, int buf) {
        uint32_t base = Bs_a + buf * 2048 * 4;
#pragma unroll
        for (int g = 0; g < 2; g++) {
            int o = (g * 256 + tid) * 4;
            cp16(base + o * 4, chunk + o);
        }
    };

    // prologue: A slab + B stage 0 via cp.async
    {
        const uint32_t* asrc = xf + (size_t)blockIdx.y * 8192;
#pragma unroll
        for (int g = 0; g < 8; g++) {
            int o = (g * 256 + tid) * 4;
            cp16(As_a + o * 4, asrc + o);
        }
    }
    cpB(chunkPtr(0), 0);
    CP_COMMIT();

    float acc[4][4][4];
    auto initAcc = [&](int tg) {
        const float* bias = bp[tg >> 2] + (tg & 3) * 128 + wn * 32;
#pragma unroll
        for (int j = 0; j < 4; j++) {
            float bv0 = __ldg(bias + j * 8 + 2 * (lane & 3));
            float bv1 = __ldg(bias + j * 8 + 2 * (lane & 3) + 1);
#pragma unroll
            for (int i = 0; i < 4; i++) {
                acc[i][j][0] = bv0; acc[i][j][1] = bv1;
                acc[i][j][2] = bv0; acc[i][j][3] = bv1;
            }
        }
    };
    auto epilogue = [&](int tg) {
        const int w = tg >> 2;
        const int col = (tg & 3) * 128 + wn * 32 + 2 * (lane & 3);
        if (w < 2) {
            __nv_bfloat16* out = (w == 0) ? oq : ok;
#pragma unroll
            for (int i = 0; i < 4; i++) {
                int row = m0 + wm * 64 + i * 16 + (lane >> 2);
#pragma unroll
                for (int j = 0; j < 4; j++) {
                    *(__nv_bfloat162*)(out + (size_t)row * HCC + col + j * 8) =
                        __floats2bfloat162_rn(acc[i][j][0], acc[i][j][1]);
                    *(__nv_bfloat162*)(out + (size_t)(row + 8) * HCC + col + j * 8) =
                        __floats2bfloat162_rn(acc[i][j][2], acc[i][j][3]);
                }
            }
        } else {
#pragma unroll
            for (int i = 0; i < 4; i++) {
                int row = m0 + wm * 64 + i * 16 + (lane >> 2);
#pragma unroll
                for (int j = 0; j < 4; j++) {
                    *(__half2*)(ov + (size_t)row * HCC + col + j * 8) =
                        __floats2half2_rn(acc[i][j][0], acc[i][j][1]);
                    *(__half2*)(ov + (size_t)(row + 8) * HCC + col + j * 8) =
                        __floats2half2_rn(acc[i][j][2], acc[i][j][3]);
                }
            }
        }
    };
    auto mmaChunk = [&](int buf, int kc) {
        const uint32_t* B = Bs + buf * 2048;
        const uint32_t* Ac = As + kc * 2048;
#pragma unroll
        for (int k16 = 0; k16 < 2; k16++) {
            uint32_t af[4][4];
#pragma unroll
            for (int i = 0; i < 4; i++) {
                uint32_t u = (uint32_t)(((k16 * 8 + wm * 4 + i) * 32 + lane) * 4);
                uint4 t4 = *(const uint4*)(Ac + u);
                af[i][0] = t4.x; af[i][1] = t4.y; af[i][2] = t4.z; af[i][3] = t4.w;
            }
            uint32_t bf[4][2];
#pragma unroll
            for (int j = 0; j < 4; j++) {
                uint32_t v = (uint32_t)(((k16 * 16 + wn * 4 + j) * 32 + lane) * 2);
                uint2 t2 = *(const uint2*)(B + v);
                bf[j][0] = t2.x; bf[j][1] = t2.y;
            }
#pragma unroll
            for (int i = 0; i < 4; i++)
#pragma unroll
                for (int j = 0; j < 4; j++)
                    mma16816(acc[i][j], af[i], bf[j]);
        }
    };

    initAcc(t0);
    CP_WAIT0();
    __syncthreads();

    for (int s = 0; s < 12; s++) {
        int tg = t0 + (s >> 2), kc = s & 3;
        if (s < 11) { cpB(chunkPtr(s + 1), (s + 1) & 1); CP_COMMIT(); }
        mmaChunk(s & 1, kc);
        if (kc == 3) {
            epilogue(tg);
            if ((s >> 2) < 2) initAcc(tg + 1);
        }
        if (s < 11) { CP_WAIT0(); }
        __syncthreads();
    }
}

// ---------------- Proj GEMM + ELU + residual + LayerNorm (fp16 mma, cp.async) ----------------
__global__ __launch_bounds__(256, 2) void gemm_proj_ln(
    const uint32_t* __restrict__ aggf, const uint32_t* __restrict__ wpf,
    const uint32_t* __restrict__ xf, const uint32_t* __restrict__ wff,
    const float* __restrict__ bias,
    const float* __restrict__ x, const float* __restrict__ gamma,
    const float* __restrict__ beta,
    float* __restrict__ out, uint32_t* __restrict__ xfo)
{
    extern __shared__ uint32_t smu[];
    uint32_t* As = smu;              // 2 x 2048
    uint32_t* Bs = smu + 4096;       // 2 x 2048
    const uint32_t As_a = cvta_sm(As);
    const uint32_t Bs_a = cvta_sm(Bs);

    const int tid = threadIdx.x;
    const int wid = tid >> 5;
    const int lane = tid & 31;
    const int slab = blockIdx.x;
    const int m0 = slab * 128;
    const int wm = wid >> 2;
    const int wn = wid & 3;

    auto cpStage = [&](int s1, int buf) {
        const uint32_t *Asrc, *Bsrc;
        if (s1 < 16) {
            Asrc = aggf + (size_t)slab * 32768 + (size_t)s1 * 2048;
            Bsrc = wpf + (size_t)s1 * 2048;
        } else {
            Asrc = xf + (size_t)slab * 8192 + (size_t)(s1 - 16) * 2048;
            Bsrc = wff + (size_t)(s1 - 16) * 2048;
        }
        uint32_t ab = As_a + buf * 2048 * 4;
        uint32_t bb = Bs_a + buf * 2048 * 4;
#pragma unroll
        for (int g = 0; g < 2; g++) {
            int o = (g * 256 + tid) * 4;
            cp16(ab + o * 4, Asrc + o);
            cp16(bb + o * 4, Bsrc + o);
        }
    };

    float acc[4][4][4];
    {
        const float* bp = bias + wn * 32;
#pragma unroll
        for (int j = 0; j < 4; j++) {
            float bv0 = __ldg(bp + j * 8 + 2 * (lane & 3));
            float bv1 = __ldg(bp + j * 8 + 2 * (lane & 3) + 1);
#pragma unroll
            for (int i = 0; i < 4; i++) {
                acc[i][j][0] = bv0; acc[i][j][1] = bv1;
                acc[i][j][2] = bv0; acc[i][j][3] = bv1;
            }
        }
    }

    cpStage(0, 0);
    CP_COMMIT();
    CP_WAIT0();
    __syncthreads();

    for (int s = 0; s < 20; s++) {
        if (s < 19) { cpStage(s + 1, (s + 1) & 1); CP_COMMIT(); }
        {
            const uint32_t* Ac = As + (s & 1) * 2048;
            const uint32_t* Bc = Bs + (s & 1) * 2048;
#pragma unroll
            for (int k16 = 0; k16 < 2; k16++) {
                uint32_t af[4][4];
#pragma unroll
                for (int i = 0; i < 4; i++) {
                    uint32_t u = (uint32_t)(((k16 * 8 + wm * 4 + i) * 32 + lane) * 4);
                    uint4 t4 = *(const uint4*)(Ac + u);
                    af[i][0] = t4.x; af[i][1] = t4.y; af[i][2] = t4.z; af[i][3] = t4.w;
                }
                uint32_t bf[4][2];
#pragma unroll
                for (int j = 0; j < 4; j++) {
                    uint32_t v = (uint32_t)(((k16 * 16 + wn * 4 + j) * 32 + lane) * 2);
                    uint2 t2 = *(const uint2*)(Bc + v);
                    bf[j][0] = t2.x; bf[j][1] = t2.y;
                }
#pragma unroll
                for (int i = 0; i < 4; i++)
#pragma unroll
                    for (int j = 0; j < 4; j++)
                        mma16816(acc[i][j], af[i], bf[j]);
            }
        }
        if (s < 19) { CP_WAIT0(); }
        __syncthreads();
    }

    // ---- fused epilogue: elu(h) staged in smem [128][132], LN per row ----
    float* ht = (float*)smu;
    {
        int col = wn * 32 + 2 * (lane & 3);
#pragma unroll
        for (int i = 0; i < 4; i++) {
            int r0 = wm * 64 + i * 16 + (lane >> 2);
#pragma unroll
            for (int j = 0; j < 4; j++) {
                float e0 = acc[i][j][0], e1 = acc[i][j][1];
                float e2 = acc[i][j][2], e3 = acc[i][j][3];
                ht[r0 * 132 + col + j * 8]           = e0 > 0.f ? e0 : expm1f(e0);
                ht[r0 * 132 + col + j * 8 + 1]       = e1 > 0.f ? e1 : expm1f(e1);
                ht[(r0 + 8) * 132 + col + j * 8]     = e2 > 0.f ? e2 : expm1f(e2);
                ht[(r0 + 8) * 132 + col + j * 8 + 1] = e3 > 0.f ? e3 : expm1f(e3);
            }
        }
    }
    __syncthreads();

    const float4 gv = *(const float4*)(gamma + lane * 4);
    const float4 bv = *(const float4*)(beta + lane * 4);
    __half* xfoh = (__half*)xfo;

#pragma unroll
    for (int r = 0; r < 16; r++) {
        int row = wid * 16 + r;
        int grow = m0 + row;
        float4 h4 = *(const float4*)(ht + row * 132 + lane * 4);
        float4 x4 = *(const float4*)(x + (size_t)grow * HIDD + lane * 4);
        float4 y;
        y.x = x4.x + h4.x; y.y = x4.y + h4.y;
        y.z = x4.z + h4.z; y.w = x4.w + h4.w;

        float sum = y.x + y.y + y.z + y.w;
        float sq  = y.x * y.x + y.y * y.y + y.z * y.z + y.w * y.w;
#pragma unroll
        for (int off = 16; off; off >>= 1) {
            sum += __shfl_xor_sync(0xffffffffu, sum, off);
            sq  += __shfl_xor_sync(0xffffffffu, sq, off);
        }
        float mu = sum * (1.f / 128.f);
        float var = sq * (1.f / 128.f) - mu * mu;
        float inv = rsqrtf(var + 1e-5f);

        float4 o;
        o.x = (y.x - mu) * inv * gv.x + bv.x;
        o.y = (y.y - mu) * inv * gv.y + bv.y;
        o.z = (y.z - mu) * inv * gv.z + bv.z;
        o.w = (y.w - mu) * inv * gv.w + bv.w;

        if (grow < NN)
            *(float4*)(out + (size_t)grow * HIDD + lane * 4) = o;

        if (xfo) {
            float vals[4] = {o.x, o.y, o.z, o.w};
            __half* dst = xfoh + (size_t)slab * 16384;
#pragma unroll
            for (int j = 0; j < 4; j++) {
                int k = lane * 4 + j;
                dst[(size_t)(k >> 5) * 4096 + aidx_h(row, k & 31)] = __float2half_rn(vals[j]);
            }
        }
    }
}

// ---------------- Weight prep (fp16 frag order) ----------------
__global__ void prep_qkv_w(const float* __restrict__ Wq, const float* __restrict__ Wk,
                           const float* __restrict__ Wv, uint32_t* __restrict__ dst)
{
    int t = blockIdx.x * 256 + threadIdx.x;
    int l = t / 196608;
    int r = t - l * 196608;
    int w = r >> 16;
    int e = r & 65535;
    int k = e >> 9, n = e & 511;
    const float* W = (w == 0 ? Wq : (w == 1 ? Wk : Wv)) + (size_t)l * 65536;
    float val = W[k * 512 + n];
    __half* dh = (__half*)dst;
    dh[(size_t)((l * 3 + w) * 16 + (n >> 7) * 4 + (k >> 5)) * 4096 +
       bidx_h(k & 31, n & 127)] = __float2half_rn(val);
}

__global__ void prep_proj_w(const float* __restrict__ Wproj, uint32_t* __restrict__ dst)
{
    int t = blockIdx.x * 256 + threadIdx.x;
    int l = t >> 16, e = t & 65535;
    int k = e >> 7, n = e & 127;
    float val = Wproj[(size_t)l * 65536 + k * 128 + n];
    __half* dh = (__half*)dst;
    dh[(size_t)(l * 16 + (k >> 5)) * 4096 + bidx_h(k & 31, n)] = __float2half_rn(val);
}

// Wf = Wskip @ Wproj — coalesced
__global__ __launch_bounds__(512) void wf_k(const float* __restrict__ Wskip,
                                            const float* __restrict__ Wproj,
                                            uint32_t* __restrict__ wff)
{
    __shared__ float red[4][128];
    int i = blockIdx.x, l = blockIdx.y;
    int j = threadIdx.x & 127, q = threadIdx.x >> 7;
    const float* ws = Wskip + (size_t)l * HIDD * HCC + (size_t)i * HCC + q * 128;
    const float* wp = Wproj + (size_t)l * HCC * HIDD + (size_t)(q * 128) * HIDD + j;
    float s0 = 0.f, s1 = 0.f, s2 = 0.f, s3 = 0.f;
#pragma unroll 8
    for (int k = 0; k < 128; k += 4) {
        s0 = fmaf(ws[k],     wp[(size_t)k * HIDD],       s0);
        s1 = fmaf(ws[k + 1], wp[(size_t)(k + 1) * HIDD], s1);
        s2 = fmaf(ws[k + 2], wp[(size_t)(k + 2) * HIDD], s2);
        s3 = fmaf(ws[k + 3], wp[(size_t)(k + 3) * HIDD], s3);
    }
    red[q][j] = (s0 + s1) + (s2 + s3);
    __syncthreads();
    if (q == 0) {
        float s = red[0][j] + red[1][j] + red[2][j] + red[3][j];
        __half* dh = (__half*)wff;
        dh[(size_t)(l * 4 + (i >> 5)) * 4096 + bidx_h(i & 31, j)] = __float2half_rn(s);
    }
}

__global__ void bf_k(const float* __restrict__ bskip, const float* __restrict__ Wproj,
                     const float* __restrict__ bproj, float* __restrict__ bf)
{
    int l = blockIdx.x, j = threadIdx.x;
    const float* bs = bskip + (size_t)l * HCC;
    const float* wp = Wproj + (size_t)l * HCC * HIDD + j;
    float s0 = 0.f, s1 = 0.f, s2 = 0.f, s3 = 0.f;
#pragma unroll 8
    for (int k = 0; k < HCC; k += 4) {
        s0 = fmaf(bs[k],     wp[(size_t)k * HIDD],       s0);
        s1 = fmaf(bs[k + 1], wp[(size_t)(k + 1) * HIDD], s1);
        s2 = fmaf(bs[k + 2], wp[(size_t)(k + 2) * HIDD], s2);
        s3 = fmaf(bs[k + 3], wp[(size_t)(k + 3) * HIDD], s3);
    }
    bf[l * HIDD + j] = bproj[(size_t)l * HIDD + j] + (s0 + s1) + (s2 + s3);
}

// x_in -> fp16 frag order (layer 0)
__global__ void init_xfrag_k(const float* __restrict__ x, uint32_t* __restrict__ xf)
{
    int t = blockIdx.x * 256 + threadIdx.x;
    int row = t >> 5, lane = t & 31;
    float4 v = *(const float4*)(x + (size_t)row * HIDD + lane * 4);
    int slab = row >> 7, m = row & 127;
    float vals[4] = {v.x, v.y, v.z, v.w};
    __half* xfh = (__half*)xf;
#pragma unroll
    for (int j = 0; j < 4; j++) {
        int k = lane * 4 + j;
        xfh[(size_t)slab * 16384 + (size_t)(k >> 5) * 4096 + aidx_h(m, k & 31)] =
            __float2half_rn(vals[j]);
    }
}

// ---------------- CSR build ----------------
__global__ void hist_k(const int* __restrict__ dst, int* __restrict__ deg) {
    int e = blockIdx.x * 256 + threadIdx.x;
    if (e < EE) atomicAdd(deg + dst[e], 1);
}

__global__ void scanA_k(const int* __restrict__ deg, int* __restrict__ off,
                        int* __restrict__ blk) {
    __shared__ int sh[256];
    int t = threadIdx.x;
    int idx = blockIdx.x * 256 + t;
    int val = (idx < NN) ? deg[idx] : 0;
    sh[t] = val;
    __syncthreads();
#pragma unroll
    for (int d = 1; d < 256; d <<= 1) {
        int add = (t >= d) ? sh[t - d] : 0;
        __syncthreads();
        sh[t] += add;
        __syncthreads();
    }
    if (idx < NN) off[idx] = sh[t] - val;
    if (t == 255) blk[blockIdx.x] = sh[255];
}

__global__ void scanB_k(int* __restrict__ blk) {
    __shared__ int sh[256];
    int t = threadIdx.x;
    int val = (t < 196) ? blk[t] : 0;
    sh[t] = val;
    __syncthreads();
#pragma unroll
    for (int d = 1; d < 256; d <<= 1) {
        int add = (t >= d) ? sh[t - d] : 0;
        __syncthreads();
        sh[t] += add;
        __syncthreads();
    }
    if (t < 196) blk[t] = sh[t] - val;
}

__global__ void scanC_k(int* __restrict__ off, const int* __restrict__ blk,
                        int* __restrict__ cur) {
    int idx = blockIdx.x * 256 + threadIdx.x;
    if (idx < NN) {
        int o = off[idx] + blk[blockIdx.x];
        off[idx] = o;
        cur[idx] = o;
    }
    if (idx == 0) off[NN] = EE;
}

__global__ void scatter_k(const int* __restrict__ src, const int* __restrict__ dst,
                          const float* __restrict__ ea, int* __restrict__ cur,
                          int* __restrict__ srcs, float* __restrict__ eas) {
    int e = blockIdx.x * 256 + threadIdx.x;
    if (e < EE) {
        int p = atomicAdd(cur + dst[e], 1);
        srcs[p] = src[e];
        eas[p] = ea[e];
    }
}

// ---------------- Node-centric fused attention (q,k bf16; v fp16) ----------------
__global__ __launch_bounds__(256) void attn_node_k(
    const __nv_bfloat16* __restrict__ q, const __nv_bfloat16* __restrict__ k,
    const __half* __restrict__ v, const int* __restrict__ off,
    const int* __restrict__ srcs, const float* __restrict__ eas,
    const float* __restrict__ We, uint32_t* __restrict__ aggf)
{
    int wg = blockIdx.x * 8 + (threadIdx.x >> 5);
    int lane = threadIdx.x & 31;
    int d = wg >> 2, h = wg & 3;

    int beg = __ldg(off + d), end = __ldg(off + d + 1);

    uint2 qraw = *(const uint2*)(q + (size_t)d * HCC + h * CCC + lane * 4);
    float2 q01 = __bfloat1622float2(*(__nv_bfloat162*)&qraw.x);
    float2 q23 = __bfloat1622float2(*(__nv_bfloat162*)&qraw.y);
    const float4 wv = *(const float4*)(We + h * CCC + lane * 4);

    float a0 = 0.f, a1 = 0.f, a2 = 0.f, a3 = 0.f, den = 0.f;

    for (int i = beg; i < end; i++) {
        int sN = __ldg(srcs + i);
        float eav = __ldg(eas + i);

        uint2 kraw = *(const uint2*)(k + (size_t)sN * HCC + h * CCC + lane * 4);
        float2 k01 = __bfloat1622float2(*(__nv_bfloat162*)&kraw.x);
        float2 k23 = __bfloat1622float2(*(__nv_bfloat162*)&kraw.y);

        float s = q01.x * fmaf(eav, wv.x, k01.x) + q01.y * fmaf(eav, wv.y, k01.y)
                + q23.x * fmaf(eav, wv.z, k23.x) + q23.y * fmaf(eav, wv.w, k23.y);
#pragma unroll
        for (int o = 16; o; o >>= 1) s += __shfl_xor_sync(0xffffffffu, s, o);

        float pv = expf(s * 0.08838834764831845f);
        den += pv;

        uint2 vraw = *(const uint2*)(v + (size_t)sN * HCC + h * CCC + lane * 4);
        float2 v01 = __half22float2(*(__half2*)&vraw.x);
        float2 v23 = __half22float2(*(__half2*)&vraw.y);
        a0 = fmaf(fmaf(eav, wv.x, v01.x), pv, a0);
        a1 = fmaf(fmaf(eav, wv.y, v01.y), pv, a1);
        a2 = fmaf(fmaf(eav, wv.z, v23.x), pv, a2);
        a3 = fmaf(fmaf(eav, wv.w, v23.y), pv, a3);
    }

    float inv = 1.f / (den + 1e-16f);
    float vals[4] = {a0 * inv, a1 * inv, a2 * inv, a3 * inv};

    int slab = d >> 7, m = d & 127;
    __half* base = (__half*)aggf + (size_t)slab * 65536;
#pragma unroll
    for (int j = 0; j < 4; j++) {
        int kk = h * 128 + lane * 4 + j;
        base[(size_t)(kk >> 5) * 4096 + aidx_h(m, kk & 31)] = __float2half_rn(vals[j]);
    }
}

// ---------------- host ----------------
extern "C" void kernel_launch(void* const* d_in, const int* in_sizes, int n_in,
                              void* d_out, int out_size)
{
    const float* x_in  = (const float*)d_in[0];
    const int*   ei    = (const int*)d_in[1];
    const float* ea    = (const float*)d_in[2];
    const float* Wq    = (const float*)d_in[3];
    const float* bq    = (const float*)d_in[4];
    const float* Wk    = (const float*)d_in[5];
    const float* bk    = (const float*)d_in[6];
    const float* Wv    = (const float*)d_in[7];
    const float* bv    = (const float*)d_in[8];
    const float* We    = (const float*)d_in[9];
    const float* Wskip = (const float*)d_in[10];
    const float* bskip = (const float*)d_in[11];
    const float* Wproj = (const float*)d_in[12];
    const float* bproj = (const float*)d_in[13];
    const float* gamma = (const float*)d_in[14];
    const float* beta  = (const float*)d_in[15];

    __nv_bfloat16 *qb, *kb;
    __half *v;
    float *xbuf, *bfv, *eas;
    uint32_t *xf, *aggf, *wqkvf, *wpf, *wff;
    int *deg, *off, *cur, *blk, *srcs;
    cudaGetSymbolAddress((void**)&qb,    g_qb);
    cudaGetSymbolAddress((void**)&kb,    g_kb);
    cudaGetSymbolAddress((void**)&v,     g_v);
    cudaGetSymbolAddress((void**)&xbuf,  g_x);
    cudaGetSymbolAddress((void**)&xf,    g_xf);
    cudaGetSymbolAddress((void**)&aggf,  g_aggf);
    cudaGetSymbolAddress((void**)&wqkvf, g_wqkvf);
    cudaGetSymbolAddress((void**)&wpf,   g_wpf);
    cudaGetSymbolAddress((void**)&wff,   g_wff);
    cudaGetSymbolAddress((void**)&bfv,   g_bf);
    cudaGetSymbolAddress((void**)&deg,   g_deg);
    cudaGetSymbolAddress((void**)&off,   g_off);
    cudaGetSymbolAddress((void**)&cur,   g_cur);
    cudaGetSymbolAddress((void**)&blk,   g_blk);
    cudaGetSymbolAddress((void**)&srcs,  g_srcs);
    cudaGetSymbolAddress((void**)&eas,   g_eas);

    cudaFuncSetAttribute(gemm_qkv_mma, cudaFuncAttributeMaxDynamicSharedMemorySize,
                         QKV_SMEM_B);
    cudaFuncSetAttribute(gemm_proj_ln, cudaFuncAttributeMaxDynamicSharedMemorySize,
                         PRJ_SMEM_B);

    const int* src = ei;
    const int* dst = ei + EE;

    cudaMemcpyAsync(xbuf, x_in, (size_t)NN * HIDD * sizeof(float),
                    cudaMemcpyDeviceToDevice);
    init_xfrag_k<<<(NN * 32) / 256, 256>>>(x_in, xf);

    prep_qkv_w<<<2304, 256>>>(Wq, Wk, Wv, wqkvf);
    prep_proj_w<<<768, 256>>>(Wproj, wpf);
    wf_k<<<dim3(128, 3), 512>>>(Wskip, Wproj, wff);
    bf_k<<<3, 128>>>(bskip, Wproj, bproj, bfv);

    cudaMemsetAsync(deg, 0, NN * sizeof(int));
    hist_k<<<(EE + 255) / 256, 256>>>(dst, deg);
    scanA_k<<<(NN + 255) / 256, 256>>>(deg, off, blk);
    scanB_k<<<1, 256>>>(blk);
    scanC_k<<<(NN + 255) / 256, 256>>>(off, blk, cur);
    scatter_k<<<(EE + 255) / 256, 256>>>(src, dst, ea, cur, srcs, eas);

    const int attnBlocks = (NN * HH) / 8;

    for (int l = 0; l < LLL; l++) {
        float* xo = (l == LLL - 1) ? (float*)d_out : xbuf;
        uint32_t* xfo = (l == LLL - 1) ? nullptr : xf;

        gemm_qkv_mma<<<dim3(4, NSLAB), 256, QKV_SMEM_B>>>(
            xf, wqkvf + (size_t)l * 3 * 32768,
            bq + l * HCC, bk + l * HCC, bv + l * HCC, qb, kb, v);

        attn_node_k<<<attnBlocks, 256>>>(qb, kb, v, off, srcs, eas,
                                         We + l * HCC, aggf);

        gemm_proj_ln<<<NSLAB, 256, PRJ_SMEM_B>>>(
            aggf, wpf + (size_t)l * 32768,
            xf, wff + (size_t)l * 8192,
            bfv + l * HIDD,
            xbuf, gamma + l * HIDD, beta + l * HIDD,
            xo, xfo);
    }
}

// round 13
// speedup vs baseline: 3.8106x; 1.0326x over previous
#include <cuda_runtime.h>
#include <cuda_bf16.h>
#include <cuda_fp16.h>
#include <math.h>
#include <stdint.h>

#define NN 50000
#define NPAD 50048          // 391 * 128
#define NSLAB 391
#define EE 100000
#define HIDD 128
#define HH 4
#define CCC 128
#define HCC 512
#define LLL 3

// ---------------- scratch ----------------
__device__ __nv_bfloat16 g_qb[(size_t)NPAD * HCC];
__device__ __nv_bfloat16 g_kb[(size_t)NPAD * HCC];
__device__ __half g_v[(size_t)NPAD * HCC];
__device__ float g_x[(size_t)NPAD * HIDD];
// fragment-order fp16 buffers (uint32 views; 1 chunk = 2048 u32 = 4096 halves)
__device__ uint32_t g_xf[(size_t)NSLAB * 8192];
__device__ uint32_t g_aggf[(size_t)NSLAB * 32768];
__device__ uint32_t g_wqkvf[(size_t)LLL * 3 * 32768];
__device__ uint32_t g_wpf[(size_t)LLL * 32768];
__device__ uint32_t g_wff[(size_t)LLL * 8192];
__device__ float g_bf[(size_t)LLL * HIDD];

// CSR
__device__ int   g_deg[NN];
__device__ int   g_off[NN + 1];
__device__ int   g_cur[NN];
__device__ int   g_blk[256];
__device__ int   g_srcs[EE];
__device__ float g_eas[EE];

__device__ __forceinline__ uint32_t cvta_sm(const void* p) {
    uint32_t a;
    asm("{ .reg .u64 t; cvta.to.shared.u64 t, %1; cvt.u32.u64 %0, t; }" : "=r"(a) : "l"(p));
    return a;
}
__device__ __forceinline__ void cp16(uint32_t smem, const void* g) {
    asm volatile("cp.async.cg.shared.global [%0], [%1], 16;" :: "r"(smem), "l"(g));
}
#define CP_COMMIT() asm volatile("cp.async.commit_group;" ::: "memory")
#define CP_WAIT(n)  asm volatile("cp.async.wait_group %0;" :: "n"(n) : "memory")

// fp16 mma m16n8k16: D += A*B (fp32 acc in-place)
__device__ __forceinline__ void mma16816(float* d, const uint32_t* a, const uint32_t* b) {
    asm volatile("mma.sync.aligned.m16n8k16.row.col.f32.f16.f16.f32 "
        "{%0,%1,%2,%3}, {%4,%5,%6,%7}, {%8,%9}, {%0,%1,%2,%3};"
        : "+f"(d[0]), "+f"(d[1]), "+f"(d[2]), "+f"(d[3])
        : "r"(a[0]), "r"(a[1]), "r"(a[2]), "r"(a[3]), "r"(b[0]), "r"(b[1]));
}

// half-index within one A chunk (128m x 32k fp16, 4096 halves)
__device__ __forceinline__ int aidx_h(int m, int kk) {
    int m_tile = m >> 4, r = m & 15;
    int k16 = kk >> 4, kw = kk & 15;
    int lane = (r & 7) * 4 + ((kw & 7) >> 1);
    int reg = ((kw >> 3) << 1) + (r >> 3);
    int u = ((k16 * 8 + m_tile) * 32 + lane) * 4 + reg;
    return u * 2 + (kw & 1);
}
// half-index within one B chunk (32k x 128n fp16, 4096 halves)
__device__ __forceinline__ int bidx_h(int kk, int n) {
    int k16 = kk >> 4, kw = kk & 15;
    int n_tile = n >> 3, nn = n & 7;
    int tg = (kw & 7) >> 1;
    int lane = nn * 4 + tg;
    int reg = kw >> 3;
    int u = ((k16 * 16 + n_tile) * 32 + lane) * 2 + reg;
    return u * 2 + (kw & 1);
}

#define QKV_SMEM_B ((8192 + 4*2048) * 4)     // 65536: A slab + 4-buf B ring
#define PRJ_SMEM_B (128 * 132 * 4)           // 67584 (>= ring's 4*2048*2*4 = 65536)

// ---------------- Fused QKV GEMM (fp16 mma, 4-deep cp.async ring, N-split x4) ----------------
__global__ __launch_bounds__(256, 2) void gemm_qkv_mma(
    const uint32_t* __restrict__ xf, const uint32_t* __restrict__ wf,
    const float* __restrict__ b0, const float* __restrict__ b1, const float* __restrict__ b2,
    __nv_bfloat16* __restrict__ oq, __nv_bfloat16* __restrict__ ok,
    __half* __restrict__ ov)
{
    extern __shared__ uint32_t smu[];
    uint32_t* As = smu;              // 4 chunks x 2048 u32
    uint32_t* Bs = smu + 8192;       // 4 bufs x 2048 u32
    const uint32_t As_a = cvta_sm(As);
    const uint32_t Bs_a = cvta_sm(Bs);

    const int tid = threadIdx.x;
    const int wid = tid >> 5;
    const int lane = tid & 31;
    const int m0 = blockIdx.y * 128;
    const int wm = wid >> 2;
    const int wn = wid & 3;
    const int t0 = blockIdx.x * 3;

    const float* bp[3] = {b0, b1, b2};

    auto chunkPtr = [&](int s) {
        int tg = t0 + (s >> 2);
        return wf + (size_t)(tg >> 2) * 32768 + (size_t)(((tg & 3) * 4) + (s & 3)) * 2048;
    };
    auto cpB = [&](const uint32_t* chunk, int buf) {
        uint32_t base = Bs_a + buf * 2048 * 4;
#pragma unroll
        for (int g = 0; g < 2; g++) {
            int o = (g * 256 + tid) * 4;
            cp16(base + o * 4, chunk + o);
        }
    };

    // prologue: group0 = A slab + B0; group1 = B1; group2 = B2
    {
        const uint32_t* asrc = xf + (size_t)blockIdx.y * 8192;
#pragma unroll
        for (int g = 0; g < 8; g++) {
            int o = (g * 256 + tid) * 4;
            cp16(As_a + o * 4, asrc + o);
        }
    }
    cpB(chunkPtr(0), 0);
    CP_COMMIT();
    cpB(chunkPtr(1), 1);
    CP_COMMIT();
    cpB(chunkPtr(2), 2);
    CP_COMMIT();

    float acc[4][4][4];
    auto initAcc = [&](int tg) {
        const float* bias = bp[tg >> 2] + (tg & 3) * 128 + wn * 32;
#pragma unroll
        for (int j = 0; j < 4; j++) {
            float bv0 = __ldg(bias + j * 8 + 2 * (lane & 3));
            float bv1 = __ldg(bias + j * 8 + 2 * (lane & 3) + 1);
#pragma unroll
            for (int i = 0; i < 4; i++) {
                acc[i][j][0] = bv0; acc[i][j][1] = bv1;
                acc[i][j][2] = bv0; acc[i][j][3] = bv1;
            }
        }
    };
    auto epilogue = [&](int tg) {
        const int w = tg >> 2;
        const int col = (tg & 3) * 128 + wn * 32 + 2 * (lane & 3);
        if (w < 2) {
            __nv_bfloat16* out = (w == 0) ? oq : ok;
#pragma unroll
            for (int i = 0; i < 4; i++) {
                int row = m0 + wm * 64 + i * 16 + (lane >> 2);
#pragma unroll
                for (int j = 0; j < 4; j++) {
                    *(__nv_bfloat162*)(out + (size_t)row * HCC + col + j * 8) =
                        __floats2bfloat162_rn(acc[i][j][0], acc[i][j][1]);
                    *(__nv_bfloat162*)(out + (size_t)(row + 8) * HCC + col + j * 8) =
                        __floats2bfloat162_rn(acc[i][j][2], acc[i][j][3]);
                }
            }
        } else {
#pragma unroll
            for (int i = 0; i < 4; i++) {
                int row = m0 + wm * 64 + i * 16 + (lane >> 2);
#pragma unroll
                for (int j = 0; j < 4; j++) {
                    *(__half2*)(ov + (size_t)row * HCC + col + j * 8) =
                        __floats2half2_rn(acc[i][j][0], acc[i][j][1]);
                    *(__half2*)(ov + (size_t)(row + 8) * HCC + col + j * 8) =
                        __floats2half2_rn(acc[i][j][2], acc[i][j][3]);
                }
            }
        }
    };
    auto mmaChunk = [&](int buf, int kc) {
        const uint32_t* B = Bs + buf * 2048;
        const uint32_t* Ac = As + kc * 2048;
#pragma unroll
        for (int k16 = 0; k16 < 2; k16++) {
            uint32_t af[4][4];
#pragma unroll
            for (int i = 0; i < 4; i++) {
                uint32_t u = (uint32_t)(((k16 * 8 + wm * 4 + i) * 32 + lane) * 4);
                uint4 t4 = *(const uint4*)(Ac + u);
                af[i][0] = t4.x; af[i][1] = t4.y; af[i][2] = t4.z; af[i][3] = t4.w;
            }
            uint32_t bf[4][2];
#pragma unroll
            for (int j = 0; j < 4; j++) {
                uint32_t v = (uint32_t)(((k16 * 16 + wn * 4 + j) * 32 + lane) * 2);
                uint2 t2 = *(const uint2*)(B + v);
                bf[j][0] = t2.x; bf[j][1] = t2.y;
            }
#pragma unroll
            for (int i = 0; i < 4; i++)
#pragma unroll
                for (int j = 0; j < 4; j++)
                    mma16816(acc[i][j], af[i], bf[j]);
        }
    };

    initAcc(t0);

    for (int s = 0; s < 12; s++) {
        // stage s must be complete: issued = min(12, s+3) groups, need s+1 done
        if (s < 10)      { CP_WAIT(2); }
        else if (s == 10){ CP_WAIT(1); }
        else             { CP_WAIT(0); }
        __syncthreads();
        if (s + 3 < 12) { cpB(chunkPtr(s + 3), (s + 3) & 3); CP_COMMIT(); }
        mmaChunk(s & 3, s & 3);
        if ((s & 3) == 3) {
            int tg = t0 + (s >> 2);
            epilogue(tg);
            if ((s >> 2) < 2) initAcc(tg + 1);
        }
    }
}

// ---------------- Proj GEMM + ELU + residual + LayerNorm (fp16 mma, 4-deep ring) ----------------
__global__ __launch_bounds__(256, 2) void gemm_proj_ln(
    const uint32_t* __restrict__ aggf, const uint32_t* __restrict__ wpf,
    const uint32_t* __restrict__ xf, const uint32_t* __restrict__ wff,
    const float* __restrict__ bias,
    const float* __restrict__ x, const float* __restrict__ gamma,
    const float* __restrict__ beta,
    float* __restrict__ out, uint32_t* __restrict__ xfo)
{
    extern __shared__ uint32_t smu[];
    uint32_t* As = smu;              // 4 x 2048
    uint32_t* Bs = smu + 8192;       // 4 x 2048
    const uint32_t As_a = cvta_sm(As);
    const uint32_t Bs_a = cvta_sm(Bs);

    const int tid = threadIdx.x;
    const int wid = tid >> 5;
    const int lane = tid & 31;
    const int slab = blockIdx.x;
    const int m0 = slab * 128;
    const int wm = wid >> 2;
    const int wn = wid & 3;

    auto cpStage = [&](int s1, int buf) {
        const uint32_t *Asrc, *Bsrc;
        if (s1 < 16) {
            Asrc = aggf + (size_t)slab * 32768 + (size_t)s1 * 2048;
            Bsrc = wpf + (size_t)s1 * 2048;
        } else {
            Asrc = xf + (size_t)slab * 8192 + (size_t)(s1 - 16) * 2048;
            Bsrc = wff + (size_t)(s1 - 16) * 2048;
        }
        uint32_t ab = As_a + buf * 2048 * 4;
        uint32_t bb = Bs_a + buf * 2048 * 4;
#pragma unroll
        for (int g = 0; g < 2; g++) {
            int o = (g * 256 + tid) * 4;
            cp16(ab + o * 4, Asrc + o);
            cp16(bb + o * 4, Bsrc + o);
        }
    };

    float acc[4][4][4];
    {
        const float* bp = bias + wn * 32;
#pragma unroll
        for (int j = 0; j < 4; j++) {
            float bv0 = __ldg(bp + j * 8 + 2 * (lane & 3));
            float bv1 = __ldg(bp + j * 8 + 2 * (lane & 3) + 1);
#pragma unroll
            for (int i = 0; i < 4; i++) {
                acc[i][j][0] = bv0; acc[i][j][1] = bv1;
                acc[i][j][2] = bv0; acc[i][j][3] = bv1;
            }
        }
    }

    cpStage(0, 0); CP_COMMIT();
    cpStage(1, 1); CP_COMMIT();
    cpStage(2, 2); CP_COMMIT();

    for (int s = 0; s < 20; s++) {
        if (s < 18)      { CP_WAIT(2); }
        else if (s == 18){ CP_WAIT(1); }
        else             { CP_WAIT(0); }
        __syncthreads();
        if (s + 3 < 20) { cpStage(s + 3, (s + 3) & 3); CP_COMMIT(); }
        {
            const uint32_t* Ac = As + (s & 3) * 2048;
            const uint32_t* Bc = Bs + (s & 3) * 2048;
#pragma unroll
            for (int k16 = 0; k16 < 2; k16++) {
                uint32_t af[4][4];
#pragma unroll
                for (int i = 0; i < 4; i++) {
                    uint32_t u = (uint32_t)(((k16 * 8 + wm * 4 + i) * 32 + lane) * 4);
                    uint4 t4 = *(const uint4*)(Ac + u);
                    af[i][0] = t4.x; af[i][1] = t4.y; af[i][2] = t4.z; af[i][3] = t4.w;
                }
                uint32_t bf[4][2];
#pragma unroll
                for (int j = 0; j < 4; j++) {
                    uint32_t v = (uint32_t)(((k16 * 16 + wn * 4 + j) * 32 + lane) * 2);
                    uint2 t2 = *(const uint2*)(Bc + v);
                    bf[j][0] = t2.x; bf[j][1] = t2.y;
                }
#pragma unroll
                for (int i = 0; i < 4; i++)
#pragma unroll
                    for (int j = 0; j < 4; j++)
                        mma16816(acc[i][j], af[i], bf[j]);
            }
        }
    }

    // ---- fused epilogue: elu(h) staged in smem [128][132], LN per row ----
    __syncthreads();
    float* ht = (float*)smu;
    {
        int col = wn * 32 + 2 * (lane & 3);
#pragma unroll
        for (int i = 0; i < 4; i++) {
            int r0 = wm * 64 + i * 16 + (lane >> 2);
#pragma unroll
            for (int j = 0; j < 4; j++) {
                float e0 = acc[i][j][0], e1 = acc[i][j][1];
                float e2 = acc[i][j][2], e3 = acc[i][j][3];
                ht[r0 * 132 + col + j * 8]           = e0 > 0.f ? e0 : expm1f(e0);
                ht[r0 * 132 + col + j * 8 + 1]       = e1 > 0.f ? e1 : expm1f(e1);
                ht[(r0 + 8) * 132 + col + j * 8]     = e2 > 0.f ? e2 : expm1f(e2);
                ht[(r0 + 8) * 132 + col + j * 8 + 1] = e3 > 0.f ? e3 : expm1f(e3);
            }
        }
    }
    __syncthreads();

    const float4 gv = *(const float4*)(gamma + lane * 4);
    const float4 bv = *(const float4*)(beta + lane * 4);
    __half* xfoh = (__half*)xfo;

#pragma unroll
    for (int r = 0; r < 16; r++) {
        int row = wid * 16 + r;
        int grow = m0 + row;
        float4 h4 = *(const float4*)(ht + row * 132 + lane * 4);
        float4 x4 = *(const float4*)(x + (size_t)grow * HIDD + lane * 4);
        float4 y;
        y.x = x4.x + h4.x; y.y = x4.y + h4.y;
        y.z = x4.z + h4.z; y.w = x4.w + h4.w;

        float sum = y.x + y.y + y.z + y.w;
        float sq  = y.x * y.x + y.y * y.y + y.z * y.z + y.w * y.w;
#pragma unroll
        for (int off = 16; off; off >>= 1) {
            sum += __shfl_xor_sync(0xffffffffu, sum, off);
            sq  += __shfl_xor_sync(0xffffffffu, sq, off);
        }
        float mu = sum * (1.f / 128.f);
        float var = sq * (1.f / 128.f) - mu * mu;
        float inv = rsqrtf(var + 1e-5f);

        float4 o;
        o.x = (y.x - mu) * inv * gv.x + bv.x;
        o.y = (y.y - mu) * inv * gv.y + bv.y;
        o.z = (y.z - mu) * inv * gv.z + bv.z;
        o.w = (y.w - mu) * inv * gv.w + bv.w;

        if (grow < NN)
            *(float4*)(out + (size_t)grow * HIDD + lane * 4) = o;

        if (xfo) {
            float vals[4] = {o.x, o.y, o.z, o.w};
            __half* dst = xfoh + (size_t)slab * 16384;
#pragma unroll
            for (int j = 0; j < 4; j++) {
                int k = lane * 4 + j;
                dst[(size_t)(k >> 5) * 4096 + aidx_h(row, k & 31)] = __float2half_rn(vals[j]);
            }
        }
    }
}

// ---------------- Weight prep (fp16 frag order) ----------------
__global__ void prep_qkv_w(const float* __restrict__ Wq, const float* __restrict__ Wk,
                           const float* __restrict__ Wv, uint32_t* __restrict__ dst)
{
    int t = blockIdx.x * 256 + threadIdx.x;
    int l = t / 196608;
    int r = t - l * 196608;
    int w = r >> 16;
    int e = r & 65535;
    int k = e >> 9, n = e & 511;
    const float* W = (w == 0 ? Wq : (w == 1 ? Wk : Wv)) + (size_t)l * 65536;
    float val = W[k * 512 + n];
    __half* dh = (__half*)dst;
    dh[(size_t)((l * 3 + w) * 16 + (n >> 7) * 4 + (k >> 5)) * 4096 +
       bidx_h(k & 31, n & 127)] = __float2half_rn(val);
}

__global__ void prep_proj_w(const float* __restrict__ Wproj, uint32_t* __restrict__ dst)
{
    int t = blockIdx.x * 256 + threadIdx.x;
    int l = t >> 16, e = t & 65535;
    int k = e >> 7, n = e & 127;
    float val = Wproj[(size_t)l * 65536 + k * 128 + n];
    __half* dh = (__half*)dst;
    dh[(size_t)(l * 16 + (k >> 5)) * 4096 + bidx_h(k & 31, n)] = __float2half_rn(val);
}

// Wf = Wskip @ Wproj — coalesced
__global__ __launch_bounds__(512) void wf_k(const float* __restrict__ Wskip,
                                            const float* __restrict__ Wproj,
                                            uint32_t* __restrict__ wff)
{
    __shared__ float red[4][128];
    int i = blockIdx.x, l = blockIdx.y;
    int j = threadIdx.x & 127, q = threadIdx.x >> 7;
    const float* ws = Wskip + (size_t)l * HIDD * HCC + (size_t)i * HCC + q * 128;
    const float* wp = Wproj + (size_t)l * HCC * HIDD + (size_t)(q * 128) * HIDD + j;
    float s0 = 0.f, s1 = 0.f, s2 = 0.f, s3 = 0.f;
#pragma unroll 8
    for (int k = 0; k < 128; k += 4) {
        s0 = fmaf(ws[k],     wp[(size_t)k * HIDD],       s0);
        s1 = fmaf(ws[k + 1], wp[(size_t)(k + 1) * HIDD], s1);
        s2 = fmaf(ws[k + 2], wp[(size_t)(k + 2) * HIDD], s2);
        s3 = fmaf(ws[k + 3], wp[(size_t)(k + 3) * HIDD], s3);
    }
    red[q][j] = (s0 + s1) + (s2 + s3);
    __syncthreads();
    if (q == 0) {
        float s = red[0][j] + red[1][j] + red[2][j] + red[3][j];
        __half* dh = (__half*)wff;
        dh[(size_t)(l * 4 + (i >> 5)) * 4096 + bidx_h(i & 31, j)] = __float2half_rn(s);
    }
}

__global__ void bf_k(const float* __restrict__ bskip, const float* __restrict__ Wproj,
                     const float* __restrict__ bproj, float* __restrict__ bf)
{
    int l = blockIdx.x, j = threadIdx.x;
    const float* bs = bskip + (size_t)l * HCC;
    const float* wp = Wproj + (size_t)l * HCC * HIDD + j;
    float s0 = 0.f, s1 = 0.f, s2 = 0.f, s3 = 0.f;
#pragma unroll 8
    for (int k = 0; k < HCC; k += 4) {
        s0 = fmaf(bs[k],     wp[(size_t)k * HIDD],       s0);
        s1 = fmaf(bs[k + 1], wp[(size_t)(k + 1) * HIDD], s1);
        s2 = fmaf(bs[k + 2], wp[(size_t)(k + 2) * HIDD], s2);
        s3 = fmaf(bs[k + 3], wp[(size_t)(k + 3) * HIDD], s3);
    }
    bf[l * HIDD + j] = bproj[(size_t)l * HIDD + j] + (s0 + s1) + (s2 + s3);
}

// x_in -> fp16 frag order (layer 0)
__global__ void init_xfrag_k(const float* __restrict__ x, uint32_t* __restrict__ xf)
{
    int t = blockIdx.x * 256 + threadIdx.x;
    int row = t >> 5, lane = t & 31;
    float4 v = *(const float4*)(x + (size_t)row * HIDD + lane * 4);
    int slab = row >> 7, m = row & 127;
    float vals[4] = {v.x, v.y, v.z, v.w};
    __half* xfh = (__half*)xf;
#pragma unroll
    for (int j = 0; j < 4; j++) {
        int k = lane * 4 + j;
        xfh[(size_t)slab * 16384 + (size_t)(k >> 5) * 4096 + aidx_h(m, k & 31)] =
            __float2half_rn(vals[j]);
    }
}

// ---------------- CSR build ----------------
__global__ void hist_k(const int* __restrict__ dst, int* __restrict__ deg) {
    int e = blockIdx.x * 256 + threadIdx.x;
    if (e < EE) atomicAdd(deg + dst[e], 1);
}

__global__ void scanA_k(const int* __restrict__ deg, int* __restrict__ off,
                        int* __restrict__ blk) {
    __shared__ int sh[256];
    int t = threadIdx.x;
    int idx = blockIdx.x * 256 + t;
    int val = (idx < NN) ? deg[idx] : 0;
    sh[t] = val;
    __syncthreads();
#pragma unroll
    for (int d = 1; d < 256; d <<= 1) {
        int add = (t >= d) ? sh[t - d] : 0;
        __syncthreads();
        sh[t] += add;
        __syncthreads();
    }
    if (idx < NN) off[idx] = sh[t] - val;
    if (t == 255) blk[blockIdx.x] = sh[255];
}

__global__ void scanB_k(int* __restrict__ blk) {
    __shared__ int sh[256];
    int t = threadIdx.x;
    int val = (t < 196) ? blk[t] : 0;
    sh[t] = val;
    __syncthreads();
#pragma unroll
    for (int d = 1; d < 256; d <<= 1) {
        int add = (t >= d) ? sh[t - d] : 0;
        __syncthreads();
        sh[t] += add;
        __syncthreads();
    }
    if (t < 196) blk[t] = sh[t] - val;
}

__global__ void scanC_k(int* __restrict__ off, const int* __restrict__ blk,
                        int* __restrict__ cur) {
    int idx = blockIdx.x * 256 + threadIdx.x;
    if (idx < NN) {
        int o = off[idx] + blk[blockIdx.x];
        off[idx] = o;
        cur[idx] = o;
    }
    if (idx == 0) off[NN] = EE;
}

__global__ void scatter_k(const int* __restrict__ src, const int* __restrict__ dst,
                          const float* __restrict__ ea, int* __restrict__ cur,
                          int* __restrict__ srcs, float* __restrict__ eas) {
    int e = blockIdx.x * 256 + threadIdx.x;
    if (e < EE) {
        int p = atomicAdd(cur + dst[e], 1);
        srcs[p] = src[e];
        eas[p] = ea[e];
    }
}

// ---------------- Node-centric fused attention (q,k bf16; v fp16) ----------------
__global__ __launch_bounds__(256) void attn_node_k(
    const __nv_bfloat16* __restrict__ q, const __nv_bfloat16* __restrict__ k,
    const __half* __restrict__ v, const int* __restrict__ off,
    const int* __restrict__ srcs, const float* __restrict__ eas,
    const float* __restrict__ We, uint32_t* __restrict__ aggf)
{
    int wg = blockIdx.x * 8 + (threadIdx.x >> 5);
    int lane = threadIdx.x & 31;
    int d = wg >> 2, h = wg & 3;

    int beg = __ldg(off + d), end = __ldg(off + d + 1);

    uint2 qraw = *(const uint2*)(q + (size_t)d * HCC + h * CCC + lane * 4);
    float2 q01 = __bfloat1622float2(*(__nv_bfloat162*)&qraw.x);
    float2 q23 = __bfloat1622float2(*(__nv_bfloat162*)&qraw.y);
    const float4 wv = *(const float4*)(We + h * CCC + lane * 4);

    float a0 = 0.f, a1 = 0.f, a2 = 0.f, a3 = 0.f, den = 0.f;

    for (int i = beg; i < end; i++) {
        int sN = __ldg(srcs + i);
        float eav = __ldg(eas + i);

        uint2 kraw = *(const uint2*)(k + (size_t)sN * HCC + h * CCC + lane * 4);
        float2 k01 = __bfloat1622float2(*(__nv_bfloat162*)&kraw.x);
        float2 k23 = __bfloat1622float2(*(__nv_bfloat162*)&kraw.y);

        float s = q01.x * fmaf(eav, wv.x, k01.x) + q01.y * fmaf(eav, wv.y, k01.y)
                + q23.x * fmaf(eav, wv.z, k23.x) + q23.y * fmaf(eav, wv.w, k23.y);
#pragma unroll
        for (int o = 16; o; o >>= 1) s += __shfl_xor_sync(0xffffffffu, s, o);

        float pv = expf(s * 0.08838834764831845f);
        den += pv;

        uint2 vraw = *(const uint2*)(v + (size_t)sN * HCC + h * CCC + lane * 4);
        float2 v01 = __half22float2(*(__half2*)&vraw.x);
        float2 v23 = __half22float2(*(__half2*)&vraw.y);
        a0 = fmaf(fmaf(eav, wv.x, v01.x), pv, a0);
        a1 = fmaf(fmaf(eav, wv.y, v01.y), pv, a1);
        a2 = fmaf(fmaf(eav, wv.z, v23.x), pv, a2);
        a3 = fmaf(fmaf(eav, wv.w, v23.y), pv, a3);
    }

    float inv = 1.f / (den + 1e-16f);
    float vals[4] = {a0 * inv, a1 * inv, a2 * inv, a3 * inv};

    int slab = d >> 7, m = d & 127;
    __half* base = (__half*)aggf + (size_t)slab * 65536;
#pragma unroll
    for (int j = 0; j < 4; j++) {
        int kk = h * 128 + lane * 4 + j;
        base[(size_t)(kk >> 5) * 4096 + aidx_h(m, kk & 31)] = __float2half_rn(vals[j]);
    }
}

// ---------------- host ----------------
extern "C" void kernel_launch(void* const* d_in, const int* in_sizes, int n_in,
                              void* d_out, int out_size)
{
    const float* x_in  = (const float*)d_in[0];
    const int*   ei    = (const int*)d_in[1];
    const float* ea    = (const float*)d_in[2];
    const float* Wq    = (const float*)d_in[3];
    const float* bq    = (const float*)d_in[4];
    const float* Wk    = (const float*)d_in[5];
    const float* bk    = (const float*)d_in[6];
    const float* Wv    = (const float*)d_in[7];
    const float* bv    = (const float*)d_in[8];
    const float* We    = (const float*)d_in[9];
    const float* Wskip = (const float*)d_in[10];
    const float* bskip = (const float*)d_in[11];
    const float* Wproj = (const float*)d_in[12];
    const float* bproj = (const float*)d_in[13];
    const float* gamma = (const float*)d_in[14];
    const float* beta  = (const float*)d_in[15];

    __nv_bfloat16 *qb, *kb;
    __half *v;
    float *xbuf, *bfv, *eas;
    uint32_t *xf, *aggf, *wqkvf, *wpf, *wff;
    int *deg, *off, *cur, *blk, *srcs;
    cudaGetSymbolAddress((void**)&qb,    g_qb);
    cudaGetSymbolAddress((void**)&kb,    g_kb);
    cudaGetSymbolAddress((void**)&v,     g_v);
    cudaGetSymbolAddress((void**)&xbuf,  g_x);
    cudaGetSymbolAddress((void**)&xf,    g_xf);
    cudaGetSymbolAddress((void**)&aggf,  g_aggf);
    cudaGetSymbolAddress((void**)&wqkvf, g_wqkvf);
    cudaGetSymbolAddress((void**)&wpf,   g_wpf);
    cudaGetSymbolAddress((void**)&wff,   g_wff);
    cudaGetSymbolAddress((void**)&bfv,   g_bf);
    cudaGetSymbolAddress((void**)&deg,   g_deg);
    cudaGetSymbolAddress((void**)&off,   g_off);
    cudaGetSymbolAddress((void**)&cur,   g_cur);
    cudaGetSymbolAddress((void**)&blk,   g_blk);
    cudaGetSymbolAddress((void**)&srcs,  g_srcs);
    cudaGetSymbolAddress((void**)&eas,   g_eas);

    cudaFuncSetAttribute(gemm_qkv_mma, cudaFuncAttributeMaxDynamicSharedMemorySize,
                         QKV_SMEM_B);
    cudaFuncSetAttribute(gemm_proj_ln, cudaFuncAttributeMaxDynamicSharedMemorySize,
                         PRJ_SMEM_B);

    const int* src = ei;
    const int* dst = ei + EE;

    cudaMemcpyAsync(xbuf, x_in, (size_t)NN * HIDD * sizeof(float),
                    cudaMemcpyDeviceToDevice);
    init_xfrag_k<<<(NN * 32) / 256, 256>>>(x_in, xf);

    prep_qkv_w<<<2304, 256>>>(Wq, Wk, Wv, wqkvf);
    prep_proj_w<<<768, 256>>>(Wproj, wpf);
    wf_k<<<dim3(128, 3), 512>>>(Wskip, Wproj, wff);
    bf_k<<<3, 128>>>(bskip, Wproj, bproj, bfv);

    cudaMemsetAsync(deg, 0, NN * sizeof(int));
    hist_k<<<(EE + 255) / 256, 256>>>(dst, deg);
    scanA_k<<<(NN + 255) / 256, 256>>>(deg, off, blk);
    scanB_k<<<1, 256>>>(blk);
    scanC_k<<<(NN + 255) / 256, 256>>>(off, blk, cur);
    scatter_k<<<(EE + 255) / 256, 256>>>(src, dst, ea, cur, srcs, eas);

    const int attnBlocks = (NN * HH) / 8;

    for (int l = 0; l < LLL; l++) {
        float* xo = (l == LLL - 1) ? (float*)d_out : xbuf;
        uint32_t* xfo = (l == LLL - 1) ? nullptr : xf;

        gemm_qkv_mma<<<dim3(4, NSLAB), 256, QKV_SMEM_B>>>(
            xf, wqkvf + (size_t)l * 3 * 32768,
            bq + l * HCC, bk + l * HCC, bv + l * HCC, qb, kb, v);

        attn_node_k<<<attnBlocks, 256>>>(qb, kb, v, off, srcs, eas,
                                         We + l * HCC, aggf);

        gemm_proj_ln<<<NSLAB, 256, PRJ_SMEM_B>>>(
            aggf, wpf + (size_t)l * 32768,
            xf, wff + (size_t)l * 8192,
            bfv + l * HIDD,
            xbuf, gamma + l * HIDD, beta + l * HIDD,
            xo, xfo);
    }
}

// round 14
// speedup vs baseline: 4.3204x; 1.1338x over previous
#include <cuda_runtime.h>
#include <cuda_bf16.h>
#include <cuda_fp16.h>
#include <math.h>
#include <stdint.h>

#define NN 50000
#define NPAD 50048          // 391 * 128
#define NSLAB 391
#define EE 100000
#define HIDD 128
#define HH 4
#define CCC 128
#define HCC 512
#define LLL 3

// ---------------- scratch ----------------
__device__ __half g_t[(size_t)NPAD * HCC];               // t = x@Mstack + r, row-major
__device__ __half g_xh[(size_t)NPAD * HIDD];             // x row-major half (gathers)
__device__ float g_x[(size_t)NPAD * HIDD];               // x fp32 (residual)
// fragment-order fp16 buffers (uint32 views; 1 chunk = 2048 u32 = 4096 halves)
__device__ uint32_t g_xf[(size_t)NSLAB * 8192];          // x frag
__device__ uint32_t g_gf[(size_t)NSLAB * 32768];         // g frag (x-space agg)
__device__ uint32_t g_scf[(size_t)NSLAB * 2048];         // sa/cn ext chunk (zeros elsewhere)
__device__ uint32_t g_wtf[(size_t)LLL * 16 * 2048];      // Mstack frag
__device__ uint32_t g_wvpf[(size_t)LLL * 16 * 2048];     // Wv@Wproj frag
__device__ uint32_t g_extf[(size_t)LLL * 2048];          // [bvP;WeP] ext chunk
__device__ uint32_t g_wff[(size_t)LLL * 8192];           // Wskip@Wproj frag
__device__ float g_bt[(size_t)LLL * HCC];                // t bias (r)
__device__ float g_uz[(size_t)LLL * 1024];               // u[4][128], z[4][128]
__device__ float g_ccv[(size_t)LLL * 8];                 // cq[4], cw[4]
__device__ float g_bf[(size_t)LLL * HIDD];               // bproj + bskip@Wproj

// CSR
__device__ int   g_deg[NN];
__device__ int   g_off[NN + 1];
__device__ int   g_cur[NN];
__device__ int   g_blk[256];
__device__ int   g_srcs[EE];
__device__ float g_eas[EE];

__device__ __forceinline__ uint32_t cvta_sm(const void* p) {
    uint32_t a;
    asm("{ .reg .u64 t; cvta.to.shared.u64 t, %1; cvt.u32.u64 %0, t; }" : "=r"(a) : "l"(p));
    return a;
}
__device__ __forceinline__ void cp16(uint32_t smem, const void* g) {
    asm volatile("cp.async.cg.shared.global [%0], [%1], 16;" :: "r"(smem), "l"(g));
}
#define CP_COMMIT() asm volatile("cp.async.commit_group;" ::: "memory")
#define CP_WAIT(n)  asm volatile("cp.async.wait_group %0;" :: "n"(n) : "memory")

__device__ __forceinline__ void mma16816(float* d, const uint32_t* a, const uint32_t* b) {
    asm volatile("mma.sync.aligned.m16n8k16.row.col.f32.f16.f16.f32 "
        "{%0,%1,%2,%3}, {%4,%5,%6,%7}, {%8,%9}, {%0,%1,%2,%3};"
        : "+f"(d[0]), "+f"(d[1]), "+f"(d[2]), "+f"(d[3])
        : "r"(a[0]), "r"(a[1]), "r"(a[2]), "r"(a[3]), "r"(b[0]), "r"(b[1]));
}

// half-index within one A chunk (128m x 32k fp16)
__device__ __forceinline__ int aidx_h(int m, int kk) {
    int m_tile = m >> 4, r = m & 15;
    int k16 = kk >> 4, kw = kk & 15;
    int lane = (r & 7) * 4 + ((kw & 7) >> 1);
    int reg = ((kw >> 3) << 1) + (r >> 3);
    int u = ((k16 * 8 + m_tile) * 32 + lane) * 4 + reg;
    return u * 2 + (kw & 1);
}
// half-index within one B chunk (32k x 128n fp16)
__device__ __forceinline__ int bidx_h(int kk, int n) {
    int k16 = kk >> 4, kw = kk & 15;
    int n_tile = n >> 3, nn = n & 7;
    int tg = (kw & 7) >> 1;
    int lane = nn * 4 + tg;
    int reg = kw >> 3;
    int u = ((k16 * 16 + n_tile) * 32 + lane) * 2 + reg;
    return u * 2 + (kw & 1);
}

#define T_SMEM_B ((8192 + 4*2048) * 4)       // 65536
#define PRJ_SMEM_B (128 * 132 * 4)           // 67584

// ---------------- t GEMM: t = x@Mstack + r (fp16 mma, N-split x2, 8 stages) ----------------
__global__ __launch_bounds__(256, 2) void gemm_t_mma(
    const uint32_t* __restrict__ xf, const uint32_t* __restrict__ wt,
    const float* __restrict__ bt, __half* __restrict__ ot)
{
    extern __shared__ uint32_t smu[];
    uint32_t* As = smu;              // 4 chunks x 2048 u32
    uint32_t* Bs = smu + 8192;       // 4 bufs x 2048 u32
    const uint32_t As_a = cvta_sm(As);
    const uint32_t Bs_a = cvta_sm(Bs);

    const int tid = threadIdx.x;
    const int wid = tid >> 5;
    const int lane = tid & 31;
    const int m0 = blockIdx.y * 128;
    const int wm = wid >> 2;
    const int wn = wid & 3;
    const int t0 = blockIdx.x * 2;

    auto chunkPtr = [&](int s) {
        int tg = t0 + (s >> 2);
        return wt + (size_t)(tg * 4 + (s & 3)) * 2048;
    };
    auto cpB = [&](const uint32_t* chunk, int buf) {
        uint32_t base = Bs_a + buf * 2048 * 4;
#pragma unroll
        for (int g = 0; g < 2; g++) {
            int o = (g * 256 + tid) * 4;
            cp16(base + o * 4, chunk + o);
        }
    };

    {
        const uint32_t* asrc = xf + (size_t)blockIdx.y * 8192;
#pragma unroll
        for (int g = 0; g < 8; g++) {
            int o = (g * 256 + tid) * 4;
            cp16(As_a + o * 4, asrc + o);
        }
    }
    cpB(chunkPtr(0), 0); CP_COMMIT();
    cpB(chunkPtr(1), 1); CP_COMMIT();
    cpB(chunkPtr(2), 2); CP_COMMIT();

    float acc[4][4][4];
    auto initAcc = [&](int tg) {
        const float* bias = bt + tg * 128 + wn * 32;
#pragma unroll
        for (int j = 0; j < 4; j++) {
            float bv0 = __ldg(bias + j * 8 + 2 * (lane & 3));
            float bv1 = __ldg(bias + j * 8 + 2 * (lane & 3) + 1);
#pragma unroll
            for (int i = 0; i < 4; i++) {
                acc[i][j][0] = bv0; acc[i][j][1] = bv1;
                acc[i][j][2] = bv0; acc[i][j][3] = bv1;
            }
        }
    };
    auto epilogue = [&](int tg) {
        const int col = tg * 128 + wn * 32 + 2 * (lane & 3);
#pragma unroll
        for (int i = 0; i < 4; i++) {
            int row = m0 + wm * 64 + i * 16 + (lane >> 2);
#pragma unroll
            for (int j = 0; j < 4; j++) {
                *(__half2*)(ot + (size_t)row * HCC + col + j * 8) =
                    __floats2half2_rn(acc[i][j][0], acc[i][j][1]);
                *(__half2*)(ot + (size_t)(row + 8) * HCC + col + j * 8) =
                    __floats2half2_rn(acc[i][j][2], acc[i][j][3]);
            }
        }
    };
    auto mmaChunk = [&](int buf) {
        const uint32_t* B = Bs + buf * 2048;
        const uint32_t* Ac = As + buf * 2048;   // kc == buf (s&3)
#pragma unroll
        for (int k16 = 0; k16 < 2; k16++) {
            uint32_t af[4][4];
#pragma unroll
            for (int i = 0; i < 4; i++) {
                uint32_t u = (uint32_t)(((k16 * 8 + wm * 4 + i) * 32 + lane) * 4);
                uint4 t4 = *(const uint4*)(Ac + u);
                af[i][0] = t4.x; af[i][1] = t4.y; af[i][2] = t4.z; af[i][3] = t4.w;
            }
            uint32_t bf[4][2];
#pragma unroll
            for (int j = 0; j < 4; j++) {
                uint32_t v = (uint32_t)(((k16 * 16 + wn * 4 + j) * 32 + lane) * 2);
                uint2 t2 = *(const uint2*)(B + v);
                bf[j][0] = t2.x; bf[j][1] = t2.y;
            }
#pragma unroll
            for (int i = 0; i < 4; i++)
#pragma unroll
                for (int j = 0; j < 4; j++)
                    mma16816(acc[i][j], af[i], bf[j]);
        }
    };

    initAcc(t0);

    for (int s = 0; s < 8; s++) {
        if (s < 6)      { CP_WAIT(2); }
        else if (s == 6){ CP_WAIT(1); }
        else            { CP_WAIT(0); }
        __syncthreads();
        if (s + 3 < 8) { cpB(chunkPtr(s + 3), (s + 3) & 3); CP_COMMIT(); }
        mmaChunk(s & 3);
        if ((s & 3) == 3) {
            epilogue(t0 + (s >> 2));
            if ((s >> 2) < 1) initAcc(t0 + (s >> 2) + 1);
        }
    }
}

// ---------------- Proj GEMM + ext + ELU + residual + LayerNorm (21 stages) ----------------
__global__ __launch_bounds__(256, 2) void gemm_proj_ln(
    const uint32_t* __restrict__ gfr, const uint32_t* __restrict__ wvpf,
    const uint32_t* __restrict__ xf, const uint32_t* __restrict__ wff,
    const uint32_t* __restrict__ scf, const uint32_t* __restrict__ extf,
    const float* __restrict__ bias,
    const float* __restrict__ x, const float* __restrict__ gamma,
    const float* __restrict__ beta,
    float* __restrict__ out, uint32_t* __restrict__ xfo,
    __half* __restrict__ xho)
{
    extern __shared__ uint32_t smu[];
    uint32_t* As = smu;              // 4 x 2048
    uint32_t* Bs = smu + 8192;       // 4 x 2048
    const uint32_t As_a = cvta_sm(As);
    const uint32_t Bs_a = cvta_sm(Bs);

    const int tid = threadIdx.x;
    const int wid = tid >> 5;
    const int lane = tid & 31;
    const int slab = blockIdx.x;
    const int m0 = slab * 128;
    const int wm = wid >> 2;
    const int wn = wid & 3;

    auto cpStage = [&](int s1, int buf) {
        const uint32_t *Asrc, *Bsrc;
        if (s1 < 16) {
            Asrc = gfr + (size_t)slab * 32768 + (size_t)s1 * 2048;
            Bsrc = wvpf + (size_t)s1 * 2048;
        } else if (s1 < 20) {
            Asrc = xf + (size_t)slab * 8192 + (size_t)(s1 - 16) * 2048;
            Bsrc = wff + (size_t)(s1 - 16) * 2048;
        } else {
            Asrc = scf + (size_t)slab * 2048;
            Bsrc = extf;
        }
        uint32_t ab = As_a + buf * 2048 * 4;
        uint32_t bb = Bs_a + buf * 2048 * 4;
#pragma unroll
        for (int g = 0; g < 2; g++) {
            int o = (g * 256 + tid) * 4;
            cp16(ab + o * 4, Asrc + o);
            cp16(bb + o * 4, Bsrc + o);
        }
    };

    float acc[4][4][4];
    {
        const float* bp = bias + wn * 32;
#pragma unroll
        for (int j = 0; j < 4; j++) {
            float bv0 = __ldg(bp + j * 8 + 2 * (lane & 3));
            float bv1 = __ldg(bp + j * 8 + 2 * (lane & 3) + 1);
#pragma unroll
            for (int i = 0; i < 4; i++) {
                acc[i][j][0] = bv0; acc[i][j][1] = bv1;
                acc[i][j][2] = bv0; acc[i][j][3] = bv1;
            }
        }
    }

    cpStage(0, 0); CP_COMMIT();
    cpStage(1, 1); CP_COMMIT();
    cpStage(2, 2); CP_COMMIT();

    for (int s = 0; s < 21; s++) {
        if (s < 19)      { CP_WAIT(2); }
        else if (s == 19){ CP_WAIT(1); }
        else             { CP_WAIT(0); }
        __syncthreads();
        if (s + 3 < 21) { cpStage(s + 3, (s + 3) & 3); CP_COMMIT(); }
        {
            const uint32_t* Ac = As + (s & 3) * 2048;
            const uint32_t* Bc = Bs + (s & 3) * 2048;
#pragma unroll
            for (int k16 = 0; k16 < 2; k16++) {
                uint32_t af[4][4];
#pragma unroll
                for (int i = 0; i < 4; i++) {
                    uint32_t u = (uint32_t)(((k16 * 8 + wm * 4 + i) * 32 + lane) * 4);
                    uint4 t4 = *(const uint4*)(Ac + u);
                    af[i][0] = t4.x; af[i][1] = t4.y; af[i][2] = t4.z; af[i][3] = t4.w;
                }
                uint32_t bf[4][2];
#pragma unroll
                for (int j = 0; j < 4; j++) {
                    uint32_t v = (uint32_t)(((k16 * 16 + wn * 4 + j) * 32 + lane) * 2);
                    uint2 t2 = *(const uint2*)(Bc + v);
                    bf[j][0] = t2.x; bf[j][1] = t2.y;
                }
#pragma unroll
                for (int i = 0; i < 4; i++)
#pragma unroll
                    for (int j = 0; j < 4; j++)
                        mma16816(acc[i][j], af[i], bf[j]);
            }
        }
    }

    // ---- fused epilogue: elu(h) staged in smem [128][132], LN per row ----
    __syncthreads();
    float* ht = (float*)smu;
    {
        int col = wn * 32 + 2 * (lane & 3);
#pragma unroll
        for (int i = 0; i < 4; i++) {
            int r0 = wm * 64 + i * 16 + (lane >> 2);
#pragma unroll
            for (int j = 0; j < 4; j++) {
                float e0 = acc[i][j][0], e1 = acc[i][j][1];
                float e2 = acc[i][j][2], e3 = acc[i][j][3];
                ht[r0 * 132 + col + j * 8]           = e0 > 0.f ? e0 : expm1f(e0);
                ht[r0 * 132 + col + j * 8 + 1]       = e1 > 0.f ? e1 : expm1f(e1);
                ht[(r0 + 8) * 132 + col + j * 8]     = e2 > 0.f ? e2 : expm1f(e2);
                ht[(r0 + 8) * 132 + col + j * 8 + 1] = e3 > 0.f ? e3 : expm1f(e3);
            }
        }
    }
    __syncthreads();

    const float4 gv = *(const float4*)(gamma + lane * 4);
    const float4 bv = *(const float4*)(beta + lane * 4);
    __half* xfoh = (__half*)xfo;

#pragma unroll
    for (int r = 0; r < 16; r++) {
        int row = wid * 16 + r;
        int grow = m0 + row;
        float4 h4 = *(const float4*)(ht + row * 132 + lane * 4);
        float4 x4 = *(const float4*)(x + (size_t)grow * HIDD + lane * 4);
        float4 y;
        y.x = x4.x + h4.x; y.y = x4.y + h4.y;
        y.z = x4.z + h4.z; y.w = x4.w + h4.w;

        float sum = y.x + y.y + y.z + y.w;
        float sq  = y.x * y.x + y.y * y.y + y.z * y.z + y.w * y.w;
#pragma unroll
        for (int off = 16; off; off >>= 1) {
            sum += __shfl_xor_sync(0xffffffffu, sum, off);
            sq  += __shfl_xor_sync(0xffffffffu, sq, off);
        }
        float mu = sum * (1.f / 128.f);
        float var = sq * (1.f / 128.f) - mu * mu;
        float inv = rsqrtf(var + 1e-5f);

        float4 o;
        o.x = (y.x - mu) * inv * gv.x + bv.x;
        o.y = (y.y - mu) * inv * gv.y + bv.y;
        o.z = (y.z - mu) * inv * gv.z + bv.z;
        o.w = (y.w - mu) * inv * gv.w + bv.w;

        if (grow < NN)
            *(float4*)(out + (size_t)grow * HIDD + lane * 4) = o;

        if (xfo) {
            float vals[4] = {o.x, o.y, o.z, o.w};
            __half* dst = xfoh + (size_t)slab * 16384;
#pragma unroll
            for (int j = 0; j < 4; j++) {
                int k = lane * 4 + j;
                dst[(size_t)(k >> 5) * 4096 + aidx_h(row, k & 31)] = __float2half_rn(vals[j]);
            }
            uint2 packed;
            *(__half2*)&packed.x = __floats2half2_rn(o.x, o.y);
            *(__half2*)&packed.y = __floats2half2_rn(o.z, o.w);
            *(uint2*)(xho + (size_t)grow * HIDD + lane * 4) = packed;
        }
    }
}

// ---------------- Prep: Mstack = Wq_h @ Wk_h^T (frag), r bias ----------------
__global__ __launch_bounds__(128) void mstack_k(
    const float* __restrict__ Wq, const float* __restrict__ Wk,
    const float* __restrict__ bq, uint32_t* __restrict__ wtf, float* __restrict__ bt)
{
    __shared__ float sA[128];
    int i = blockIdx.x, h = blockIdx.y, l = blockIdx.z;
    int j = threadIdx.x;
    sA[j] = Wq[(size_t)l * 65536 + (size_t)i * HCC + h * 128 + j];
    __syncthreads();
    const float* wk = Wk + (size_t)l * 65536 + (size_t)j * HCC + h * 128;
    float s0 = 0.f, s1 = 0.f, s2 = 0.f, s3 = 0.f;
#pragma unroll 8
    for (int c = 0; c < 128; c += 4) {
        s0 = fmaf(sA[c],     wk[c],     s0);
        s1 = fmaf(sA[c + 1], wk[c + 1], s1);
        s2 = fmaf(sA[c + 2], wk[c + 2], s2);
        s3 = fmaf(sA[c + 3], wk[c + 3], s3);
    }
    float m = (s0 + s1) + (s2 + s3);
    __half* dh = (__half*)wtf;
    dh[(size_t)(l * 16 + h * 4 + (i >> 5)) * 4096 + bidx_h(i & 31, j)] = __float2half_rn(m);
    if (i == 0) {
        const float* bqh = bq + (size_t)l * HCC + h * 128;
        float r0 = 0.f, r1 = 0.f;
#pragma unroll 8
        for (int c = 0; c < 128; c += 2) {
            r0 = fmaf(bqh[c],     wk[c],     r0);
            r1 = fmaf(bqh[c + 1], wk[c + 1], r1);
        }
        bt[(size_t)l * HCC + h * 128 + j] = r0 + r1;
    }
}

// ---------------- Prep: WvP = Wv_h @ Wproj_h (frag) ----------------
__global__ __launch_bounds__(128) void wvp_k(
    const float* __restrict__ Wv, const float* __restrict__ Wproj,
    uint32_t* __restrict__ wvpf)
{
    __shared__ float sV[128];
    int i = blockIdx.x, h = blockIdx.y, l = blockIdx.z;
    int j = threadIdx.x;
    sV[j] = Wv[(size_t)l * 65536 + (size_t)i * HCC + h * 128 + j];
    __syncthreads();
    const float* wp = Wproj + (size_t)l * 65536 + (size_t)(h * 128) * HIDD + j;
    float s0 = 0.f, s1 = 0.f, s2 = 0.f, s3 = 0.f;
#pragma unroll 8
    for (int c = 0; c < 128; c += 4) {
        s0 = fmaf(sV[c],     wp[(size_t)c * HIDD],       s0);
        s1 = fmaf(sV[c + 1], wp[(size_t)(c + 1) * HIDD], s1);
        s2 = fmaf(sV[c + 2], wp[(size_t)(c + 2) * HIDD], s2);
        s3 = fmaf(sV[c + 3], wp[(size_t)(c + 3) * HIDD], s3);
    }
    float m = (s0 + s1) + (s2 + s3);
    __half* dh = (__half*)wvpf;
    dh[(size_t)(l * 16 + h * 4 + (i >> 5)) * 4096 + bidx_h(i & 31, j)] = __float2half_rn(m);
}

// ---------------- Prep: ext chunk rows 0..3 = bvP_h, 4..7 = WeP_h ----------------
__global__ void ext_k(const float* __restrict__ bv, const float* __restrict__ We,
                      const float* __restrict__ Wproj, uint32_t* __restrict__ extf)
{
    int r = blockIdx.x, l = blockIdx.y;     // r: 0..7
    int j = threadIdx.x;
    int h = r & 3;
    const float* vec = (r < 4) ? (bv + (size_t)l * HCC + h * 128)
                               : (We + (size_t)l * HCC + h * 128);
    const float* wp = Wproj + (size_t)l * 65536 + (size_t)(h * 128) * HIDD + j;
    float s0 = 0.f, s1 = 0.f;
#pragma unroll 8
    for (int c = 0; c < 128; c += 2) {
        s0 = fmaf(vec[c],     wp[(size_t)c * HIDD],       s0);
        s1 = fmaf(vec[c + 1], wp[(size_t)(c + 1) * HIDD], s1);
    }
    __half* dh = (__half*)extf;
    dh[(size_t)l * 4096 + bidx_h(r, j)] = __float2half_rn(s0 + s1);
}

// ---------------- Prep: u = Wq_h@bk_h, z = Wq_h@We_h, cq, cw ----------------
__global__ void vecs_k(const float* __restrict__ Wq, const float* __restrict__ bq,
                       const float* __restrict__ bk, const float* __restrict__ We,
                       float* __restrict__ uz, float* __restrict__ ccv)
{
    int h = blockIdx.x, l = blockIdx.y;
    int i = threadIdx.x;
    const float* wq = Wq + (size_t)l * 65536 + (size_t)i * HCC + h * 128;
    const float* bkh = bk + (size_t)l * HCC + h * 128;
    const float* weh = We + (size_t)l * HCC + h * 128;
    float u0 = 0.f, u1 = 0.f, z0 = 0.f, z1 = 0.f;
#pragma unroll 8
    for (int c = 0; c < 128; c += 2) {
        u0 = fmaf(wq[c], bkh[c], u0);     u1 = fmaf(wq[c + 1], bkh[c + 1], u1);
        z0 = fmaf(wq[c], weh[c], z0);     z1 = fmaf(wq[c + 1], weh[c + 1], z1);
    }
    uz[(size_t)l * 1024 + h * 128 + i] = u0 + u1;
    uz[(size_t)l * 1024 + 512 + h * 128 + i] = z0 + z1;
    if (i == 0) {
        const float* bqh = bq + (size_t)l * HCC + h * 128;
        float q1 = 0.f, q2 = 0.f;
        for (int c = 0; c < 128; c++) {
            q1 = fmaf(bqh[c], bkh[c], q1);
            q2 = fmaf(bqh[c], weh[c], q2);
        }
        ccv[l * 8 + h] = q1;
        ccv[l * 8 + 4 + h] = q2;
    }
}

// Wf = Wskip @ Wproj — coalesced
__global__ __launch_bounds__(512) void wf_k(const float* __restrict__ Wskip,
                                            const float* __restrict__ Wproj,
                                            uint32_t* __restrict__ wff)
{
    __shared__ float red[4][128];
    int i = blockIdx.x, l = blockIdx.y;
    int j = threadIdx.x & 127, q = threadIdx.x >> 7;
    const float* ws = Wskip + (size_t)l * HIDD * HCC + (size_t)i * HCC + q * 128;
    const float* wp = Wproj + (size_t)l * HCC * HIDD + (size_t)(q * 128) * HIDD + j;
    float s0 = 0.f, s1 = 0.f, s2 = 0.f, s3 = 0.f;
#pragma unroll 8
    for (int k = 0; k < 128; k += 4) {
        s0 = fmaf(ws[k],     wp[(size_t)k * HIDD],       s0);
        s1 = fmaf(ws[k + 1], wp[(size_t)(k + 1) * HIDD], s1);
        s2 = fmaf(ws[k + 2], wp[(size_t)(k + 2) * HIDD], s2);
        s3 = fmaf(ws[k + 3], wp[(size_t)(k + 3) * HIDD], s3);
    }
    red[q][j] = (s0 + s1) + (s2 + s3);
    __syncthreads();
    if (q == 0) {
        float s = red[0][j] + red[1][j] + red[2][j] + red[3][j];
        __half* dh = (__half*)wff;
        dh[(size_t)(l * 4 + (i >> 5)) * 4096 + bidx_h(i & 31, j)] = __float2half_rn(s);
    }
}

__global__ void bf_k(const float* __restrict__ bskip, const float* __restrict__ Wproj,
                     const float* __restrict__ bproj, float* __restrict__ bf)
{
    int l = blockIdx.x, j = threadIdx.x;
    const float* bs = bskip + (size_t)l * HCC;
    const float* wp = Wproj + (size_t)l * HCC * HIDD + j;
    float s0 = 0.f, s1 = 0.f, s2 = 0.f, s3 = 0.f;
#pragma unroll 8
    for (int k = 0; k < HCC; k += 4) {
        s0 = fmaf(bs[k],     wp[(size_t)k * HIDD],       s0);
        s1 = fmaf(bs[k + 1], wp[(size_t)(k + 1) * HIDD], s1);
        s2 = fmaf(bs[k + 2], wp[(size_t)(k + 2) * HIDD], s2);
        s3 = fmaf(bs[k + 3], wp[(size_t)(k + 3) * HIDD], s3);
    }
    bf[l * HIDD + j] = bproj[(size_t)l * HIDD + j] + (s0 + s1) + (s2 + s3);
}

// x_in -> frag order + row-major half (layer 0)
__global__ void init_xfrag_k(const float* __restrict__ x, uint32_t* __restrict__ xf,
                             __half* __restrict__ xh)
{
    int t = blockIdx.x * 256 + threadIdx.x;
    int row = t >> 5, lane = t & 31;
    float4 v = *(const float4*)(x + (size_t)row * HIDD + lane * 4);
    int slab = row >> 7, m = row & 127;
    float vals[4] = {v.x, v.y, v.z, v.w};
    __half* xfh = (__half*)xf;
#pragma unroll
    for (int j = 0; j < 4; j++) {
        int k = lane * 4 + j;
        xfh[(size_t)slab * 16384 + (size_t)(k >> 5) * 4096 + aidx_h(m, k & 31)] =
            __float2half_rn(vals[j]);
    }
    uint2 packed;
    *(__half2*)&packed.x = __floats2half2_rn(v.x, v.y);
    *(__half2*)&packed.y = __floats2half2_rn(v.z, v.w);
    *(uint2*)(xh + (size_t)row * HIDD + lane * 4) = packed;
}

// ---------------- CSR build ----------------
__global__ void hist_k(const int* __restrict__ dst, int* __restrict__ deg) {
    int e = blockIdx.x * 256 + threadIdx.x;
    if (e < EE) atomicAdd(deg + dst[e], 1);
}

__global__ void scanA_k(const int* __restrict__ deg, int* __restrict__ off,
                        int* __restrict__ blk) {
    __shared__ int sh[256];
    int t = threadIdx.x;
    int idx = blockIdx.x * 256 + t;
    int val = (idx < NN) ? deg[idx] : 0;
    sh[t] = val;
    __syncthreads();
#pragma unroll
    for (int d = 1; d < 256; d <<= 1) {
        int add = (t >= d) ? sh[t - d] : 0;
        __syncthreads();
        sh[t] += add;
        __syncthreads();
    }
    if (idx < NN) off[idx] = sh[t] - val;
    if (t == 255) blk[blockIdx.x] = sh[255];
}

__global__ void scanB_k(int* __restrict__ blk) {
    __shared__ int sh[256];
    int t = threadIdx.x;
    int val = (t < 196) ? blk[t] : 0;
    sh[t] = val;
    __syncthreads();
#pragma unroll
    for (int d = 1; d < 256; d <<= 1) {
        int add = (t >= d) ? sh[t - d] : 0;
        __syncthreads();
        sh[t] += add;
        __syncthreads();
    }
    if (t < 196) blk[t] = sh[t] - val;
}

__global__ void scanC_k(int* __restrict__ off, const int* __restrict__ blk,
                        int* __restrict__ cur) {
    int idx = blockIdx.x * 256 + threadIdx.x;
    if (idx < NN) {
        int o = off[idx] + blk[blockIdx.x];
        off[idx] = o;
        cur[idx] = o;
    }
    if (idx == 0) off[NN] = EE;
}

__global__ void scatter_k(const int* __restrict__ src, const int* __restrict__ dst,
                          const float* __restrict__ ea, int* __restrict__ cur,
                          int* __restrict__ srcs, float* __restrict__ eas) {
    int e = blockIdx.x * 256 + threadIdx.x;
    if (e < EE) {
        int p = atomicAdd(cur + dst[e], 1);
        srcs[p] = src[e];
        eas[p] = ea[e];
    }
}

// ---------------- Node-centric attention in x-space (warp per node) ----------------
__global__ __launch_bounds__(256) void attn_node_k(
    const __half* __restrict__ t, const __half* __restrict__ xh,
    const int* __restrict__ off, const int* __restrict__ srcs,
    const float* __restrict__ eas, const float* __restrict__ uz,
    const float* __restrict__ ccv, uint32_t* __restrict__ gf,
    uint32_t* __restrict__ scf)
{
    int d = blockIdx.x * 8 + (threadIdx.x >> 5);
    int lane = threadIdx.x & 31;

    int beg = __ldg(off + d), end = __ldg(off + d + 1);

    // t_d (16 floats) and x_d (4 floats)
    float tf[4][4];
#pragma unroll
    for (int h = 0; h < 4; h++) {
        uint2 raw = *(const uint2*)(t + (size_t)d * HCC + h * 128 + lane * 4);
        float2 a = __half22float2(*(__half2*)&raw.x);
        float2 b = __half22float2(*(__half2*)&raw.y);
        tf[h][0] = a.x; tf[h][1] = a.y; tf[h][2] = b.x; tf[h][3] = b.y;
    }
    float xd[4];
    {
        uint2 raw = *(const uint2*)(xh + (size_t)d * HIDD + lane * 4);
        float2 a = __half22float2(*(__half2*)&raw.x);
        float2 b = __half22float2(*(__half2*)&raw.y);
        xd[0] = a.x; xd[1] = a.y; xd[2] = b.x; xd[3] = b.y;
    }
    // s_[h] = x_d·u_h + cq_h ;  w_[h] = x_d·z_h + cw_h
    float s_[4], w_[4];
#pragma unroll
    for (int h = 0; h < 4; h++) {
        float4 u4 = *(const float4*)(uz + h * 128 + lane * 4);
        float4 z4 = *(const float4*)(uz + 512 + h * 128 + lane * 4);
        float su = xd[0] * u4.x + xd[1] * u4.y + xd[2] * u4.z + xd[3] * u4.w;
        float sz = xd[0] * z4.x + xd[1] * z4.y + xd[2] * z4.z + xd[3] * z4.w;
#pragma unroll
        for (int o = 16; o; o >>= 1) {
            su += __shfl_xor_sync(0xffffffffu, su, o);
            sz += __shfl_xor_sync(0xffffffffu, sz, o);
        }
        s_[h] = su + __ldg(ccv + h);
        w_[h] = sz + __ldg(ccv + 4 + h);
    }

    float g[4][4];
#pragma unroll
    for (int h = 0; h < 4; h++)
#pragma unroll
        for (int j = 0; j < 4; j++) g[h][j] = 0.f;
    float den[4] = {0.f, 0.f, 0.f, 0.f};
    float cs[4] = {0.f, 0.f, 0.f, 0.f};

    for (int i = beg; i < end; i++) {
        int sN = __ldg(srcs + i);
        float eav = __ldg(eas + i);
        uint2 raw = *(const uint2*)(xh + (size_t)sN * HIDD + lane * 4);
        float2 a = __half22float2(*(__half2*)&raw.x);
        float2 b = __half22float2(*(__half2*)&raw.y);
        float xs[4] = {a.x, a.y, b.x, b.y};
        float al[4];
#pragma unroll
        for (int h = 0; h < 4; h++) {
            float p = tf[h][0] * xs[0] + tf[h][1] * xs[1]
                    + tf[h][2] * xs[2] + tf[h][3] * xs[3];
#pragma unroll
            for (int o = 16; o; o >>= 1) p += __shfl_xor_sync(0xffffffffu, p, o);
            al[h] = p;
        }
#pragma unroll
        for (int h = 0; h < 4; h++) {
            float pv = expf((al[h] + s_[h] + eav * w_[h]) * 0.08838834764831845f);
            den[h] += pv;
            cs[h] += pv * eav;
            g[h][0] = fmaf(pv, xs[0], g[h][0]);
            g[h][1] = fmaf(pv, xs[1], g[h][1]);
            g[h][2] = fmaf(pv, xs[2], g[h][2]);
            g[h][3] = fmaf(pv, xs[3], g[h][3]);
        }
    }

    int slab = d >> 7, m = d & 127;
    __half* gb = (__half*)gf + (size_t)slab * 65536;
#pragma unroll
    for (int h = 0; h < 4; h++) {
        float inv = 1.f / (den[h] + 1e-16f);
#pragma unroll
        for (int j = 0; j < 4; j++) {
            int kk = h * 128 + lane * 4 + j;
            gb[(size_t)(kk >> 5) * 4096 + aidx_h(m, kk & 31)] =
                __float2half_rn(g[h][j] * inv);
        }
    }
    if (lane < 8) {
        int h = lane & 3;
        float inv = 1.f / (den[h] + 1e-16f);
        float val = (lane < 4) ? den[h] * inv : cs[h] * inv;
        __half* sb = (__half*)scf + (size_t)slab * 4096;
        sb[aidx_h(m, lane)] = __float2half_rn(val);
    }
}

// ---------------- host ----------------
extern "C" void kernel_launch(void* const* d_in, const int* in_sizes, int n_in,
                              void* d_out, int out_size)
{
    const float* x_in  = (const float*)d_in[0];
    const int*   ei    = (const int*)d_in[1];
    const float* ea    = (const float*)d_in[2];
    const float* Wq    = (const float*)d_in[3];
    const float* bq    = (const float*)d_in[4];
    const float* Wk    = (const float*)d_in[5];
    const float* bk    = (const float*)d_in[6];
    const float* Wv    = (const float*)d_in[7];
    const float* bv    = (const float*)d_in[8];
    const float* We    = (const float*)d_in[9];
    const float* Wskip = (const float*)d_in[10];
    const float* bskip = (const float*)d_in[11];
    const float* Wproj = (const float*)d_in[12];
    const float* bproj = (const float*)d_in[13];
    const float* gamma = (const float*)d_in[14];
    const float* beta  = (const float*)d_in[15];

    __half *t, *xh;
    float *xbuf, *bfv, *eas, *bt, *uz, *ccv;
    uint32_t *xf, *gf, *scf, *wtf, *wvpf, *extf, *wff;
    int *deg, *off, *cur, *blk, *srcs;
    cudaGetSymbolAddress((void**)&t,     g_t);
    cudaGetSymbolAddress((void**)&xh,    g_xh);
    cudaGetSymbolAddress((void**)&xbuf,  g_x);
    cudaGetSymbolAddress((void**)&xf,    g_xf);
    cudaGetSymbolAddress((void**)&gf,    g_gf);
    cudaGetSymbolAddress((void**)&scf,   g_scf);
    cudaGetSymbolAddress((void**)&wtf,   g_wtf);
    cudaGetSymbolAddress((void**)&wvpf,  g_wvpf);
    cudaGetSymbolAddress((void**)&extf,  g_extf);
    cudaGetSymbolAddress((void**)&wff,   g_wff);
    cudaGetSymbolAddress((void**)&bt,    g_bt);
    cudaGetSymbolAddress((void**)&uz,    g_uz);
    cudaGetSymbolAddress((void**)&ccv,   g_ccv);
    cudaGetSymbolAddress((void**)&bfv,   g_bf);
    cudaGetSymbolAddress((void**)&deg,   g_deg);
    cudaGetSymbolAddress((void**)&off,   g_off);
    cudaGetSymbolAddress((void**)&cur,   g_cur);
    cudaGetSymbolAddress((void**)&blk,   g_blk);
    cudaGetSymbolAddress((void**)&srcs,  g_srcs);
    cudaGetSymbolAddress((void**)&eas,   g_eas);

    cudaFuncSetAttribute(gemm_t_mma, cudaFuncAttributeMaxDynamicSharedMemorySize,
                         T_SMEM_B);
    cudaFuncSetAttribute(gemm_proj_ln, cudaFuncAttributeMaxDynamicSharedMemorySize,
                         PRJ_SMEM_B);

    const int* src = ei;
    const int* dst = ei + EE;

    cudaMemcpyAsync(xbuf, x_in, (size_t)NN * HIDD * sizeof(float),
                    cudaMemcpyDeviceToDevice);
    init_xfrag_k<<<(NN * 32) / 256, 256>>>(x_in, xf, xh);

    // weight prep
    mstack_k<<<dim3(128, 4, 3), 128>>>(Wq, Wk, bq, wtf, bt);
    wvp_k<<<dim3(128, 4, 3), 128>>>(Wv, Wproj, wvpf);
    ext_k<<<dim3(8, 3), 128>>>(bv, We, Wproj, extf);
    vecs_k<<<dim3(4, 3), 128>>>(Wq, bq, bk, We, uz, ccv);
    wf_k<<<dim3(128, 3), 512>>>(Wskip, Wproj, wff);
    bf_k<<<3, 128>>>(bskip, Wproj, bproj, bfv);

    // CSR
    cudaMemsetAsync(deg, 0, NN * sizeof(int));
    hist_k<<<(EE + 255) / 256, 256>>>(dst, deg);
    scanA_k<<<(NN + 255) / 256, 256>>>(deg, off, blk);
    scanB_k<<<1, 256>>>(blk);
    scanC_k<<<(NN + 255) / 256, 256>>>(off, blk, cur);
    scatter_k<<<(EE + 255) / 256, 256>>>(src, dst, ea, cur, srcs, eas);

    const int attnBlocks = NN / 8;       // 6250

    for (int l = 0; l < LLL; l++) {
        float* xo = (l == LLL - 1) ? (float*)d_out : xbuf;
        uint32_t* xfo = (l == LLL - 1) ? nullptr : xf;

        gemm_t_mma<<<dim3(2, NSLAB), 256, T_SMEM_B>>>(
            xf, wtf + (size_t)l * 16 * 2048, bt + (size_t)l * HCC, t);

        attn_node_k<<<attnBlocks, 256>>>(t, xh, off, srcs, eas,
                                         uz + (size_t)l * 1024, ccv + (size_t)l * 8,
                                         gf, scf);

        gemm_proj_ln<<<NSLAB, 256, PRJ_SMEM_B>>>(
            gf, wvpf + (size_t)l * 16 * 2048,
            xf, wff + (size_t)l * 8192,
            scf, extf + (size_t)l * 2048,
            bfv + l * HIDD,
            xbuf, gamma + l * HIDD, beta + l * HIDD,
            xo, xfo, xh);
    }
}

// round 16
// speedup vs baseline: 5.3266x; 1.2329x over previous
#include <cuda_runtime.h>
#include <cuda_bf16.h>
#include <cuda_fp16.h>
#include <math.h>
#include <stdint.h>

#define NN 50000
#define NPAD 50048          // 391 * 128
#define NSLAB 391
#define EE 100000
#define HIDD 128
#define HH 4
#define CCC 128
#define HCC 512
#define LLL 3

// ---------------- scratch ----------------
__device__ __half g_t[(size_t)NPAD * HCC];               // t = x@Mstack + r, row-major
__device__ __half g_xh[(size_t)NPAD * HIDD];             // x row-major half (gathers)
__device__ float g_x[(size_t)NPAD * HIDD];               // x fp32 (residual)
__device__ float g_wkt[(size_t)LLL * 4 * 128 * 128];     // Wk^T per (l,h)
// fragment-order fp16 buffers (uint32 views; 1 chunk = 2048 u32 = 4096 halves)
__device__ uint32_t g_xf[(size_t)NSLAB * 8192];          // x frag
__device__ uint32_t g_gf[(size_t)NSLAB * 32768];         // g frag (x-space agg)
__device__ uint32_t g_scf[(size_t)NSLAB * 2048];         // sa/cn ext chunk
__device__ uint32_t g_wtf[(size_t)LLL * 16 * 2048];      // Mstack frag
__device__ uint32_t g_wvpf[(size_t)LLL * 16 * 2048];     // Wv@Wproj frag
__device__ uint32_t g_extf[(size_t)LLL * 2048];          // [bvP;WeP] ext chunk
__device__ uint32_t g_wff[(size_t)LLL * 8192];           // Wskip@Wproj frag
__device__ float g_bt[(size_t)LLL * HCC];                // t bias (r)
__device__ float g_uz[(size_t)LLL * 1024];               // u[4][128], z[4][128]
__device__ float g_ccv[(size_t)LLL * 8];                 // cq[4], cw[4]
__device__ float g_bf[(size_t)LLL * HIDD];               // bproj + bskip@Wproj

// CSR
__device__ int   g_deg[NN];
__device__ int   g_off[NN + 1];
__device__ int   g_cur[NN];
__device__ int   g_blk[256];
__device__ int   g_srcs[EE];
__device__ float g_eas[EE];

__device__ __forceinline__ uint32_t cvta_sm(const void* p) {
    uint32_t a;
    asm("{ .reg .u64 t; cvta.to.shared.u64 t, %1; cvt.u32.u64 %0, t; }" : "=r"(a) : "l"(p));
    return a;
}
__device__ __forceinline__ void cp16(uint32_t smem, const void* g) {
    asm volatile("cp.async.cg.shared.global [%0], [%1], 16;" :: "r"(smem), "l"(g));
}
#define CP_COMMIT() asm volatile("cp.async.commit_group;" ::: "memory")
#define CP_WAIT(n)  asm volatile("cp.async.wait_group %0;" :: "n"(n) : "memory")

__device__ __forceinline__ void mma16816(float* d, const uint32_t* a, const uint32_t* b) {
    asm volatile("mma.sync.aligned.m16n8k16.row.col.f32.f16.f16.f32 "
        "{%0,%1,%2,%3}, {%4,%5,%6,%7}, {%8,%9}, {%0,%1,%2,%3};"
        : "+f"(d[0]), "+f"(d[1]), "+f"(d[2]), "+f"(d[3])
        : "r"(a[0]), "r"(a[1]), "r"(a[2]), "r"(a[3]), "r"(b[0]), "r"(b[1]));
}

// half-index within one A chunk (128m x 32k fp16)
__device__ __forceinline__ int aidx_h(int m, int kk) {
    int m_tile = m >> 4, r = m & 15;
    int k16 = kk >> 4, kw = kk & 15;
    int lane = (r & 7) * 4 + ((kw & 7) >> 1);
    int reg = ((kw >> 3) << 1) + (r >> 3);
    int u = ((k16 * 8 + m_tile) * 32 + lane) * 4 + reg;
    return u * 2 + (kw & 1);
}
// half-index within one B chunk (32k x 128n fp16)
__device__ __forceinline__ int bidx_h(int kk, int n) {
    int k16 = kk >> 4, kw = kk & 15;
    int n_tile = n >> 3, nn = n & 7;
    int tg = (kw & 7) >> 1;
    int lane = nn * 4 + tg;
    int reg = kw >> 3;
    int u = ((k16 * 16 + n_tile) * 32 + lane) * 2 + reg;
    return u * 2 + (kw & 1);
}

#define T_SMEM_B ((8192 + 4*2048) * 4)       // 65536
#define PRJ_SMEM_B (128 * 132 * 4)           // 67584

// ---------------- t GEMM: t = x@Mstack + r (fp16 mma, N-split x2, 8 stages) ----------------
__global__ __launch_bounds__(256, 2) void gemm_t_mma(
    const uint32_t* __restrict__ xf, const uint32_t* __restrict__ wt,
    const float* __restrict__ bt, __half* __restrict__ ot)
{
    extern __shared__ uint32_t smu[];
    uint32_t* As = smu;
    uint32_t* Bs = smu + 8192;
    const uint32_t As_a = cvta_sm(As);
    const uint32_t Bs_a = cvta_sm(Bs);

    const int tid = threadIdx.x;
    const int wid = tid >> 5;
    const int lane = tid & 31;
    const int m0 = blockIdx.y * 128;
    const int wm = wid >> 2;
    const int wn = wid & 3;
    const int t0 = blockIdx.x * 2;

    auto chunkPtr = [&](int s) {
        int tg = t0 + (s >> 2);
        return wt + (size_t)(tg * 4 + (s & 3)) * 2048;
    };
    auto cpB = [&](const uint32_t* chunk, int buf) {
        uint32_t base = Bs_a + buf * 2048 * 4;
#pragma unroll
        for (int g = 0; g < 2; g++) {
            int o = (g * 256 + tid) * 4;
            cp16(base + o * 4, chunk + o);
        }
    };

    {
        const uint32_t* asrc = xf + (size_t)blockIdx.y * 8192;
#pragma unroll
        for (int g = 0; g < 8; g++) {
            int o = (g * 256 + tid) * 4;
            cp16(As_a + o * 4, asrc + o);
        }
    }
    cpB(chunkPtr(0), 0); CP_COMMIT();
    cpB(chunkPtr(1), 1); CP_COMMIT();
    cpB(chunkPtr(2), 2); CP_COMMIT();

    float acc[4][4][4];
    auto initAcc = [&](int tg) {
        const float* bias = bt + tg * 128 + wn * 32;
#pragma unroll
        for (int j = 0; j < 4; j++) {
            float bv0 = __ldg(bias + j * 8 + 2 * (lane & 3));
            float bv1 = __ldg(bias + j * 8 + 2 * (lane & 3) + 1);
#pragma unroll
            for (int i = 0; i < 4; i++) {
                acc[i][j][0] = bv0; acc[i][j][1] = bv1;
                acc[i][j][2] = bv0; acc[i][j][3] = bv1;
            }
        }
    };
    auto epilogue = [&](int tg) {
        const int col = tg * 128 + wn * 32 + 2 * (lane & 3);
#pragma unroll
        for (int i = 0; i < 4; i++) {
            int row = m0 + wm * 64 + i * 16 + (lane >> 2);
#pragma unroll
            for (int j = 0; j < 4; j++) {
                *(__half2*)(ot + (size_t)row * HCC + col + j * 8) =
                    __floats2half2_rn(acc[i][j][0], acc[i][j][1]);
                *(__half2*)(ot + (size_t)(row + 8) * HCC + col + j * 8) =
                    __floats2half2_rn(acc[i][j][2], acc[i][j][3]);
            }
        }
    };
    auto mmaChunk = [&](int buf) {
        const uint32_t* B = Bs + buf * 2048;
        const uint32_t* Ac = As + buf * 2048;
#pragma unroll
        for (int k16 = 0; k16 < 2; k16++) {
            uint32_t af[4][4];
#pragma unroll
            for (int i = 0; i < 4; i++) {
                uint32_t u = (uint32_t)(((k16 * 8 + wm * 4 + i) * 32 + lane) * 4);
                uint4 t4 = *(const uint4*)(Ac + u);
                af[i][0] = t4.x; af[i][1] = t4.y; af[i][2] = t4.z; af[i][3] = t4.w;
            }
            uint32_t bf[4][2];
#pragma unroll
            for (int j = 0; j < 4; j++) {
                uint32_t v = (uint32_t)(((k16 * 16 + wn * 4 + j) * 32 + lane) * 2);
                uint2 t2 = *(const uint2*)(B + v);
                bf[j][0] = t2.x; bf[j][1] = t2.y;
            }
#pragma unroll
            for (int i = 0; i < 4; i++)
#pragma unroll
                for (int j = 0; j < 4; j++)
                    mma16816(acc[i][j], af[i], bf[j]);
        }
    };

    initAcc(t0);

    for (int s = 0; s < 8; s++) {
        if (s < 6)      { CP_WAIT(2); }
        else if (s == 6){ CP_WAIT(1); }
        else            { CP_WAIT(0); }
        __syncthreads();
        if (s + 3 < 8) { cpB(chunkPtr(s + 3), (s + 3) & 3); CP_COMMIT(); }
        mmaChunk(s & 3);
        if ((s & 3) == 3) {
            epilogue(t0 + (s >> 2));
            if ((s >> 2) < 1) initAcc(t0 + (s >> 2) + 1);
        }
    }
}

// ---------------- Proj GEMM + ext + ELU + residual + LayerNorm (21 stages) ----------------
__global__ __launch_bounds__(256, 2) void gemm_proj_ln(
    const uint32_t* __restrict__ gfr, const uint32_t* __restrict__ wvpf,
    const uint32_t* __restrict__ xf, const uint32_t* __restrict__ wff,
    const uint32_t* __restrict__ scf, const uint32_t* __restrict__ extf,
    const float* __restrict__ bias,
    const float* __restrict__ x, const float* __restrict__ gamma,
    const float* __restrict__ beta,
    float* __restrict__ out, uint32_t* __restrict__ xfo,
    __half* __restrict__ xho)
{
    extern __shared__ uint32_t smu[];
    uint32_t* As = smu;
    uint32_t* Bs = smu + 8192;
    const uint32_t As_a = cvta_sm(As);
    const uint32_t Bs_a = cvta_sm(Bs);

    const int tid = threadIdx.x;
    const int wid = tid >> 5;
    const int lane = tid & 31;
    const int slab = blockIdx.x;
    const int m0 = slab * 128;
    const int wm = wid >> 2;
    const int wn = wid & 3;

    auto cpStage = [&](int s1, int buf) {
        const uint32_t *Asrc, *Bsrc;
        if (s1 < 16) {
            Asrc = gfr + (size_t)slab * 32768 + (size_t)s1 * 2048;
            Bsrc = wvpf + (size_t)s1 * 2048;
        } else if (s1 < 20) {
            Asrc = xf + (size_t)slab * 8192 + (size_t)(s1 - 16) * 2048;
            Bsrc = wff + (size_t)(s1 - 16) * 2048;
        } else {
            Asrc = scf + (size_t)slab * 2048;
            Bsrc = extf;
        }
        uint32_t ab = As_a + buf * 2048 * 4;
        uint32_t bb = Bs_a + buf * 2048 * 4;
#pragma unroll
        for (int g = 0; g < 2; g++) {
            int o = (g * 256 + tid) * 4;
            cp16(ab + o * 4, Asrc + o);
            cp16(bb + o * 4, Bsrc + o);
        }
    };

    float acc[4][4][4];
    {
        const float* bp = bias + wn * 32;
#pragma unroll
        for (int j = 0; j < 4; j++) {
            float bv0 = __ldg(bp + j * 8 + 2 * (lane & 3));
            float bv1 = __ldg(bp + j * 8 + 2 * (lane & 3) + 1);
#pragma unroll
            for (int i = 0; i < 4; i++) {
                acc[i][j][0] = bv0; acc[i][j][1] = bv1;
                acc[i][j][2] = bv0; acc[i][j][3] = bv1;
            }
        }
    }

    cpStage(0, 0); CP_COMMIT();
    cpStage(1, 1); CP_COMMIT();
    cpStage(2, 2); CP_COMMIT();

    for (int s = 0; s < 21; s++) {
        if (s < 19)      { CP_WAIT(2); }
        else if (s == 19){ CP_WAIT(1); }
        else             { CP_WAIT(0); }
        __syncthreads();
        if (s + 3 < 21) { cpStage(s + 3, (s + 3) & 3); CP_COMMIT(); }
        {
            const uint32_t* Ac = As + (s & 3) * 2048;
            const uint32_t* Bc = Bs + (s & 3) * 2048;
#pragma unroll
            for (int k16 = 0; k16 < 2; k16++) {
                uint32_t af[4][4];
#pragma unroll
                for (int i = 0; i < 4; i++) {
                    uint32_t u = (uint32_t)(((k16 * 8 + wm * 4 + i) * 32 + lane) * 4);
                    uint4 t4 = *(const uint4*)(Ac + u);
                    af[i][0] = t4.x; af[i][1] = t4.y; af[i][2] = t4.z; af[i][3] = t4.w;
                }
                uint32_t bf[4][2];
#pragma unroll
                for (int j = 0; j < 4; j++) {
                    uint32_t v = (uint32_t)(((k16 * 16 + wn * 4 + j) * 32 + lane) * 2);
                    uint2 t2 = *(const uint2*)(Bc + v);
                    bf[j][0] = t2.x; bf[j][1] = t2.y;
                }
#pragma unroll
                for (int i = 0; i < 4; i++)
#pragma unroll
                    for (int j = 0; j < 4; j++)
                        mma16816(acc[i][j], af[i], bf[j]);
            }
        }
    }

    // ---- fused epilogue: elu(h) staged in smem [128][132], LN per row ----
    __syncthreads();
    float* ht = (float*)smu;
    {
        int col = wn * 32 + 2 * (lane & 3);
#pragma unroll
        for (int i = 0; i < 4; i++) {
            int r0 = wm * 64 + i * 16 + (lane >> 2);
#pragma unroll
            for (int j = 0; j < 4; j++) {
                float e0 = acc[i][j][0], e1 = acc[i][j][1];
                float e2 = acc[i][j][2], e3 = acc[i][j][3];
                ht[r0 * 132 + col + j * 8]           = e0 > 0.f ? e0 : expm1f(e0);
                ht[r0 * 132 + col + j * 8 + 1]       = e1 > 0.f ? e1 : expm1f(e1);
                ht[(r0 + 8) * 132 + col + j * 8]     = e2 > 0.f ? e2 : expm1f(e2);
                ht[(r0 + 8) * 132 + col + j * 8 + 1] = e3 > 0.f ? e3 : expm1f(e3);
            }
        }
    }
    __syncthreads();

    const float4 gv = *(const float4*)(gamma + lane * 4);
    const float4 bv = *(const float4*)(beta + lane * 4);
    __half* xfoh = (__half*)xfo;

#pragma unroll
    for (int r = 0; r < 16; r++) {
        int row = wid * 16 + r;
        int grow = m0 + row;
        float4 h4 = *(const float4*)(ht + row * 132 + lane * 4);
        float4 x4 = *(const float4*)(x + (size_t)grow * HIDD + lane * 4);
        float4 y;
        y.x = x4.x + h4.x; y.y = x4.y + h4.y;
        y.z = x4.z + h4.z; y.w = x4.w + h4.w;

        float sum = y.x + y.y + y.z + y.w;
        float sq  = y.x * y.x + y.y * y.y + y.z * y.z + y.w * y.w;
#pragma unroll
        for (int off = 16; off; off >>= 1) {
            sum += __shfl_xor_sync(0xffffffffu, sum, off);
            sq  += __shfl_xor_sync(0xffffffffu, sq, off);
        }
        float mu = sum * (1.f / 128.f);
        float var = sq * (1.f / 128.f) - mu * mu;
        float inv = rsqrtf(var + 1e-5f);

        float4 o;
        o.x = (y.x - mu) * inv * gv.x + bv.x;
        o.y = (y.y - mu) * inv * gv.y + bv.y;
        o.z = (y.z - mu) * inv * gv.z + bv.z;
        o.w = (y.w - mu) * inv * gv.w + bv.w;

        if (grow < NN)
            *(float4*)(out + (size_t)grow * HIDD + lane * 4) = o;

        if (xfo) {
            float vals[4] = {o.x, o.y, o.z, o.w};
            __half* dst = xfoh + (size_t)slab * 16384;
#pragma unroll
            for (int j = 0; j < 4; j++) {
                int k = lane * 4 + j;
                dst[(size_t)(k >> 5) * 4096 + aidx_h(row, k & 31)] = __float2half_rn(vals[j]);
            }
            uint2 packed;
            *(__half2*)&packed.x = __floats2half2_rn(o.x, o.y);
            *(__half2*)&packed.y = __floats2half2_rn(o.z, o.w);
            *(uint2*)(xho + (size_t)grow * HIDD + lane * 4) = packed;
        }
    }
}

// ---------------- Prep: Wk transpose (smem tiled) ----------------
__global__ __launch_bounds__(256) void wkT_k(const float* __restrict__ Wk,
                                             float* __restrict__ wkt)
{
    __shared__ float tile[32][33];
    int bj = blockIdx.x & 3, bc = blockIdx.x >> 2;
    int h = blockIdx.y, l = blockIdx.z;
    int tx = threadIdx.x & 31, ty = threadIdx.x >> 5;
#pragma unroll
    for (int k = 0; k < 4; k++) {
        int j = bj * 32 + ty + k * 8;
        tile[ty + k * 8][tx] =
            Wk[(size_t)l * 65536 + (size_t)j * HCC + h * 128 + bc * 32 + tx];
    }
    __syncthreads();
#pragma unroll
    for (int k = 0; k < 4; k++) {
        int c = bc * 32 + ty + k * 8;
        wkt[((size_t)(l * 4 + h) * 128 + c) * 128 + bj * 32 + tx] = tile[tx][ty + k * 8];
    }
}

// ---------------- Prep: Mstack = Wq_h @ Wk_h^T (coalesced via wkt) ----------------
__global__ __launch_bounds__(512) void mstack_k(
    const float* __restrict__ Wq, const float* __restrict__ wkt,
    uint32_t* __restrict__ wtf)
{
    __shared__ float sA[128];
    __shared__ float red[4][128];
    int i = blockIdx.x, h = blockIdx.y, l = blockIdx.z;
    int j = threadIdx.x & 127, q = threadIdx.x >> 7;
    if (threadIdx.x < 128)
        sA[threadIdx.x] = Wq[(size_t)l * 65536 + (size_t)i * HCC + h * 128 + threadIdx.x];
    __syncthreads();
    const float* wk = wkt + ((size_t)(l * 4 + h) * 128 + q * 32) * 128 + j;
    float s0 = 0.f, s1 = 0.f, s2 = 0.f, s3 = 0.f;
#pragma unroll 8
    for (int c = 0; c < 32; c += 4) {
        s0 = fmaf(sA[q * 32 + c],     wk[(size_t)c * 128],       s0);
        s1 = fmaf(sA[q * 32 + c + 1], wk[(size_t)(c + 1) * 128], s1);
        s2 = fmaf(sA[q * 32 + c + 2], wk[(size_t)(c + 2) * 128], s2);
        s3 = fmaf(sA[q * 32 + c + 3], wk[(size_t)(c + 3) * 128], s3);
    }
    red[q][j] = (s0 + s1) + (s2 + s3);
    __syncthreads();
    if (q == 0) {
        float m = red[0][j] + red[1][j] + red[2][j] + red[3][j];
        __half* dh = (__half*)wtf;
        dh[(size_t)(l * 16 + h * 4 + (i >> 5)) * 4096 + bidx_h(i & 31, j)] =
            __float2half_rn(m);
    }
}

// ---------------- Prep: WvP = Wv_h @ Wproj_h (c-split x4) ----------------
__global__ __launch_bounds__(512) void wvp_k(
    const float* __restrict__ Wv, const float* __restrict__ Wproj,
    uint32_t* __restrict__ wvpf)
{
    __shared__ float sV[128];
    __shared__ float red[4][128];
    int i = blockIdx.x, h = blockIdx.y, l = blockIdx.z;
    int j = threadIdx.x & 127, q = threadIdx.x >> 7;
    if (threadIdx.x < 128)
        sV[threadIdx.x] = Wv[(size_t)l * 65536 + (size_t)i * HCC + h * 128 + threadIdx.x];
    __syncthreads();
    const float* wp = Wproj + (size_t)l * 65536 + (size_t)(h * 128 + q * 32) * HIDD + j;
    float s0 = 0.f, s1 = 0.f, s2 = 0.f, s3 = 0.f;
#pragma unroll 8
    for (int c = 0; c < 32; c += 4) {
        s0 = fmaf(sV[q * 32 + c],     wp[(size_t)c * HIDD],       s0);
        s1 = fmaf(sV[q * 32 + c + 1], wp[(size_t)(c + 1) * HIDD], s1);
        s2 = fmaf(sV[q * 32 + c + 2], wp[(size_t)(c + 2) * HIDD], s2);
        s3 = fmaf(sV[q * 32 + c + 3], wp[(size_t)(c + 3) * HIDD], s3);
    }
    red[q][j] = (s0 + s1) + (s2 + s3);
    __syncthreads();
    if (q == 0) {
        float m = red[0][j] + red[1][j] + red[2][j] + red[3][j];
        __half* dh = (__half*)wvpf;
        dh[(size_t)(l * 16 + h * 4 + (i >> 5)) * 4096 + bidx_h(i & 31, j)] =
            __float2half_rn(m);
    }
}

// ---------------- Prep: vec dots (warp per output): u, z, bt, cq/cw ----------------
// warps: [0,1536) u | [1536,3072) z | [3072,4608) bt | [4608,4632) cc
__global__ __launch_bounds__(256) void prep_vec_k(
    const float* __restrict__ Wq, const float* __restrict__ Wk,
    const float* __restrict__ bq, const float* __restrict__ bk,
    const float* __restrict__ We, float* __restrict__ uz,
    float* __restrict__ bt, float* __restrict__ ccv)
{
    int w = blockIdx.x * 8 + (threadIdx.x >> 5);
    int lane = threadIdx.x & 31;
    if (w >= 4632) return;

    float s = 0.f;
    if (w < 3072) {
        int kind, idx;
        if (w < 1536) { kind = 0; idx = w; }
        else          { kind = 1; idx = w - 1536; }
        int l = idx >> 9, hi = idx & 511;
        int h = hi >> 7, i = hi & 127;
        const float* row = Wq + (size_t)l * 65536 + (size_t)i * HCC + h * 128 + lane * 4;
        const float* vec = ((kind == 0) ? bk : We) + (size_t)l * HCC + h * 128 + lane * 4;
        float4 r4 = *(const float4*)row;
        float4 v4 = *(const float4*)vec;
        s = r4.x * v4.x + r4.y * v4.y + r4.z * v4.z + r4.w * v4.w;
#pragma unroll
        for (int o = 16; o; o >>= 1) s += __shfl_xor_sync(0xffffffffu, s, o);
        if (lane == 0)
            uz[(size_t)l * 1024 + kind * 512 + h * 128 + i] = s;
    } else if (w < 4608) {
        int idx = w - 3072;
        int l = idx >> 9, hj = idx & 511;
        int h = hj >> 7, j = hj & 127;
        const float* row = Wk + (size_t)l * 65536 + (size_t)j * HCC + h * 128 + lane * 4;
        const float* vec = bq + (size_t)l * HCC + h * 128 + lane * 4;
        float4 r4 = *(const float4*)row;
        float4 v4 = *(const float4*)vec;
        s = r4.x * v4.x + r4.y * v4.y + r4.z * v4.z + r4.w * v4.w;
#pragma unroll
        for (int o = 16; o; o >>= 1) s += __shfl_xor_sync(0xffffffffu, s, o);
        if (lane == 0)
            bt[(size_t)l * HCC + h * 128 + j] = s;
    } else {
        int idx = w - 4608;                  // idx = l*8 + r, r = (cw?4:0)+h
        int l = idx >> 3;
        int r = idx & 7;
        int h = r & 3;
        const float* bqh = bq + (size_t)l * HCC + h * 128 + lane * 4;
        const float* vec = ((r < 4) ? bk : We) + (size_t)l * HCC + h * 128 + lane * 4;
        float4 a4 = *(const float4*)bqh;
        float4 v4 = *(const float4*)vec;
        s = a4.x * v4.x + a4.y * v4.y + a4.z * v4.z + a4.w * v4.w;
#pragma unroll
        for (int o = 16; o; o >>= 1) s += __shfl_xor_sync(0xffffffffu, s, o);
        if (lane == 0)
            ccv[l * 8 + r] = s;
    }
}

// ---------------- Prep: ext chunk + bf (c-split x4) ----------------
// blockIdx.x: 0..7 -> ext rows (bvP / WeP); 8 -> bf
__global__ __launch_bounds__(512) void prep_mat_k(
    const float* __restrict__ bv, const float* __restrict__ We,
    const float* __restrict__ bskip, const float* __restrict__ bproj,
    const float* __restrict__ Wproj,
    uint32_t* __restrict__ extf, float* __restrict__ bf)
{
    __shared__ float red[4][128];
    int r = blockIdx.x, l = blockIdx.y;
    int j = threadIdx.x & 127, q = threadIdx.x >> 7;

    if (r < 8) {
        int h = r & 3;
        const float* vec = ((r < 4) ? bv : We) + (size_t)l * HCC + h * 128 + q * 32;
        const float* wp = Wproj + (size_t)l * 65536 + (size_t)(h * 128 + q * 32) * HIDD + j;
        float s0 = 0.f, s1 = 0.f, s2 = 0.f, s3 = 0.f;
#pragma unroll 8
        for (int c = 0; c < 32; c += 4) {
            s0 = fmaf(vec[c],     wp[(size_t)c * HIDD],       s0);
            s1 = fmaf(vec[c + 1], wp[(size_t)(c + 1) * HIDD], s1);
            s2 = fmaf(vec[c + 2], wp[(size_t)(c + 2) * HIDD], s2);
            s3 = fmaf(vec[c + 3], wp[(size_t)(c + 3) * HIDD], s3);
        }
        red[q][j] = (s0 + s1) + (s2 + s3);
        __syncthreads();
        if (q == 0) {
            float s = red[0][j] + red[1][j] + red[2][j] + red[3][j];
            __half* dh = (__half*)extf;
            dh[(size_t)l * 4096 + bidx_h(r, j)] = __float2half_rn(s);
        }
    } else {
        const float* bs = bskip + (size_t)l * HCC + q * 128;
        const float* wp = Wproj + (size_t)l * 65536 + (size_t)(q * 128) * HIDD + j;
        float s0 = 0.f, s1 = 0.f, s2 = 0.f, s3 = 0.f;
#pragma unroll 8
        for (int c = 0; c < 128; c += 4) {
            s0 = fmaf(bs[c],     wp[(size_t)c * HIDD],       s0);
            s1 = fmaf(bs[c + 1], wp[(size_t)(c + 1) * HIDD], s1);
            s2 = fmaf(bs[c + 2], wp[(size_t)(c + 2) * HIDD], s2);
            s3 = fmaf(bs[c + 3], wp[(size_t)(c + 3) * HIDD], s3);
        }
        red[q][j] = (s0 + s1) + (s2 + s3);
        __syncthreads();
        if (q == 0)
            bf[l * HIDD + j] = bproj[(size_t)l * HIDD + j] +
                               red[0][j] + red[1][j] + red[2][j] + red[3][j];
    }
}

// Wf = Wskip @ Wproj — coalesced
__global__ __launch_bounds__(512) void wf_k(const float* __restrict__ Wskip,
                                            const float* __restrict__ Wproj,
                                            uint32_t* __restrict__ wff)
{
    __shared__ float red[4][128];
    int i = blockIdx.x, l = blockIdx.y;
    int j = threadIdx.x & 127, q = threadIdx.x >> 7;
    const float* ws = Wskip + (size_t)l * HIDD * HCC + (size_t)i * HCC + q * 128;
    const float* wp = Wproj + (size_t)l * HCC * HIDD + (size_t)(q * 128) * HIDD + j;
    float s0 = 0.f, s1 = 0.f, s2 = 0.f, s3 = 0.f;
#pragma unroll 8
    for (int k = 0; k < 128; k += 4) {
        s0 = fmaf(ws[k],     wp[(size_t)k * HIDD],       s0);
        s1 = fmaf(ws[k + 1], wp[(size_t)(k + 1) * HIDD], s1);
        s2 = fmaf(ws[k + 2], wp[(size_t)(k + 2) * HIDD], s2);
        s3 = fmaf(ws[k + 3], wp[(size_t)(k + 3) * HIDD], s3);
    }
    red[q][j] = (s0 + s1) + (s2 + s3);
    __syncthreads();
    if (q == 0) {
        float s = red[0][j] + red[1][j] + red[2][j] + red[3][j];
        __half* dh = (__half*)wff;
        dh[(size_t)(l * 4 + (i >> 5)) * 4096 + bidx_h(i & 31, j)] = __float2half_rn(s);
    }
}

// x_in -> frag order + row-major half + fp32 copy (layer 0)
__global__ void init_xfrag_k(const float* __restrict__ x, uint32_t* __restrict__ xf,
                             __half* __restrict__ xh, float* __restrict__ xc)
{
    int t = blockIdx.x * 256 + threadIdx.x;
    int row = t >> 5, lane = t & 31;
    float4 v = *(const float4*)(x + (size_t)row * HIDD + lane * 4);
    int slab = row >> 7, m = row & 127;
    float vals[4] = {v.x, v.y, v.z, v.w};
    __half* xfh = (__half*)xf;
#pragma unroll
    for (int j = 0; j < 4; j++) {
        int k = lane * 4 + j;
        xfh[(size_t)slab * 16384 + (size_t)(k >> 5) * 4096 + aidx_h(m, k & 31)] =
            __float2half_rn(vals[j]);
    }
    uint2 packed;
    *(__half2*)&packed.x = __floats2half2_rn(v.x, v.y);
    *(__half2*)&packed.y = __floats2half2_rn(v.z, v.w);
    *(uint2*)(xh + (size_t)row * HIDD + lane * 4) = packed;
    *(float4*)(xc + (size_t)row * HIDD + lane * 4) = v;
}

// ---------------- CSR build ----------------
__global__ void hist_k(const int* __restrict__ dst, int* __restrict__ deg) {
    int e = blockIdx.x * 256 + threadIdx.x;
    if (e < EE) atomicAdd(deg + dst[e], 1);
}

__global__ void scanA_k(const int* __restrict__ deg, int* __restrict__ off,
                        int* __restrict__ blk) {
    __shared__ int sh[256];
    int t = threadIdx.x;
    int idx = blockIdx.x * 256 + t;
    int val = (idx < NN) ? deg[idx] : 0;
    sh[t] = val;
    __syncthreads();
#pragma unroll
    for (int d = 1; d < 256; d <<= 1) {
        int add = (t >= d) ? sh[t - d] : 0;
        __syncthreads();
        sh[t] += add;
        __syncthreads();
    }
    if (idx < NN) off[idx] = sh[t] - val;
    if (t == 255) blk[blockIdx.x] = sh[255];
}

__global__ void scanB_k(int* __restrict__ blk) {
    __shared__ int sh[256];
    int t = threadIdx.x;
    int val = (t < 196) ? blk[t] : 0;
    sh[t] = val;
    __syncthreads();
#pragma unroll
    for (int d = 1; d < 256; d <<= 1) {
        int add = (t >= d) ? sh[t - d] : 0;
        __syncthreads();
        sh[t] += add;
        __syncthreads();
    }
    if (t < 196) blk[t] = sh[t] - val;
}

__global__ void scanC_k(int* __restrict__ off, const int* __restrict__ blk,
                        int* __restrict__ cur) {
    int idx = blockIdx.x * 256 + threadIdx.x;
    if (idx < NN) {
        int o = off[idx] + blk[blockIdx.x];
        off[idx] = o;
        cur[idx] = o;
    }
    if (idx == 0) off[NN] = EE;
}

__global__ void scatter_k(const int* __restrict__ src, const int* __restrict__ dst,
                          const float* __restrict__ ea, int* __restrict__ cur,
                          int* __restrict__ srcs, float* __restrict__ eas) {
    int e = blockIdx.x * 256 + threadIdx.x;
    if (e < EE) {
        int p = atomicAdd(cur + dst[e], 1);
        srcs[p] = src[e];
        eas[p] = ea[e];
    }
}

// ---------------- Node-centric attention in x-space (warp per node) ----------------
__global__ __launch_bounds__(256) void attn_node_k(
    const __half* __restrict__ t, const __half* __restrict__ xh,
    const int* __restrict__ off, const int* __restrict__ srcs,
    const float* __restrict__ eas, const float* __restrict__ uz,
    const float* __restrict__ ccv, uint32_t* __restrict__ gf,
    uint32_t* __restrict__ scf)
{
    int d = blockIdx.x * 8 + (threadIdx.x >> 5);
    int lane = threadIdx.x & 31;

    int beg = __ldg(off + d), end = __ldg(off + d + 1);

    float tf[4][4];
#pragma unroll
    for (int h = 0; h < 4; h++) {
        uint2 raw = *(const uint2*)(t + (size_t)d * HCC + h * 128 + lane * 4);
        float2 a = __half22float2(*(__half2*)&raw.x);
        float2 b = __half22float2(*(__half2*)&raw.y);
        tf[h][0] = a.x; tf[h][1] = a.y; tf[h][2] = b.x; tf[h][3] = b.y;
    }
    float xd[4];
    {
        uint2 raw = *(const uint2*)(xh + (size_t)d * HIDD + lane * 4);
        float2 a = __half22float2(*(__half2*)&raw.x);
        float2 b = __half22float2(*(__half2*)&raw.y);
        xd[0] = a.x; xd[1] = a.y; xd[2] = b.x; xd[3] = b.y;
    }
    float s_[4], w_[4];
#pragma unroll
    for (int h = 0; h < 4; h++) {
        float4 u4 = *(const float4*)(uz + h * 128 + lane * 4);
        float4 z4 = *(const float4*)(uz + 512 + h * 128 + lane * 4);
        float su = xd[0] * u4.x + xd[1] * u4.y + xd[2] * u4.z + xd[3] * u4.w;
        float sz = xd[0] * z4.x + xd[1] * z4.y + xd[2] * z4.z + xd[3] * z4.w;
#pragma unroll
        for (int o = 16; o; o >>= 1) {
            su += __shfl_xor_sync(0xffffffffu, su, o);
            sz += __shfl_xor_sync(0xffffffffu, sz, o);
        }
        s_[h] = su + __ldg(ccv + h);
        w_[h] = sz + __ldg(ccv + 4 + h);
    }

    float g[4][4];
#pragma unroll
    for (int h = 0; h < 4; h++)
#pragma unroll
        for (int j = 0; j < 4; j++) g[h][j] = 0.f;
    float den[4] = {0.f, 0.f, 0.f, 0.f};
    float cs[4] = {0.f, 0.f, 0.f, 0.f};

    for (int i = beg; i < end; i++) {
        int sN = __ldg(srcs + i);
        float eav = __ldg(eas + i);
        uint2 raw = *(const uint2*)(xh + (size_t)sN * HIDD + lane * 4);
        float2 a = __half22float2(*(__half2*)&raw.x);
        float2 b = __half22float2(*(__half2*)&raw.y);
        float xs[4] = {a.x, a.y, b.x, b.y};
        float al[4];
#pragma unroll
        for (int h = 0; h < 4; h++) {
            float p = tf[h][0] * xs[0] + tf[h][1] * xs[1]
                    + tf[h][2] * xs[2] + tf[h][3] * xs[3];
#pragma unroll
            for (int o = 16; o; o >>= 1) p += __shfl_xor_sync(0xffffffffu, p, o);
            al[h] = p;
        }
#pragma unroll
        for (int h = 0; h < 4; h++) {
            float pv = expf((al[h] + s_[h] + eav * w_[h]) * 0.08838834764831845f);
            den[h] += pv;
            cs[h] += pv * eav;
            g[h][0] = fmaf(pv, xs[0], g[h][0]);
            g[h][1] = fmaf(pv, xs[1], g[h][1]);
            g[h][2] = fmaf(pv, xs[2], g[h][2]);
            g[h][3] = fmaf(pv, xs[3], g[h][3]);
        }
    }

    int slab = d >> 7, m = d & 127;
    __half* gb = (__half*)gf + (size_t)slab * 65536;
#pragma unroll
    for (int h = 0; h < 4; h++) {
        float inv = 1.f / (den[h] + 1e-16f);
#pragma unroll
        for (int j = 0; j < 4; j++) {
            int kk = h * 128 + lane * 4 + j;
            gb[(size_t)(kk >> 5) * 4096 + aidx_h(m, kk & 31)] =
                __float2half_rn(g[h][j] * inv);
        }
    }
    if (lane < 8) {
        int h = lane & 3;
        float inv = 1.f / (den[h] + 1e-16f);
        float val = (lane < 4) ? den[h] * inv : cs[h] * inv;
        __half* sb = (__half*)scf + (size_t)slab * 4096;
        sb[aidx_h(m, lane)] = __float2half_rn(val);
    }
}

// ---------------- host ----------------
extern "C" void kernel_launch(void* const* d_in, const int* in_sizes, int n_in,
                              void* d_out, int out_size)
{
    const float* x_in  = (const float*)d_in[0];
    const int*   ei    = (const int*)d_in[1];
    const float* ea    = (const float*)d_in[2];
    const float* Wq    = (const float*)d_in[3];
    const float* bq    = (const float*)d_in[4];
    const float* Wk    = (const float*)d_in[5];
    const float* bk    = (const float*)d_in[6];
    const float* Wv    = (const float*)d_in[7];
    const float* bv    = (const float*)d_in[8];
    const float* We    = (const float*)d_in[9];
    const float* Wskip = (const float*)d_in[10];
    const float* bskip = (const float*)d_in[11];
    const float* Wproj = (const float*)d_in[12];
    const float* bproj = (const float*)d_in[13];
    const float* gamma = (const float*)d_in[14];
    const float* beta  = (const float*)d_in[15];

    __half *t, *xh;
    float *xbuf, *bfv, *eas, *bt, *uz, *ccv, *wkt;
    uint32_t *xf, *gf, *scf, *wtf, *wvpf, *extf, *wff;
    int *deg, *off, *cur, *blk, *srcs;
    cudaGetSymbolAddress((void**)&t,     g_t);
    cudaGetSymbolAddress((void**)&xh,    g_xh);
    cudaGetSymbolAddress((void**)&xbuf,  g_x);
    cudaGetSymbolAddress((void**)&wkt,   g_wkt);
    cudaGetSymbolAddress((void**)&xf,    g_xf);
    cudaGetSymbolAddress((void**)&gf,    g_gf);
    cudaGetSymbolAddress((void**)&scf,   g_scf);
    cudaGetSymbolAddress((void**)&wtf,   g_wtf);
    cudaGetSymbolAddress((void**)&wvpf,  g_wvpf);
    cudaGetSymbolAddress((void**)&extf,  g_extf);
    cudaGetSymbolAddress((void**)&wff,   g_wff);
    cudaGetSymbolAddress((void**)&bt,    g_bt);
    cudaGetSymbolAddress((void**)&uz,    g_uz);
    cudaGetSymbolAddress((void**)&ccv,   g_ccv);
    cudaGetSymbolAddress((void**)&bfv,   g_bf);
    cudaGetSymbolAddress((void**)&deg,   g_deg);
    cudaGetSymbolAddress((void**)&off,   g_off);
    cudaGetSymbolAddress((void**)&cur,   g_cur);
    cudaGetSymbolAddress((void**)&blk,   g_blk);
    cudaGetSymbolAddress((void**)&srcs,  g_srcs);
    cudaGetSymbolAddress((void**)&eas,   g_eas);

    cudaFuncSetAttribute(gemm_t_mma, cudaFuncAttributeMaxDynamicSharedMemorySize,
                         T_SMEM_B);
    cudaFuncSetAttribute(gemm_proj_ln, cudaFuncAttributeMaxDynamicSharedMemorySize,
                         PRJ_SMEM_B);

    const int* src = ei;
    const int* dst = ei + EE;

    init_xfrag_k<<<(NN * 32) / 256, 256>>>(x_in, xf, xh, xbuf);

    // weight prep (parallel-friendly)
    wkT_k<<<dim3(16, 4, 3), 256>>>(Wk, wkt);
    mstack_k<<<dim3(128, 4, 3), 512>>>(Wq, wkt, wtf);
    wvp_k<<<dim3(128, 4, 3), 512>>>(Wv, Wproj, wvpf);
    prep_vec_k<<<579, 256>>>(Wq, Wk, bq, bk, We, uz, bt, ccv);
    prep_mat_k<<<dim3(9, 3), 512>>>(bv, We, bskip, bproj, Wproj, extf, bfv);
    wf_k<<<dim3(128, 3), 512>>>(Wskip, Wproj, wff);

    // CSR
    cudaMemsetAsync(deg, 0, NN * sizeof(int));
    hist_k<<<(EE + 255) / 256, 256>>>(dst, deg);
    scanA_k<<<(NN + 255) / 256, 256>>>(deg, off, blk);
    scanB_k<<<1, 256>>>(blk);
    scanC_k<<<(NN + 255) / 256, 256>>>(off, blk, cur);
    scatter_k<<<(EE + 255) / 256, 256>>>(src, dst, ea, cur, srcs, eas);

    const int attnBlocks = NN / 8;       // 6250

    for (int l = 0; l < LLL; l++) {
        float* xo = (l == LLL - 1) ? (float*)d_out : xbuf;
        uint32_t* xfo = (l == LLL - 1) ? nullptr : xf;

        gemm_t_mma<<<dim3(2, NSLAB), 256, T_SMEM_B>>>(
            xf, wtf + (size_t)l * 16 * 2048, bt + (size_t)l * HCC, t);

        attn_node_k<<<attnBlocks, 256>>>(t, xh, off, srcs, eas,
                                         uz + (size_t)l * 1024, ccv + (size_t)l * 8,
                                         gf, scf);

        gemm_proj_ln<<<NSLAB, 256, PRJ_SMEM_B>>>(
            gf, wvpf + (size_t)l * 16 * 2048,
            xf, wff + (size_t)l * 8192,
            scf, extf + (size_t)l * 2048,
            bfv + l * HIDD,
            xbuf, gamma + l * HIDD, beta + l * HIDD,
            xo, xfo, xh);
    }
}

// round 17
// speedup vs baseline: 5.6177x; 1.0547x over previous
#include <cuda_runtime.h>
#include <cuda_bf16.h>
#include <cuda_fp16.h>
#include <math.h>
#include <stdint.h>

#define NN 50000
#define NPAD 50048          // 391 * 128
#define NSLAB 391
#define EE 100000
#define HIDD 128
#define HH 4
#define CCC 128
#define HCC 512
#define LLL 3

// ---------------- scratch ----------------
__device__ __half g_t[(size_t)NPAD * HCC];               // t = x@Mstack + r, row-major
__device__ __half g_xh[(size_t)NPAD * HIDD];             // x row-major half (gathers)
__device__ float g_x[(size_t)NPAD * HIDD];               // x fp32 (residual)
__device__ float g_wkt[(size_t)LLL * 4 * 128 * 128];     // Wk^T per (l,h)
// fragment-order fp16 buffers (uint32 views; 1 chunk = 2048 u32 = 4096 halves)
__device__ uint32_t g_xf[(size_t)NSLAB * 8192];          // x frag
__device__ uint32_t g_gf[(size_t)NSLAB * 32768];         // g frag (x-space agg)
__device__ uint32_t g_scf[(size_t)NSLAB * 2048];         // sa/cn ext chunk
__device__ uint32_t g_wtf[(size_t)LLL * 16 * 2048];      // Mstack frag
__device__ uint32_t g_wvpf[(size_t)LLL * 16 * 2048];     // Wv@Wproj frag
__device__ uint32_t g_extf[(size_t)LLL * 2048];          // [bvP;WeP] ext chunk
__device__ uint32_t g_wff[(size_t)LLL * 8192];           // Wskip@Wproj frag
__device__ float g_bt[(size_t)LLL * HCC];                // t bias (r)
__device__ float g_uz[(size_t)LLL * 1024];               // u[4][128], z[4][128]
__device__ float g_ccv[(size_t)LLL * 8];                 // cq[4], cw[4]
__device__ float g_bf[(size_t)LLL * HIDD];               // bproj + bskip@Wproj

// CSR
__device__ int   g_deg[NN];
__device__ int   g_off[NN + 1];
__device__ int   g_cur[NN];
__device__ int   g_blk[256];
__device__ int   g_srcs[EE];
__device__ float g_eas[EE];

__device__ __forceinline__ uint32_t cvta_sm(const void* p) {
    uint32_t a;
    asm("{ .reg .u64 t; cvta.to.shared.u64 t, %1; cvt.u32.u64 %0, t; }" : "=r"(a) : "l"(p));
    return a;
}
__device__ __forceinline__ void cp16(uint32_t smem, const void* g) {
    asm volatile("cp.async.cg.shared.global [%0], [%1], 16;" :: "r"(smem), "l"(g));
}
#define CP_COMMIT() asm volatile("cp.async.commit_group;" ::: "memory")
#define CP_WAIT(n)  asm volatile("cp.async.wait_group %0;" :: "n"(n) : "memory")

__device__ __forceinline__ void mma16816(float* d, const uint32_t* a, const uint32_t* b) {
    asm volatile("mma.sync.aligned.m16n8k16.row.col.f32.f16.f16.f32 "
        "{%0,%1,%2,%3}, {%4,%5,%6,%7}, {%8,%9}, {%0,%1,%2,%3};"
        : "+f"(d[0]), "+f"(d[1]), "+f"(d[2]), "+f"(d[3])
        : "r"(a[0]), "r"(a[1]), "r"(a[2]), "r"(a[3]), "r"(b[0]), "r"(b[1]));
}

// half-index within one A chunk (128m x 32k fp16)
__device__ __forceinline__ int aidx_h(int m, int kk) {
    int m_tile = m >> 4, r = m & 15;
    int k16 = kk >> 4, kw = kk & 15;
    int lane = (r & 7) * 4 + ((kw & 7) >> 1);
    int reg = ((kw >> 3) << 1) + (r >> 3);
    int u = ((k16 * 8 + m_tile) * 32 + lane) * 4 + reg;
    return u * 2 + (kw & 1);
}
// half-index within one B chunk (32k x 128n fp16)
__device__ __forceinline__ int bidx_h(int kk, int n) {
    int k16 = kk >> 4, kw = kk & 15;
    int n_tile = n >> 3, nn = n & 7;
    int tg = (kw & 7) >> 1;
    int lane = nn * 4 + tg;
    int reg = kw >> 3;
    int u = ((k16 * 16 + n_tile) * 32 + lane) * 2 + reg;
    return u * 2 + (kw & 1);
}

#define T_SMEM_B ((8192 + 4*2048) * 4)       // 65536
#define PRJ_SMEM_B (4096 * 4 + 8192 * 4)     // 49152 (4xA(1024) + 4xB(2048)); LN tile 64*132*4=33792 fits

// ---------------- t GEMM: t = x@Mstack + r (fp16 mma, N-split x4, 4 stages) ----------------
__global__ __launch_bounds__(256, 2) void gemm_t_mma(
    const uint32_t* __restrict__ xf, const uint32_t* __restrict__ wt,
    const float* __restrict__ bt, __half* __restrict__ ot)
{
    extern __shared__ uint32_t smu[];
    uint32_t* As = smu;
    uint32_t* Bs = smu + 8192;
    const uint32_t As_a = cvta_sm(As);
    const uint32_t Bs_a = cvta_sm(Bs);

    const int tid = threadIdx.x;
    const int wid = tid >> 5;
    const int lane = tid & 31;
    const int m0 = blockIdx.y * 128;
    const int wm = wid >> 2;
    const int wn = wid & 3;
    const int t0 = blockIdx.x;          // one N-tile per CTA

    auto cpB = [&](int s, int buf) {
        const uint32_t* chunk = wt + (size_t)(t0 * 4 + s) * 2048;
        uint32_t base = Bs_a + buf * 2048 * 4;
#pragma unroll
        for (int g = 0; g < 2; g++) {
            int o = (g * 256 + tid) * 4;
            cp16(base + o * 4, chunk + o);
        }
    };

    {
        const uint32_t* asrc = xf + (size_t)blockIdx.y * 8192;
#pragma unroll
        for (int g = 0; g < 8; g++) {
            int o = (g * 256 + tid) * 4;
            cp16(As_a + o * 4, asrc + o);
        }
    }
    cpB(0, 0); CP_COMMIT();
    cpB(1, 1); CP_COMMIT();
    cpB(2, 2); CP_COMMIT();

    float acc[4][4][4];
    {
        const float* bias = bt + t0 * 128 + wn * 32;
#pragma unroll
        for (int j = 0; j < 4; j++) {
            float bv0 = __ldg(bias + j * 8 + 2 * (lane & 3));
            float bv1 = __ldg(bias + j * 8 + 2 * (lane & 3) + 1);
#pragma unroll
            for (int i = 0; i < 4; i++) {
                acc[i][j][0] = bv0; acc[i][j][1] = bv1;
                acc[i][j][2] = bv0; acc[i][j][3] = bv1;
            }
        }
    }

    for (int s = 0; s < 4; s++) {
        if (s < 2)      { CP_WAIT(2); }
        else if (s == 2){ CP_WAIT(1); }
        else            { CP_WAIT(0); }
        __syncthreads();
        if (s == 0) { cpB(3, 3); CP_COMMIT(); }
        {
            const uint32_t* B = Bs + s * 2048;
            const uint32_t* Ac = As + s * 2048;
#pragma unroll
            for (int k16 = 0; k16 < 2; k16++) {
                uint32_t af[4][4];
#pragma unroll
                for (int i = 0; i < 4; i++) {
                    uint32_t u = (uint32_t)(((k16 * 8 + wm * 4 + i) * 32 + lane) * 4);
                    uint4 t4 = *(const uint4*)(Ac + u);
                    af[i][0] = t4.x; af[i][1] = t4.y; af[i][2] = t4.z; af[i][3] = t4.w;
                }
                uint32_t bf[4][2];
#pragma unroll
                for (int j = 0; j < 4; j++) {
                    uint32_t v = (uint32_t)(((k16 * 16 + wn * 4 + j) * 32 + lane) * 2);
                    uint2 t2 = *(const uint2*)(B + v);
                    bf[j][0] = t2.x; bf[j][1] = t2.y;
                }
#pragma unroll
                for (int i = 0; i < 4; i++)
#pragma unroll
                    for (int j = 0; j < 4; j++)
                        mma16816(acc[i][j], af[i], bf[j]);
            }
        }
    }

    // epilogue
    {
        const int col = t0 * 128 + wn * 32 + 2 * (lane & 3);
#pragma unroll
        for (int i = 0; i < 4; i++) {
            int row = m0 + wm * 64 + i * 16 + (lane >> 2);
#pragma unroll
            for (int j = 0; j < 4; j++) {
                *(__half2*)(ot + (size_t)row * HCC + col + j * 8) =
                    __floats2half2_rn(acc[i][j][0], acc[i][j][1]);
                *(__half2*)(ot + (size_t)(row + 8) * HCC + col + j * 8) =
                    __floats2half2_rn(acc[i][j][2], acc[i][j][3]);
            }
        }
    }
}

// ---------------- Proj GEMM + ext + ELU + residual + LayerNorm (M=64, 21 stages) ----------------
// grid 782: blockIdx.x = slab*2 + half.
__global__ __launch_bounds__(256, 3) void gemm_proj_ln(
    const uint32_t* __restrict__ gfr, const uint32_t* __restrict__ wvpf,
    const uint32_t* __restrict__ xf, const uint32_t* __restrict__ wff,
    const uint32_t* __restrict__ scf, const uint32_t* __restrict__ extf,
    const float* __restrict__ bias,
    const float* __restrict__ x, const float* __restrict__ gamma,
    const float* __restrict__ beta,
    float* __restrict__ out, uint32_t* __restrict__ xfo,
    __half* __restrict__ xho)
{
    extern __shared__ uint32_t smu[];
    uint32_t* As = smu;              // 4 x 1024 u32 (64m x 32k halves)
    uint32_t* Bs = smu + 4096;       // 4 x 2048 u32
    const uint32_t As_a = cvta_sm(As);
    const uint32_t Bs_a = cvta_sm(Bs);

    const int tid = threadIdx.x;
    const int wid = tid >> 5;
    const int lane = tid & 31;
    const int slab = blockIdx.x >> 1;
    const int half = blockIdx.x & 1;
    const int wm = wid >> 2;         // 0..1
    const int wn = wid & 3;          // 0..3

    auto cpStage = [&](int s1, int buf) {
        const uint32_t *Asrc, *Bsrc;
        if (s1 < 16) {
            Asrc = gfr + (size_t)slab * 32768 + (size_t)s1 * 2048;
            Bsrc = wvpf + (size_t)s1 * 2048;
        } else if (s1 < 20) {
            Asrc = xf + (size_t)slab * 8192 + (size_t)(s1 - 16) * 2048;
            Bsrc = wff + (size_t)(s1 - 16) * 2048;
        } else {
            Asrc = scf + (size_t)slab * 2048;
            Bsrc = extf;
        }
        // A half-subset: per k16, m-tiles [half*4, half*4+4) = 512 contiguous u32
        {
            int k16 = tid >> 7, r = tid & 127;
            cp16(As_a + buf * 1024 * 4 + (uint32_t)(k16 * 512 + r * 4) * 4,
                 Asrc + k16 * 1024 + half * 512 + r * 4);
        }
        uint32_t bb = Bs_a + buf * 2048 * 4;
#pragma unroll
        for (int g = 0; g < 2; g++) {
            int o = (g * 256 + tid) * 4;
            cp16(bb + o * 4, Bsrc + o);
        }
    };

    float acc[2][4][4];
    {
        const float* bp = bias + wn * 32;
#pragma unroll
        for (int j = 0; j < 4; j++) {
            float bv0 = __ldg(bp + j * 8 + 2 * (lane & 3));
            float bv1 = __ldg(bp + j * 8 + 2 * (lane & 3) + 1);
#pragma unroll
            for (int i = 0; i < 2; i++) {
                acc[i][j][0] = bv0; acc[i][j][1] = bv1;
                acc[i][j][2] = bv0; acc[i][j][3] = bv1;
            }
        }
    }

    cpStage(0, 0); CP_COMMIT();
    cpStage(1, 1); CP_COMMIT();
    cpStage(2, 2); CP_COMMIT();

    for (int s = 0; s < 21; s++) {
        if (s < 19)      { CP_WAIT(2); }
        else if (s == 19){ CP_WAIT(1); }
        else             { CP_WAIT(0); }
        __syncthreads();
        if (s + 3 < 21) { cpStage(s + 3, (s + 3) & 3); CP_COMMIT(); }
        {
            const uint32_t* Ac = As + (s & 3) * 1024;
            const uint32_t* Bc = Bs + (s & 3) * 2048;
#pragma unroll
            for (int k16 = 0; k16 < 2; k16++) {
                uint32_t af[2][4];
#pragma unroll
                for (int i = 0; i < 2; i++) {
                    uint32_t u = (uint32_t)(((k16 * 4 + wm * 2 + i) * 32 + lane) * 4);
                    uint4 t4 = *(const uint4*)(Ac + u);
                    af[i][0] = t4.x; af[i][1] = t4.y; af[i][2] = t4.z; af[i][3] = t4.w;
                }
                uint32_t bf[4][2];
#pragma unroll
                for (int j = 0; j < 4; j++) {
                    uint32_t v = (uint32_t)(((k16 * 16 + wn * 4 + j) * 32 + lane) * 2);
                    uint2 t2 = *(const uint2*)(Bc + v);
                    bf[j][0] = t2.x; bf[j][1] = t2.y;
                }
#pragma unroll
                for (int i = 0; i < 2; i++)
#pragma unroll
                    for (int j = 0; j < 4; j++)
                        mma16816(acc[i][j], af[i], bf[j]);
            }
        }
    }

    // ---- fused epilogue: elu(h) staged in smem [64][132], LN per row ----
    __syncthreads();
    float* ht = (float*)smu;
    {
        int col = wn * 32 + 2 * (lane & 3);
#pragma unroll
        for (int i = 0; i < 2; i++) {
            int r0 = wm * 32 + i * 16 + (lane >> 2);
#pragma unroll
            for (int j = 0; j < 4; j++) {
                float e0 = acc[i][j][0], e1 = acc[i][j][1];
                float e2 = acc[i][j][2], e3 = acc[i][j][3];
                ht[r0 * 132 + col + j * 8]           = e0 > 0.f ? e0 : expm1f(e0);
                ht[r0 * 132 + col + j * 8 + 1]       = e1 > 0.f ? e1 : expm1f(e1);
                ht[(r0 + 8) * 132 + col + j * 8]     = e2 > 0.f ? e2 : expm1f(e2);
                ht[(r0 + 8) * 132 + col + j * 8 + 1] = e3 > 0.f ? e3 : expm1f(e3);
            }
        }
    }
    __syncthreads();

    const float4 gv = *(const float4*)(gamma + lane * 4);
    const float4 bv = *(const float4*)(beta + lane * 4);
    __half* xfoh = (__half*)xfo;

#pragma unroll
    for (int r = 0; r < 8; r++) {
        int row = wid * 8 + r;                       // 0..63
        int rslab = half * 64 + row;                 // row within 128-slab
        int grow = slab * 128 + rslab;
        float4 h4 = *(const float4*)(ht + row * 132 + lane * 4);
        float4 x4 = *(const float4*)(x + (size_t)grow * HIDD + lane * 4);
        float4 y;
        y.x = x4.x + h4.x; y.y = x4.y + h4.y;
        y.z = x4.z + h4.z; y.w = x4.w + h4.w;

        float sum = y.x + y.y + y.z + y.w;
        float sq  = y.x * y.x + y.y * y.y + y.z * y.z + y.w * y.w;
#pragma unroll
        for (int off = 16; off; off >>= 1) {
            sum += __shfl_xor_sync(0xffffffffu, sum, off);
            sq  += __shfl_xor_sync(0xffffffffu, sq, off);
        }
        float mu = sum * (1.f / 128.f);
        float var = sq * (1.f / 128.f) - mu * mu;
        float inv = rsqrtf(var + 1e-5f);

        float4 o;
        o.x = (y.x - mu) * inv * gv.x + bv.x;
        o.y = (y.y - mu) * inv * gv.y + bv.y;
        o.z = (y.z - mu) * inv * gv.z + bv.z;
        o.w = (y.w - mu) * inv * gv.w + bv.w;

        if (grow < NN)
            *(float4*)(out + (size_t)grow * HIDD + lane * 4) = o;

        if (xfo) {
            float vals[4] = {o.x, o.y, o.z, o.w};
            __half* dst = xfoh + (size_t)slab * 16384;
#pragma unroll
            for (int j = 0; j < 4; j++) {
                int k = lane * 4 + j;
                dst[(size_t)(k >> 5) * 4096 + aidx_h(rslab, k & 31)] = __float2half_rn(vals[j]);
            }
            uint2 packed;
            *(__half2*)&packed.x = __floats2half2_rn(o.x, o.y);
            *(__half2*)&packed.y = __floats2half2_rn(o.z, o.w);
            *(uint2*)(xho + (size_t)grow * HIDD + lane * 4) = packed;
        }
    }
}

// ---------------- Prep: Wk transpose (smem tiled) ----------------
__global__ __launch_bounds__(256) void wkT_k(const float* __restrict__ Wk,
                                             float* __restrict__ wkt)
{
    __shared__ float tile[32][33];
    int bj = blockIdx.x & 3, bc = blockIdx.x >> 2;
    int h = blockIdx.y, l = blockIdx.z;
    int tx = threadIdx.x & 31, ty = threadIdx.x >> 5;
#pragma unroll
    for (int k = 0; k < 4; k++) {
        int j = bj * 32 + ty + k * 8;
        tile[ty + k * 8][tx] =
            Wk[(size_t)l * 65536 + (size_t)j * HCC + h * 128 + bc * 32 + tx];
    }
    __syncthreads();
#pragma unroll
    for (int k = 0; k < 4; k++) {
        int c = bc * 32 + ty + k * 8;
        wkt[((size_t)(l * 4 + h) * 128 + c) * 128 + bj * 32 + tx] = tile[tx][ty + k * 8];
    }
}

// ---------------- Prep: Mstack = Wq_h @ Wk_h^T (coalesced via wkt) ----------------
__global__ __launch_bounds__(512) void mstack_k(
    const float* __restrict__ Wq, const float* __restrict__ wkt,
    uint32_t* __restrict__ wtf)
{
    __shared__ float sA[128];
    __shared__ float red[4][128];
    int i = blockIdx.x, h = blockIdx.y, l = blockIdx.z;
    int j = threadIdx.x & 127, q = threadIdx.x >> 7;
    if (threadIdx.x < 128)
        sA[threadIdx.x] = Wq[(size_t)l * 65536 + (size_t)i * HCC + h * 128 + threadIdx.x];
    __syncthreads();
    const float* wk = wkt + ((size_t)(l * 4 + h) * 128 + q * 32) * 128 + j;
    float s0 = 0.f, s1 = 0.f, s2 = 0.f, s3 = 0.f;
#pragma unroll 8
    for (int c = 0; c < 32; c += 4) {
        s0 = fmaf(sA[q * 32 + c],     wk[(size_t)c * 128],       s0);
        s1 = fmaf(sA[q * 32 + c + 1], wk[(size_t)(c + 1) * 128], s1);
        s2 = fmaf(sA[q * 32 + c + 2], wk[(size_t)(c + 2) * 128], s2);
        s3 = fmaf(sA[q * 32 + c + 3], wk[(size_t)(c + 3) * 128], s3);
    }
    red[q][j] = (s0 + s1) + (s2 + s3);
    __syncthreads();
    if (q == 0) {
        float m = red[0][j] + red[1][j] + red[2][j] + red[3][j];
        __half* dh = (__half*)wtf;
        dh[(size_t)(l * 16 + h * 4 + (i >> 5)) * 4096 + bidx_h(i & 31, j)] =
            __float2half_rn(m);
    }
}

// ---------------- Prep: WvP = Wv_h @ Wproj_h (c-split x4) ----------------
__global__ __launch_bounds__(512) void wvp_k(
    const float* __restrict__ Wv, const float* __restrict__ Wproj,
    uint32_t* __restrict__ wvpf)
{
    __shared__ float sV[128];
    __shared__ float red[4][128];
    int i = blockIdx.x, h = blockIdx.y, l = blockIdx.z;
    int j = threadIdx.x & 127, q = threadIdx.x >> 7;
    if (threadIdx.x < 128)
        sV[threadIdx.x] = Wv[(size_t)l * 65536 + (size_t)i * HCC + h * 128 + threadIdx.x];
    __syncthreads();
    const float* wp = Wproj + (size_t)l * 65536 + (size_t)(h * 128 + q * 32) * HIDD + j;
    float s0 = 0.f, s1 = 0.f, s2 = 0.f, s3 = 0.f;
#pragma unroll 8
    for (int c = 0; c < 32; c += 4) {
        s0 = fmaf(sV[q * 32 + c],     wp[(size_t)c * HIDD],       s0);
        s1 = fmaf(sV[q * 32 + c + 1], wp[(size_t)(c + 1) * HIDD], s1);
        s2 = fmaf(sV[q * 32 + c + 2], wp[(size_t)(c + 2) * HIDD], s2);
        s3 = fmaf(sV[q * 32 + c + 3], wp[(size_t)(c + 3) * HIDD], s3);
    }
    red[q][j] = (s0 + s1) + (s2 + s3);
    __syncthreads();
    if (q == 0) {
        float m = red[0][j] + red[1][j] + red[2][j] + red[3][j];
        __half* dh = (__half*)wvpf;
        dh[(size_t)(l * 16 + h * 4 + (i >> 5)) * 4096 + bidx_h(i & 31, j)] =
            __float2half_rn(m);
    }
}

// ---------------- Prep: vec dots (warp per output): u, z, bt, cq/cw ----------------
__global__ __launch_bounds__(256) void prep_vec_k(
    const float* __restrict__ Wq, const float* __restrict__ Wk,
    const float* __restrict__ bq, const float* __restrict__ bk,
    const float* __restrict__ We, float* __restrict__ uz,
    float* __restrict__ bt, float* __restrict__ ccv)
{
    int w = blockIdx.x * 8 + (threadIdx.x >> 5);
    int lane = threadIdx.x & 31;
    if (w >= 4632) return;

    float s = 0.f;
    if (w < 3072) {
        int kind, idx;
        if (w < 1536) { kind = 0; idx = w; }
        else          { kind = 1; idx = w - 1536; }
        int l = idx >> 9, hi = idx & 511;
        int h = hi >> 7, i = hi & 127;
        const float* row = Wq + (size_t)l * 65536 + (size_t)i * HCC + h * 128 + lane * 4;
        const float* vec = ((kind == 0) ? bk : We) + (size_t)l * HCC + h * 128 + lane * 4;
        float4 r4 = *(const float4*)row;
        float4 v4 = *(const float4*)vec;
        s = r4.x * v4.x + r4.y * v4.y + r4.z * v4.z + r4.w * v4.w;
#pragma unroll
        for (int o = 16; o; o >>= 1) s += __shfl_xor_sync(0xffffffffu, s, o);
        if (lane == 0)
            uz[(size_t)l * 1024 + kind * 512 + h * 128 + i] = s;
    } else if (w < 4608) {
        int idx = w - 3072;
        int l = idx >> 9, hj = idx & 511;
        int h = hj >> 7, j = hj & 127;
        const float* row = Wk + (size_t)l * 65536 + (size_t)j * HCC + h * 128 + lane * 4;
        const float* vec = bq + (size_t)l * HCC + h * 128 + lane * 4;
        float4 r4 = *(const float4*)row;
        float4 v4 = *(const float4*)vec;
        s = r4.x * v4.x + r4.y * v4.y + r4.z * v4.z + r4.w * v4.w;
#pragma unroll
        for (int o = 16; o; o >>= 1) s += __shfl_xor_sync(0xffffffffu, s, o);
        if (lane == 0)
            bt[(size_t)l * HCC + h * 128 + j] = s;
    } else {
        int idx = w - 4608;
        int l = idx >> 3;
        int r = idx & 7;
        int h = r & 3;
        const float* bqh = bq + (size_t)l * HCC + h * 128 + lane * 4;
        const float* vec = ((r < 4) ? bk : We) + (size_t)l * HCC + h * 128 + lane * 4;
        float4 a4 = *(const float4*)bqh;
        float4 v4 = *(const float4*)vec;
        s = a4.x * v4.x + a4.y * v4.y + a4.z * v4.z + a4.w * v4.w;
#pragma unroll
        for (int o = 16; o; o >>= 1) s += __shfl_xor_sync(0xffffffffu, s, o);
        if (lane == 0)
            ccv[l * 8 + r] = s;
    }
}

// ---------------- Prep: ext chunk + bf (c-split x4) ----------------
__global__ __launch_bounds__(512) void prep_mat_k(
    const float* __restrict__ bv, const float* __restrict__ We,
    const float* __restrict__ bskip, const float* __restrict__ bproj,
    const float* __restrict__ Wproj,
    uint32_t* __restrict__ extf, float* __restrict__ bf)
{
    __shared__ float red[4][128];
    int r = blockIdx.x, l = blockIdx.y;
    int j = threadIdx.x & 127, q = threadIdx.x >> 7;

    if (r < 8) {
        int h = r & 3;
        const float* vec = ((r < 4) ? bv : We) + (size_t)l * HCC + h * 128 + q * 32;
        const float* wp = Wproj + (size_t)l * 65536 + (size_t)(h * 128 + q * 32) * HIDD + j;
        float s0 = 0.f, s1 = 0.f, s2 = 0.f, s3 = 0.f;
#pragma unroll 8
        for (int c = 0; c < 32; c += 4) {
            s0 = fmaf(vec[c],     wp[(size_t)c * HIDD],       s0);
            s1 = fmaf(vec[c + 1], wp[(size_t)(c + 1) * HIDD], s1);
            s2 = fmaf(vec[c + 2], wp[(size_t)(c + 2) * HIDD], s2);
            s3 = fmaf(vec[c + 3], wp[(size_t)(c + 3) * HIDD], s3);
        }
        red[q][j] = (s0 + s1) + (s2 + s3);
        __syncthreads();
        if (q == 0) {
            float s = red[0][j] + red[1][j] + red[2][j] + red[3][j];
            __half* dh = (__half*)extf;
            dh[(size_t)l * 4096 + bidx_h(r, j)] = __float2half_rn(s);
        }
    } else {
        const float* bs = bskip + (size_t)l * HCC + q * 128;
        const float* wp = Wproj + (size_t)l * 65536 + (size_t)(q * 128) * HIDD + j;
        float s0 = 0.f, s1 = 0.f, s2 = 0.f, s3 = 0.f;
#pragma unroll 8
        for (int c = 0; c < 128; c += 4) {
            s0 = fmaf(bs[c],     wp[(size_t)c * HIDD],       s0);
            s1 = fmaf(bs[c + 1], wp[(size_t)(c + 1) * HIDD], s1);
            s2 = fmaf(bs[c + 2], wp[(size_t)(c + 2) * HIDD], s2);
            s3 = fmaf(bs[c + 3], wp[(size_t)(c + 3) * HIDD], s3);
        }
        red[q][j] = (s0 + s1) + (s2 + s3);
        __syncthreads();
        if (q == 0)
            bf[l * HIDD + j] = bproj[(size_t)l * HIDD + j] +
                               red[0][j] + red[1][j] + red[2][j] + red[3][j];
    }
}

// Wf = Wskip @ Wproj — coalesced
__global__ __launch_bounds__(512) void wf_k(const float* __restrict__ Wskip,
                                            const float* __restrict__ Wproj,
                                            uint32_t* __restrict__ wff)
{
    __shared__ float red[4][128];
    int i = blockIdx.x, l = blockIdx.y;
    int j = threadIdx.x & 127, q = threadIdx.x >> 7;
    const float* ws = Wskip + (size_t)l * HIDD * HCC + (size_t)i * HCC + q * 128;
    const float* wp = Wproj + (size_t)l * HCC * HIDD + (size_t)(q * 128) * HIDD + j;
    float s0 = 0.f, s1 = 0.f, s2 = 0.f, s3 = 0.f;
#pragma unroll 8
    for (int k = 0; k < 128; k += 4) {
        s0 = fmaf(ws[k],     wp[(size_t)k * HIDD],       s0);
        s1 = fmaf(ws[k + 1], wp[(size_t)(k + 1) * HIDD], s1);
        s2 = fmaf(ws[k + 2], wp[(size_t)(k + 2) * HIDD], s2);
        s3 = fmaf(ws[k + 3], wp[(size_t)(k + 3) * HIDD], s3);
    }
    red[q][j] = (s0 + s1) + (s2 + s3);
    __syncthreads();
    if (q == 0) {
        float s = red[0][j] + red[1][j] + red[2][j] + red[3][j];
        __half* dh = (__half*)wff;
        dh[(size_t)(l * 4 + (i >> 5)) * 4096 + bidx_h(i & 31, j)] = __float2half_rn(s);
    }
}

// x_in -> frag order + row-major half + fp32 copy (layer 0)
__global__ void init_xfrag_k(const float* __restrict__ x, uint32_t* __restrict__ xf,
                             __half* __restrict__ xh, float* __restrict__ xc)
{
    int t = blockIdx.x * 256 + threadIdx.x;
    int row = t >> 5, lane = t & 31;
    float4 v = *(const float4*)(x + (size_t)row * HIDD + lane * 4);
    int slab = row >> 7, m = row & 127;
    float vals[4] = {v.x, v.y, v.z, v.w};
    __half* xfh = (__half*)xf;
#pragma unroll
    for (int j = 0; j < 4; j++) {
        int k = lane * 4 + j;
        xfh[(size_t)slab * 16384 + (size_t)(k >> 5) * 4096 + aidx_h(m, k & 31)] =
            __float2half_rn(vals[j]);
    }
    uint2 packed;
    *(__half2*)&packed.x = __floats2half2_rn(v.x, v.y);
    *(__half2*)&packed.y = __floats2half2_rn(v.z, v.w);
    *(uint2*)(xh + (size_t)row * HIDD + lane * 4) = packed;
    *(float4*)(xc + (size_t)row * HIDD + lane * 4) = v;
}

// ---------------- CSR build ----------------
__global__ void hist_k(const int* __restrict__ dst, int* __restrict__ deg) {
    int e = blockIdx.x * 256 + threadIdx.x;
    if (e < EE) atomicAdd(deg + dst[e], 1);
}

__global__ void scanA_k(const int* __restrict__ deg, int* __restrict__ off,
                        int* __restrict__ blk) {
    __shared__ int sh[256];
    int t = threadIdx.x;
    int idx = blockIdx.x * 256 + t;
    int val = (idx < NN) ? deg[idx] : 0;
    sh[t] = val;
    __syncthreads();
#pragma unroll
    for (int d = 1; d < 256; d <<= 1) {
        int add = (t >= d) ? sh[t - d] : 0;
        __syncthreads();
        sh[t] += add;
        __syncthreads();
    }
    if (idx < NN) off[idx] = sh[t] - val;
    if (t == 255) blk[blockIdx.x] = sh[255];
}

__global__ void scanB_k(int* __restrict__ blk) {
    __shared__ int sh[256];
    int t = threadIdx.x;
    int val = (t < 196) ? blk[t] : 0;
    sh[t] = val;
    __syncthreads();
#pragma unroll
    for (int d = 1; d < 256; d <<= 1) {
        int add = (t >= d) ? sh[t - d] : 0;
        __syncthreads();
        sh[t] += add;
        __syncthreads();
    }
    if (t < 196) blk[t] = sh[t] - val;
}

__global__ void scanC_k(int* __restrict__ off, const int* __restrict__ blk,
                        int* __restrict__ cur) {
    int idx = blockIdx.x * 256 + threadIdx.x;
    if (idx < NN) {
        int o = off[idx] + blk[blockIdx.x];
        off[idx] = o;
        cur[idx] = o;
    }
    if (idx == 0) off[NN] = EE;
}

__global__ void scatter_k(const int* __restrict__ src, const int* __restrict__ dst,
                          const float* __restrict__ ea, int* __restrict__ cur,
                          int* __restrict__ srcs, float* __restrict__ eas) {
    int e = blockIdx.x * 256 + threadIdx.x;
    if (e < EE) {
        int p = atomicAdd(cur + dst[e], 1);
        srcs[p] = src[e];
        eas[p] = ea[e];
    }
}

// ---------------- Node-centric attention in x-space (warp per node) ----------------
__global__ __launch_bounds__(256) void attn_node_k(
    const __half* __restrict__ t, const __half* __restrict__ xh,
    const int* __restrict__ off, const int* __restrict__ srcs,
    const float* __restrict__ eas, const float* __restrict__ uz,
    const float* __restrict__ ccv, uint32_t* __restrict__ gf,
    uint32_t* __restrict__ scf)
{
    int d = blockIdx.x * 8 + (threadIdx.x >> 5);
    int lane = threadIdx.x & 31;

    int beg = __ldg(off + d), end = __ldg(off + d + 1);

    float tf[4][4];
#pragma unroll
    for (int h = 0; h < 4; h++) {
        uint2 raw = *(const uint2*)(t + (size_t)d * HCC + h * 128 + lane * 4);
        float2 a = __half22float2(*(__half2*)&raw.x);
        float2 b = __half22float2(*(__half2*)&raw.y);
        tf[h][0] = a.x; tf[h][1] = a.y; tf[h][2] = b.x; tf[h][3] = b.y;
    }
    float xd[4];
    {
        uint2 raw = *(const uint2*)(xh + (size_t)d * HIDD + lane * 4);
        float2 a = __half22float2(*(__half2*)&raw.x);
        float2 b = __half22float2(*(__half2*)&raw.y);
        xd[0] = a.x; xd[1] = a.y; xd[2] = b.x; xd[3] = b.y;
    }
    float s_[4], w_[4];
#pragma unroll
    for (int h = 0; h < 4; h++) {
        float4 u4 = *(const float4*)(uz + h * 128 + lane * 4);
        float4 z4 = *(const float4*)(uz + 512 + h * 128 + lane * 4);
        float su = xd[0] * u4.x + xd[1] * u4.y + xd[2] * u4.z + xd[3] * u4.w;
        float sz = xd[0] * z4.x + xd[1] * z4.y + xd[2] * z4.z + xd[3] * z4.w;
#pragma unroll
        for (int o = 16; o; o >>= 1) {
            su += __shfl_xor_sync(0xffffffffu, su, o);
            sz += __shfl_xor_sync(0xffffffffu, sz, o);
        }
        s_[h] = su + __ldg(ccv + h);
        w_[h] = sz + __ldg(ccv + 4 + h);
    }

    float g[4][4];
#pragma unroll
    for (int h = 0; h < 4; h++)
#pragma unroll
        for (int j = 0; j < 4; j++) g[h][j] = 0.f;
    float den[4] = {0.f, 0.f, 0.f, 0.f};
    float cs[4] = {0.f, 0.f, 0.f, 0.f};

    for (int i = beg; i < end; i++) {
        int sN = __ldg(srcs + i);
        float eav = __ldg(eas + i);
        uint2 raw = *(const uint2*)(xh + (size_t)sN * HIDD + lane * 4);
        float2 a = __half22float2(*(__half2*)&raw.x);
        float2 b = __half22float2(*(__half2*)&raw.y);
        float xs[4] = {a.x, a.y, b.x, b.y};
        float al[4];
#pragma unroll
        for (int h = 0; h < 4; h++) {
            float p = tf[h][0] * xs[0] + tf[h][1] * xs[1]
                    + tf[h][2] * xs[2] + tf[h][3] * xs[3];
#pragma unroll
            for (int o = 16; o; o >>= 1) p += __shfl_xor_sync(0xffffffffu, p, o);
            al[h] = p;
        }
#pragma unroll
        for (int h = 0; h < 4; h++) {
            float pv = expf((al[h] + s_[h] + eav * w_[h]) * 0.08838834764831845f);
            den[h] += pv;
            cs[h] += pv * eav;
            g[h][0] = fmaf(pv, xs[0], g[h][0]);
            g[h][1] = fmaf(pv, xs[1], g[h][1]);
            g[h][2] = fmaf(pv, xs[2], g[h][2]);
            g[h][3] = fmaf(pv, xs[3], g[h][3]);
        }
    }

    int slab = d >> 7, m = d & 127;
    __half* gb = (__half*)gf + (size_t)slab * 65536;
#pragma unroll
    for (int h = 0; h < 4; h++) {
        float inv = 1.f / (den[h] + 1e-16f);
#pragma unroll
        for (int j = 0; j < 4; j++) {
            int kk = h * 128 + lane * 4 + j;
            gb[(size_t)(kk >> 5) * 4096 + aidx_h(m, kk & 31)] =
                __float2half_rn(g[h][j] * inv);
        }
    }
    if (lane < 8) {
        int h = lane & 3;
        float inv = 1.f / (den[h] + 1e-16f);
        float val = (lane < 4) ? den[h] * inv : cs[h] * inv;
        __half* sb = (__half*)scf + (size_t)slab * 4096;
        sb[aidx_h(m, lane)] = __float2half_rn(val);
    }
}

// ---------------- host ----------------
extern "C" void kernel_launch(void* const* d_in, const int* in_sizes, int n_in,
                              void* d_out, int out_size)
{
    const float* x_in  = (const float*)d_in[0];
    const int*   ei    = (const int*)d_in[1];
    const float* ea    = (const float*)d_in[2];
    const float* Wq    = (const float*)d_in[3];
    const float* bq    = (const float*)d_in[4];
    const float* Wk    = (const float*)d_in[5];
    const float* bk    = (const float*)d_in[6];
    const float* Wv    = (const float*)d_in[7];
    const float* bv    = (const float*)d_in[8];
    const float* We    = (const float*)d_in[9];
    const float* Wskip = (const float*)d_in[10];
    const float* bskip = (const float*)d_in[11];
    const float* Wproj = (const float*)d_in[12];
    const float* bproj = (const float*)d_in[13];
    const float* gamma = (const float*)d_in[14];
    const float* beta  = (const float*)d_in[15];

    __half *t, *xh;
    float *xbuf, *bfv, *eas, *bt, *uz, *ccv, *wkt;
    uint32_t *xf, *gf, *scf, *wtf, *wvpf, *extf, *wff;
    int *deg, *off, *cur, *blk, *srcs;
    cudaGetSymbolAddress((void**)&t,     g_t);
    cudaGetSymbolAddress((void**)&xh,    g_xh);
    cudaGetSymbolAddress((void**)&xbuf,  g_x);
    cudaGetSymbolAddress((void**)&wkt,   g_wkt);
    cudaGetSymbolAddress((void**)&xf,    g_xf);
    cudaGetSymbolAddress((void**)&gf,    g_gf);
    cudaGetSymbolAddress((void**)&scf,   g_scf);
    cudaGetSymbolAddress((void**)&wtf,   g_wtf);
    cudaGetSymbolAddress((void**)&wvpf,  g_wvpf);
    cudaGetSymbolAddress((void**)&extf,  g_extf);
    cudaGetSymbolAddress((void**)&wff,   g_wff);
    cudaGetSymbolAddress((void**)&bt,    g_bt);
    cudaGetSymbolAddress((void**)&uz,    g_uz);
    cudaGetSymbolAddress((void**)&ccv,   g_ccv);
    cudaGetSymbolAddress((void**)&bfv,   g_bf);
    cudaGetSymbolAddress((void**)&deg,   g_deg);
    cudaGetSymbolAddress((void**)&off,   g_off);
    cudaGetSymbolAddress((void**)&cur,   g_cur);
    cudaGetSymbolAddress((void**)&blk,   g_blk);
    cudaGetSymbolAddress((void**)&srcs,  g_srcs);
    cudaGetSymbolAddress((void**)&eas,   g_eas);

    cudaFuncSetAttribute(gemm_t_mma, cudaFuncAttributeMaxDynamicSharedMemorySize,
                         T_SMEM_B);
    cudaFuncSetAttribute(gemm_proj_ln, cudaFuncAttributeMaxDynamicSharedMemorySize,
                         PRJ_SMEM_B);

    const int* src = ei;
    const int* dst = ei + EE;

    init_xfrag_k<<<(NN * 32) / 256, 256>>>(x_in, xf, xh, xbuf);

    // weight prep
    wkT_k<<<dim3(16, 4, 3), 256>>>(Wk, wkt);
    mstack_k<<<dim3(128, 4, 3), 512>>>(Wq, wkt, wtf);
    wvp_k<<<dim3(128, 4, 3), 512>>>(Wv, Wproj, wvpf);
    prep_vec_k<<<579, 256>>>(Wq, Wk, bq, bk, We, uz, bt, ccv);
    prep_mat_k<<<dim3(9, 3), 512>>>(bv, We, bskip, bproj, Wproj, extf, bfv);
    wf_k<<<dim3(128, 3), 512>>>(Wskip, Wproj, wff);

    // CSR
    cudaMemsetAsync(deg, 0, NN * sizeof(int));
    hist_k<<<(EE + 255) / 256, 256>>>(dst, deg);
    scanA_k<<<(NN + 255) / 256, 256>>>(deg, off, blk);
    scanB_k<<<1, 256>>>(blk);
    scanC_k<<<(NN + 255) / 256, 256>>>(off, blk, cur);
    scatter_k<<<(EE + 255) / 256, 256>>>(src, dst, ea, cur, srcs, eas);

    const int attnBlocks = NN / 8;       // 6250

    for (int l = 0; l < LLL; l++) {
        float* xo = (l == LLL - 1) ? (float*)d_out : xbuf;
        uint32_t* xfo = (l == LLL - 1) ? nullptr : xf;

        gemm_t_mma<<<dim3(4, NSLAB), 256, T_SMEM_B>>>(
            xf, wtf + (size_t)l * 16 * 2048, bt + (size_t)l * HCC, t);

        attn_node_k<<<attnBlocks, 256>>>(t, xh, off, srcs, eas,
                                         uz + (size_t)l * 1024, ccv + (size_t)l * 8,
                                         gf, scf);

        gemm_proj_ln<<<NSLAB * 2, 256, PRJ_SMEM_B>>>(
            gf, wvpf + (size_t)l * 16 * 2048,
            xf, wff + (size_t)l * 8192,
            scf, extf + (size_t)l * 2048,
            bfv + l * HIDD,
            xbuf, gamma + l * HIDD, beta + l * HIDD,
            xo, xfo, xh);
    }
}